// round 1
// baseline (speedup 1.0000x reference)
#include <cuda_runtime.h>
#include <math.h>

#define CB 2
#define CT 2048
#define CD 1024
#define CH 16
#define CHD 64

// Scratch (no cudaMalloc allowed): qkv activations and attention output.
__device__ float g_qkv[(size_t)CB * CT * 3 * CD];   // [B, T, 3D]  ~50 MB
__device__ float g_y[(size_t)CB * CT * CD];         // [B, T, D]   ~17 MB

// ---------------------------------------------------------------------------
// SGEMM with bias: C[M,N] = A[M,K] @ B[K,N] + bias[N]
// 128x128 tile, BK=8, 256 threads, 8x8 micro-tile per thread.
// Assumes M%128==0, N%128==0, K%8==0 (true for all launches here).
// ---------------------------------------------------------------------------
__global__ __launch_bounds__(256) void sgemm_bias_kernel(
    const float* __restrict__ A, const float* __restrict__ B,
    const float* __restrict__ bias, float* __restrict__ C,
    int M, int N, int K)
{
    __shared__ float As[8][128];
    __shared__ float Bs[8][128];

    const int tid = threadIdx.x;
    const int tx = tid & 15;        // 0..15 -> column group
    const int ty = tid >> 4;        // 0..15 -> row group
    const int bm = blockIdx.y * 128;
    const int bn = blockIdx.x * 128;

    float acc[8][8];
#pragma unroll
    for (int i = 0; i < 8; i++)
#pragma unroll
        for (int j = 0; j < 8; j++) acc[i][j] = 0.0f;

    // A tile load mapping: 128 rows x 8 k -> 256 float4 (one per thread)
    const int arow = tid >> 1;             // 0..127
    const int ak4  = (tid & 1) << 2;       // 0 or 4
    // B tile load mapping: 8 k-rows x 128 n -> 256 float4
    const int brow = tid >> 5;             // 0..7
    const int bn4  = (tid & 31) << 2;      // 0..124

    const float* Aptr = A + (size_t)(bm + arow) * K + ak4;
    const float* Bptr = B + (size_t)brow * N + bn + bn4;

    for (int k0 = 0; k0 < K; k0 += 8) {
        float4 av = *(const float4*)(Aptr + k0);
        float4 bv = *(const float4*)(Bptr + (size_t)k0 * N);
        As[ak4 + 0][arow] = av.x;
        As[ak4 + 1][arow] = av.y;
        As[ak4 + 2][arow] = av.z;
        As[ak4 + 3][arow] = av.w;
        *(float4*)&Bs[brow][bn4] = bv;
        __syncthreads();

#pragma unroll
        for (int kk = 0; kk < 8; kk++) {
            float a[8], b[8];
            *(float4*)(a)     = *(const float4*)&As[kk][(ty << 2)];
            *(float4*)(a + 4) = *(const float4*)&As[kk][64 + (ty << 2)];
            *(float4*)(b)     = *(const float4*)&Bs[kk][(tx << 2)];
            *(float4*)(b + 4) = *(const float4*)&Bs[kk][64 + (tx << 2)];
#pragma unroll
            for (int i = 0; i < 8; i++)
#pragma unroll
                for (int j = 0; j < 8; j++)
                    acc[i][j] = fmaf(a[i], b[j], acc[i][j]);
        }
        __syncthreads();
    }

    float4 bv0 = *(const float4*)&bias[bn + (tx << 2)];
    float4 bv1 = *(const float4*)&bias[bn + 64 + (tx << 2)];
#pragma unroll
    for (int i = 0; i < 8; i++) {
        int r = bm + ((i < 4) ? ((ty << 2) + i) : (64 + (ty << 2) + i - 4));
        float4 o0 = make_float4(acc[i][0] + bv0.x, acc[i][1] + bv0.y,
                                acc[i][2] + bv0.z, acc[i][3] + bv0.w);
        float4 o1 = make_float4(acc[i][4] + bv1.x, acc[i][5] + bv1.y,
                                acc[i][6] + bv1.z, acc[i][7] + bv1.w);
        *(float4*)&C[(size_t)r * N + bn + (tx << 2)]      = o0;
        *(float4*)&C[(size_t)r * N + bn + 64 + (tx << 2)] = o1;
    }
}

// ---------------------------------------------------------------------------
// Causal flash attention over qkv layout [B, T, 3D], heads packed in D.
// One CTA = (batch b, head h, 64-row query tile). 256 threads, 4x4 per thread.
// Online softmax; K smem buffer reused for P tile.
// ---------------------------------------------------------------------------
__global__ __launch_bounds__(256) void attn_kernel(
    const float* __restrict__ qkv, float* __restrict__ y)
{
    __shared__ float Qs[64 * 64];
    __shared__ float Ks[64 * 64];   // K (transposed: [d][token]) then reused as P [q][k]
    __shared__ float Vs[64 * 64];   // [token][d]

    const int qt = blockIdx.x;      // 0..31
    const int h  = blockIdx.y;      // 0..15
    const int b  = blockIdx.z;      // 0..1
    const int tid = threadIdx.x;
    const int tx = tid & 15;
    const int ty = tid >> 4;

    const float* base = qkv + (size_t)b * CT * 3 * CD;

    // Load Q tile [64 tokens][64 dims], row-major in smem.
#pragma unroll
    for (int it = 0; it < 4; it++) {
        int idx = tid + (it << 8);
        int r = idx >> 4;
        int d4 = (idx & 15) << 2;
        *(float4*)&Qs[(r << 6) + d4] =
            *(const float4*)&base[(size_t)(qt * 64 + r) * (3 * CD) + h * CHD + d4];
    }

    float m[4], l[4], o[4][4];
#pragma unroll
    for (int i = 0; i < 4; i++) {
        m[i] = -INFINITY;
        l[i] = 0.0f;
#pragma unroll
        for (int j = 0; j < 4; j++) o[i][j] = 0.0f;
    }

    const float scale = 0.125f;     // 1/sqrt(64)

    for (int kt = 0; kt <= qt; kt++) {
        __syncthreads();            // previous P/V readers done (also covers Q store)

        // Load K tile transposed (Ks[d][token]) and V tile (Vs[token][d]).
#pragma unroll
        for (int it = 0; it < 4; it++) {
            int idx = tid + (it << 8);
            int kk = idx >> 4;
            int d4 = (idx & 15) << 2;
            const float* kr = &base[(size_t)(kt * 64 + kk) * (3 * CD) + CD + h * CHD + d4];
            float4 kv = *(const float4*)kr;
            Ks[((d4 + 0) << 6) + kk] = kv.x;
            Ks[((d4 + 1) << 6) + kk] = kv.y;
            Ks[((d4 + 2) << 6) + kk] = kv.z;
            Ks[((d4 + 3) << 6) + kk] = kv.w;
            *(float4*)&Vs[(kk << 6) + d4] = *(const float4*)(kr + CD);
        }
        __syncthreads();

        // S = Q K^T  (each thread: rows ty*4.., cols tx*4..)
        float s[4][4];
#pragma unroll
        for (int i = 0; i < 4; i++)
#pragma unroll
            for (int j = 0; j < 4; j++) s[i][j] = 0.0f;

#pragma unroll
        for (int d = 0; d < 64; d += 4) {
            float qv[4][4];
#pragma unroll
            for (int rr = 0; rr < 4; rr++) {
                float4 t = *(const float4*)&Qs[(((ty << 2) + rr) << 6) + d];
                qv[rr][0] = t.x; qv[rr][1] = t.y; qv[rr][2] = t.z; qv[rr][3] = t.w;
            }
#pragma unroll
            for (int dd = 0; dd < 4; dd++) {
                float4 kv = *(const float4*)&Ks[((d + dd) << 6) + (tx << 2)];
                float kvv[4] = {kv.x, kv.y, kv.z, kv.w};
#pragma unroll
                for (int rr = 0; rr < 4; rr++)
#pragma unroll
                    for (int cc = 0; cc < 4; cc++)
                        s[rr][cc] = fmaf(qv[rr][dd], kvv[cc], s[rr][cc]);
            }
        }

        // Scale + causal mask (only the diagonal tile is partial).
#pragma unroll
        for (int rr = 0; rr < 4; rr++)
#pragma unroll
            for (int cc = 0; cc < 4; cc++) s[rr][cc] *= scale;
        if (kt == qt) {
#pragma unroll
            for (int rr = 0; rr < 4; rr++)
#pragma unroll
                for (int cc = 0; cc < 4; cc++)
                    if (((tx << 2) + cc) > ((ty << 2) + rr)) s[rr][cc] = -INFINITY;
        }

        // Online softmax (row groups: 16 threads with equal ty; shfl width 16).
        float p[4][4];
#pragma unroll
        for (int rr = 0; rr < 4; rr++) {
            float mx = fmaxf(fmaxf(s[rr][0], s[rr][1]), fmaxf(s[rr][2], s[rr][3]));
#pragma unroll
            for (int off = 8; off > 0; off >>= 1)
                mx = fmaxf(mx, __shfl_xor_sync(0xffffffffu, mx, off));
            float mn = fmaxf(m[rr], mx);
            float f = expf(m[rr] - mn);
            float sum = 0.0f;
#pragma unroll
            for (int cc = 0; cc < 4; cc++) {
                float e = expf(s[rr][cc] - mn);
                p[rr][cc] = e;
                sum += e;
            }
#pragma unroll
            for (int off = 8; off > 0; off >>= 1)
                sum += __shfl_xor_sync(0xffffffffu, sum, off);
            l[rr] = l[rr] * f + sum;
            m[rr] = mn;
#pragma unroll
            for (int cc = 0; cc < 4; cc++) o[rr][cc] *= f;
        }

        __syncthreads();            // all threads done reading Ks
        // Write P into the K buffer.
#pragma unroll
        for (int rr = 0; rr < 4; rr++)
            *(float4*)&Ks[(((ty << 2) + rr) << 6) + (tx << 2)] =
                make_float4(p[rr][0], p[rr][1], p[rr][2], p[rr][3]);
        __syncthreads();

        // O += P @ V
#pragma unroll
        for (int k = 0; k < 64; k += 4) {
            float pv[4][4];
#pragma unroll
            for (int rr = 0; rr < 4; rr++) {
                float4 t = *(const float4*)&Ks[(((ty << 2) + rr) << 6) + k];
                pv[rr][0] = t.x; pv[rr][1] = t.y; pv[rr][2] = t.z; pv[rr][3] = t.w;
            }
#pragma unroll
            for (int kk = 0; kk < 4; kk++) {
                float4 vv = *(const float4*)&Vs[((k + kk) << 6) + (tx << 2)];
                float vvv[4] = {vv.x, vv.y, vv.z, vv.w};
#pragma unroll
                for (int rr = 0; rr < 4; rr++)
#pragma unroll
                    for (int cc = 0; cc < 4; cc++)
                        o[rr][cc] = fmaf(pv[rr][kk], vvv[cc], o[rr][cc]);
            }
        }
    }

    // Epilogue: normalize and write y[b, t, h*64 + d]
    float* yb = y + (size_t)b * CT * CD + (size_t)(qt * 64) * CD + h * CHD;
#pragma unroll
    for (int rr = 0; rr < 4; rr++) {
        float inv = 1.0f / l[rr];
        float4 ov = make_float4(o[rr][0] * inv, o[rr][1] * inv,
                                o[rr][2] * inv, o[rr][3] * inv);
        *(float4*)&yb[(size_t)((ty << 2) + rr) * CD + (tx << 2)] = ov;
    }
}

// ---------------------------------------------------------------------------
// Launch: GEMM1 (qkv) -> attention -> GEMM2 (output projection)
// ---------------------------------------------------------------------------
extern "C" void kernel_launch(void* const* d_in, const int* in_sizes, int n_in,
                              void* d_out, int out_size)
{
    (void)in_sizes; (void)n_in; (void)out_size;
    const float* x  = (const float*)d_in[0];
    const float* W1 = (const float*)d_in[1];
    const float* b1 = (const float*)d_in[2];
    const float* W2 = (const float*)d_in[3];
    const float* b2 = (const float*)d_in[4];
    float* out = (float*)d_out;

    float *qkv, *y;
    cudaGetSymbolAddress((void**)&qkv, g_qkv);
    cudaGetSymbolAddress((void**)&y, g_y);

    const int M = CB * CT;          // 4096

    // qkv = x @ W1 + b1   [4096,1024]x[1024,3072]
    sgemm_bias_kernel<<<dim3(3 * CD / 128, M / 128), 256>>>(x, W1, b1, qkv, M, 3 * CD, CD);

    // causal MHA -> y [B,T,D]
    attn_kernel<<<dim3(CT / 64, CH, CB), 256>>>(qkv, y);

    // out = y @ W2 + b2   [4096,1024]x[1024,1024]
    sgemm_bias_kernel<<<dim3(CD / 128, M / 128), 256>>>(y, W2, b2, out, M, CD, CD);
}

// round 3
// speedup vs baseline: 1.5023x; 1.5023x over previous
#include <cuda_runtime.h>
#include <cuda_bf16.h>
#include <math.h>
#include <stdint.h>

#define CB 2
#define CT 2048
#define CD 1024
#define CH 16
#define CHD 64

// ---------------------------------------------------------------------------
// Device scratch (no cudaMalloc allowed); 16B-aligned for cp.async/ldmatrix.
// ---------------------------------------------------------------------------
__device__ __align__(128) float g_qkv[(size_t)CB * CT * 3 * CD];   // [B,T,3D]
__device__ __align__(128) float g_y[(size_t)CB * CT * CD];         // [B,T,D]
__device__ __align__(128) __nv_bfloat16 g_xh[(size_t)CB * CT * CD];
__device__ __align__(128) __nv_bfloat16 g_xl[(size_t)CB * CT * CD];
__device__ __align__(128) __nv_bfloat16 g_yh[(size_t)CB * CT * CD];
__device__ __align__(128) __nv_bfloat16 g_yl[(size_t)CB * CT * CD];
__device__ __align__(128) __nv_bfloat16 g_w1th[(size_t)3 * CD * CD];  // W1^T [N,K]
__device__ __align__(128) __nv_bfloat16 g_w1tl[(size_t)3 * CD * CD];
__device__ __align__(128) __nv_bfloat16 g_w2th[(size_t)CD * CD];      // W2^T [N,K]
__device__ __align__(128) __nv_bfloat16 g_w2tl[(size_t)CD * CD];

// ---------------------------------------------------------------------------
// Low-level helpers (sm_80+ only: cp.async, ldmatrix, mma.sync)
// ---------------------------------------------------------------------------
__device__ __forceinline__ uint32_t smem_u32(const void* p) {
    uint32_t a;
    asm("{ .reg .u64 t; cvta.to.shared.u64 t, %1; cvt.u32.u64 %0, t; }" : "=r"(a) : "l"(p));
    return a;
}
__device__ __forceinline__ void cpasync16(uint32_t s, const void* g) {
    asm volatile("cp.async.cg.shared.global [%0], [%1], 16;" :: "r"(s), "l"(g));
}
__device__ __forceinline__ void cp_commit() {
    asm volatile("cp.async.commit_group;" ::: "memory");
}
template <int N>
__device__ __forceinline__ void cp_wait() {
    asm volatile("cp.async.wait_group %0;" :: "n"(N) : "memory");
}
__device__ __forceinline__ void ldsm4(uint32_t* r, uint32_t addr) {
    asm volatile("ldmatrix.sync.aligned.m8n8.x4.shared.b16 {%0,%1,%2,%3}, [%4];"
                 : "=r"(r[0]), "=r"(r[1]), "=r"(r[2]), "=r"(r[3]) : "r"(addr));
}
__device__ __forceinline__ void mma16816(float* d, const uint32_t* a, const uint32_t* b) {
    asm volatile(
        "mma.sync.aligned.m16n8k16.row.col.f32.bf16.bf16.f32 "
        "{%0,%1,%2,%3}, {%4,%5,%6,%7}, {%8,%9}, {%0,%1,%2,%3};"
        : "+f"(d[0]), "+f"(d[1]), "+f"(d[2]), "+f"(d[3])
        : "r"(a[0]), "r"(a[1]), "r"(a[2]), "r"(a[3]), "r"(b[0]), "r"(b[1]));
}
__device__ __forceinline__ uint32_t swz128(uint32_t b) { return b ^ ((b >> 3) & 0x70); }

// ---------------------------------------------------------------------------
// fp32 -> (bf16 hi, bf16 lo) split (elementwise)
// ---------------------------------------------------------------------------
__global__ __launch_bounds__(256) void split_kernel(
    const float* __restrict__ in, __nv_bfloat16* __restrict__ hi,
    __nv_bfloat16* __restrict__ lo, int n4)
{
    int i = blockIdx.x * blockDim.x + threadIdx.x;
    if (i >= n4) return;
    float4 v = ((const float4*)in)[i];
    __nv_bfloat16 h0 = __float2bfloat16(v.x), h1 = __float2bfloat16(v.y);
    __nv_bfloat16 h2 = __float2bfloat16(v.z), h3 = __float2bfloat16(v.w);
    __nv_bfloat16 l0 = __float2bfloat16(v.x - __bfloat162float(h0));
    __nv_bfloat16 l1 = __float2bfloat16(v.y - __bfloat162float(h1));
    __nv_bfloat16 l2 = __float2bfloat16(v.z - __bfloat162float(h2));
    __nv_bfloat16 l3 = __float2bfloat16(v.w - __bfloat162float(h3));
    __nv_bfloat162 hv0 = __nv_bfloat162(h0, h1), hv1 = __nv_bfloat162(h2, h3);
    __nv_bfloat162 lv0 = __nv_bfloat162(l0, l1), lv1 = __nv_bfloat162(l2, l3);
    ((uint2*)hi)[i] = make_uint2(*(uint32_t*)&hv0, *(uint32_t*)&hv1);
    ((uint2*)lo)[i] = make_uint2(*(uint32_t*)&lv0, *(uint32_t*)&lv1);
}

// ---------------------------------------------------------------------------
// W [K,N] fp32 -> Wt hi/lo [N,K] bf16 (split + transpose)
// ---------------------------------------------------------------------------
__global__ __launch_bounds__(256) void split_transpose_kernel(
    const float* __restrict__ W, __nv_bfloat16* __restrict__ outh,
    __nv_bfloat16* __restrict__ outl, int K, int N)
{
    __shared__ float t[32][33];
    int n0 = blockIdx.x * 32, k0 = blockIdx.y * 32;
    int tx = threadIdx.x, ty = threadIdx.y;
#pragma unroll
    for (int j = 0; j < 4; j++)
        t[ty + j * 8][tx] = W[(size_t)(k0 + ty + j * 8) * N + n0 + tx];
    __syncthreads();
#pragma unroll
    for (int j = 0; j < 4; j++) {
        int n = n0 + ty + j * 8;
        float v = t[tx][ty + j * 8];
        __nv_bfloat16 h = __float2bfloat16(v);
        __nv_bfloat16 l = __float2bfloat16(v - __bfloat162float(h));
        outh[(size_t)n * K + k0 + tx] = h;
        outl[(size_t)n * K + k0 + tx] = l;
    }
}

// ---------------------------------------------------------------------------
// HMMA split-bf16 GEMM: C[M,N] = A[M,K] @ Bt[N,K]^T + bias  (3-pass hi/lo)
// CTA 128x128, K-chunk 64, 8 warps (4m x 2n), warp tile 32x64.
// Double-buffered cp.async; SW128-swizzled smem; ldmatrix fragments.
// ---------------------------------------------------------------------------
#define HTILE 16384                 // 128 rows x 128 bytes
#define HSTAGE (4 * HTILE)          // Ah, Al, Bh, Bl
#define HSMEM (2 * HSTAGE)          // 131072 bytes

__global__ __launch_bounds__(256) void gemm_hmma3_kernel(
    const __nv_bfloat16* __restrict__ Ahg, const __nv_bfloat16* __restrict__ Alg,
    const __nv_bfloat16* __restrict__ Bhg, const __nv_bfloat16* __restrict__ Blg,
    const float* __restrict__ bias, float* __restrict__ C, int N, int K)
{
    extern __shared__ char smem[];
    const uint32_t sbase = smem_u32(smem);
    const int tid = threadIdx.x;
    const int wid = tid >> 5;
    const int lid = tid & 31;
    const int wm = wid & 3;          // warp row 0..3 (32 rows each)
    const int wn = wid >> 2;         // warp col 0..1 (64 cols each)
    const int bm = blockIdx.y * 128;
    const int bn = blockIdx.x * 128;

    const int nch = K >> 6;

    // --- stage loader: 4 tiles x 1024 16B-chunks, 16 cp.async per thread ---
    auto load_stage = [&](int buf, int k0) {
        uint32_t sb = sbase + buf * HSTAGE;
#pragma unroll
        for (int i = 0; i < 4; i++) {
            int c = tid + (i << 8);              // 0..1023
            int row = c >> 3, seg = c & 7;
            uint32_t so = swz128((row << 7) + (seg << 4));
            size_t ka = (size_t)(bm + row) * K + k0 + (seg << 3);
            size_t kb = (size_t)(bn + row) * K + k0 + (seg << 3);
            cpasync16(sb + 0 * HTILE + so, Ahg + ka);
            cpasync16(sb + 1 * HTILE + so, Alg + ka);
            cpasync16(sb + 2 * HTILE + so, Bhg + kb);
            cpasync16(sb + 3 * HTILE + so, Blg + kb);
        }
        cp_commit();
    };

    float d[2][8][4];
#pragma unroll
    for (int mi = 0; mi < 2; mi++)
#pragma unroll
        for (int ni = 0; ni < 8; ni++)
#pragma unroll
            for (int r = 0; r < 4; r++) d[mi][ni][r] = 0.0f;

    load_stage(0, 0);
    load_stage(1, 64);

    for (int c = 0; c < nch; c++) {
        if (c + 1 < nch) cp_wait<1>(); else cp_wait<0>();
        __syncthreads();

        const uint32_t sb = sbase + (c & 1) * HSTAGE;
        const uint32_t aTh = sb + 0 * HTILE, aTl = sb + 1 * HTILE;
        const uint32_t bTh = sb + 2 * HTILE, bTl = sb + 3 * HTILE;

#pragma unroll
        for (int ks = 0; ks < 4; ks++) {
            // A fragments: rows wm*32 + mi*16 + (lid&15), k-chunk ks*2 + (lid>>4)
            uint32_t ah[2][4], al[2][4];
#pragma unroll
            for (int mi = 0; mi < 2; mi++) {
                uint32_t off = swz128(((wm * 32 + mi * 16 + (lid & 15)) << 7) +
                                      ((ks * 2 + (lid >> 4)) << 4));
                ldsm4(ah[mi], aTh + off);
                ldsm4(al[mi], aTl + off);
            }
#pragma unroll
            for (int pi = 0; pi < 4; pi++) {
                // B fragments for 16 n: rows wn*64 + pi*16 + (lid&7) + ((lid>>4)<<3)
                uint32_t boff = swz128(((wn * 64 + pi * 16 + (lid & 7) + ((lid >> 4) << 3)) << 7) +
                                       ((ks * 2 + ((lid >> 3) & 1)) << 4));
                uint32_t bh4[4], bl4[4];
                ldsm4(bh4, bTh + boff);
                ldsm4(bl4, bTl + boff);
#pragma unroll
                for (int mi = 0; mi < 2; mi++) {
#pragma unroll
                    for (int sub = 0; sub < 2; sub++) {
                        float* acc = d[mi][pi * 2 + sub];
                        mma16816(acc, ah[mi], bh4 + sub * 2);   // Ah*Bh
                        mma16816(acc, ah[mi], bl4 + sub * 2);   // Ah*Bl
                        mma16816(acc, al[mi], bh4 + sub * 2);   // Al*Bh
                    }
                }
            }
        }
        __syncthreads();
        if (c + 2 < nch) load_stage(c & 1, (c + 2) << 6);
    }

    // --- epilogue: d0,d1 -> (row, col..col+1); d2,d3 -> (row+8, ...) ---
#pragma unroll
    for (int mi = 0; mi < 2; mi++) {
        int row = bm + wm * 32 + mi * 16 + (lid >> 2);
#pragma unroll
        for (int ni = 0; ni < 8; ni++) {
            int col = bn + wn * 64 + ni * 8 + ((lid & 3) << 1);
            float2 bv = *(const float2*)&bias[col];
            float2 o0 = make_float2(d[mi][ni][0] + bv.x, d[mi][ni][1] + bv.y);
            float2 o1 = make_float2(d[mi][ni][2] + bv.x, d[mi][ni][3] + bv.y);
            *(float2*)&C[(size_t)row * N + col] = o0;
            *(float2*)&C[(size_t)(row + 8) * N + col] = o1;
        }
    }
}

// ---------------------------------------------------------------------------
// Causal flash attention (unchanged fp32 SIMT from Round 1).
// ---------------------------------------------------------------------------
__global__ __launch_bounds__(256) void attn_kernel(
    const float* __restrict__ qkv, float* __restrict__ y)
{
    __shared__ float Qs[64 * 64];
    __shared__ float Ks[64 * 64];
    __shared__ float Vs[64 * 64];

    const int qt = blockIdx.x;
    const int h  = blockIdx.y;
    const int b  = blockIdx.z;
    const int tid = threadIdx.x;
    const int tx = tid & 15;
    const int ty = tid >> 4;

    const float* base = qkv + (size_t)b * CT * 3 * CD;

#pragma unroll
    for (int it = 0; it < 4; it++) {
        int idx = tid + (it << 8);
        int r = idx >> 4;
        int d4 = (idx & 15) << 2;
        *(float4*)&Qs[(r << 6) + d4] =
            *(const float4*)&base[(size_t)(qt * 64 + r) * (3 * CD) + h * CHD + d4];
    }

    float m[4], l[4], o[4][4];
#pragma unroll
    for (int i = 0; i < 4; i++) {
        m[i] = -INFINITY;
        l[i] = 0.0f;
#pragma unroll
        for (int j = 0; j < 4; j++) o[i][j] = 0.0f;
    }

    const float scale = 0.125f;

    for (int kt = 0; kt <= qt; kt++) {
        __syncthreads();
#pragma unroll
        for (int it = 0; it < 4; it++) {
            int idx = tid + (it << 8);
            int kk = idx >> 4;
            int d4 = (idx & 15) << 2;
            const float* kr = &base[(size_t)(kt * 64 + kk) * (3 * CD) + CD + h * CHD + d4];
            float4 kv = *(const float4*)kr;
            Ks[((d4 + 0) << 6) + kk] = kv.x;
            Ks[((d4 + 1) << 6) + kk] = kv.y;
            Ks[((d4 + 2) << 6) + kk] = kv.z;
            Ks[((d4 + 3) << 6) + kk] = kv.w;
            *(float4*)&Vs[(kk << 6) + d4] = *(const float4*)(kr + CD);
        }
        __syncthreads();

        float s[4][4];
#pragma unroll
        for (int i = 0; i < 4; i++)
#pragma unroll
            for (int j = 0; j < 4; j++) s[i][j] = 0.0f;

#pragma unroll
        for (int d = 0; d < 64; d += 4) {
            float qv[4][4];
#pragma unroll
            for (int rr = 0; rr < 4; rr++) {
                float4 t = *(const float4*)&Qs[(((ty << 2) + rr) << 6) + d];
                qv[rr][0] = t.x; qv[rr][1] = t.y; qv[rr][2] = t.z; qv[rr][3] = t.w;
            }
#pragma unroll
            for (int dd = 0; dd < 4; dd++) {
                float4 kv = *(const float4*)&Ks[((d + dd) << 6) + (tx << 2)];
                float kvv[4] = {kv.x, kv.y, kv.z, kv.w};
#pragma unroll
                for (int rr = 0; rr < 4; rr++)
#pragma unroll
                    for (int cc = 0; cc < 4; cc++)
                        s[rr][cc] = fmaf(qv[rr][dd], kvv[cc], s[rr][cc]);
            }
        }

#pragma unroll
        for (int rr = 0; rr < 4; rr++)
#pragma unroll
            for (int cc = 0; cc < 4; cc++) s[rr][cc] *= scale;
        if (kt == qt) {
#pragma unroll
            for (int rr = 0; rr < 4; rr++)
#pragma unroll
                for (int cc = 0; cc < 4; cc++)
                    if (((tx << 2) + cc) > ((ty << 2) + rr)) s[rr][cc] = -INFINITY;
        }

        float p[4][4];
#pragma unroll
        for (int rr = 0; rr < 4; rr++) {
            float mx = fmaxf(fmaxf(s[rr][0], s[rr][1]), fmaxf(s[rr][2], s[rr][3]));
#pragma unroll
            for (int off = 8; off > 0; off >>= 1)
                mx = fmaxf(mx, __shfl_xor_sync(0xffffffffu, mx, off));
            float mn = fmaxf(m[rr], mx);
            float f = expf(m[rr] - mn);
            float sum = 0.0f;
#pragma unroll
            for (int cc = 0; cc < 4; cc++) {
                float e = expf(s[rr][cc] - mn);
                p[rr][cc] = e;
                sum += e;
            }
#pragma unroll
            for (int off = 8; off > 0; off >>= 1)
                sum += __shfl_xor_sync(0xffffffffu, sum, off);
            l[rr] = l[rr] * f + sum;
            m[rr] = mn;
#pragma unroll
            for (int cc = 0; cc < 4; cc++) o[rr][cc] *= f;
        }

        __syncthreads();
#pragma unroll
        for (int rr = 0; rr < 4; rr++)
            *(float4*)&Ks[(((ty << 2) + rr) << 6) + (tx << 2)] =
                make_float4(p[rr][0], p[rr][1], p[rr][2], p[rr][3]);
        __syncthreads();

#pragma unroll
        for (int k = 0; k < 64; k += 4) {
            float pv[4][4];
#pragma unroll
            for (int rr = 0; rr < 4; rr++) {
                float4 t = *(const float4*)&Ks[(((ty << 2) + rr) << 6) + k];
                pv[rr][0] = t.x; pv[rr][1] = t.y; pv[rr][2] = t.z; pv[rr][3] = t.w;
            }
#pragma unroll
            for (int kk = 0; kk < 4; kk++) {
                float4 vv = *(const float4*)&Vs[((k + kk) << 6) + (tx << 2)];
                float vvv[4] = {vv.x, vv.y, vv.z, vv.w};
#pragma unroll
                for (int rr = 0; rr < 4; rr++)
#pragma unroll
                    for (int cc = 0; cc < 4; cc++)
                        o[rr][cc] = fmaf(pv[rr][kk], vvv[cc], o[rr][cc]);
            }
        }
    }

    float* yb = y + (size_t)b * CT * CD + (size_t)(qt * 64) * CD + h * CHD;
#pragma unroll
    for (int rr = 0; rr < 4; rr++) {
        float inv = 1.0f / l[rr];
        float4 ov = make_float4(o[rr][0] * inv, o[rr][1] * inv,
                                o[rr][2] * inv, o[rr][3] * inv);
        *(float4*)&yb[(size_t)((ty << 2) + rr) * CD + (tx << 2)] = ov;
    }
}

// ---------------------------------------------------------------------------
// Launch
// ---------------------------------------------------------------------------
extern "C" void kernel_launch(void* const* d_in, const int* in_sizes, int n_in,
                              void* d_out, int out_size)
{
    (void)in_sizes; (void)n_in; (void)out_size;
    const float* x  = (const float*)d_in[0];
    const float* W1 = (const float*)d_in[1];
    const float* b1 = (const float*)d_in[2];
    const float* W2 = (const float*)d_in[3];
    const float* b2 = (const float*)d_in[4];
    float* out = (float*)d_out;

    float *qkv, *y;
    __nv_bfloat16 *xh, *xl, *yh, *yl, *w1th, *w1tl, *w2th, *w2tl;
    cudaGetSymbolAddress((void**)&qkv, g_qkv);
    cudaGetSymbolAddress((void**)&y, g_y);
    cudaGetSymbolAddress((void**)&xh, g_xh);
    cudaGetSymbolAddress((void**)&xl, g_xl);
    cudaGetSymbolAddress((void**)&yh, g_yh);
    cudaGetSymbolAddress((void**)&yl, g_yl);
    cudaGetSymbolAddress((void**)&w1th, g_w1th);
    cudaGetSymbolAddress((void**)&w1tl, g_w1tl);
    cudaGetSymbolAddress((void**)&w2th, g_w2th);
    cudaGetSymbolAddress((void**)&w2tl, g_w2tl);

    static int smem_set = 0;
    if (!smem_set) {
        cudaFuncSetAttribute(gemm_hmma3_kernel,
                             cudaFuncAttributeMaxDynamicSharedMemorySize, HSMEM);
        smem_set = 1;
    }

    const int M = CB * CT;                 // 4096
    const int n4x = M * CD / 4;

    // Conversions
    split_kernel<<<(n4x + 255) / 256, 256>>>(x, xh, xl, n4x);
    split_transpose_kernel<<<dim3(3 * CD / 32, CD / 32), dim3(32, 8)>>>(W1, w1th, w1tl, CD, 3 * CD);
    split_transpose_kernel<<<dim3(CD / 32, CD / 32), dim3(32, 8)>>>(W2, w2th, w2tl, CD, CD);

    // qkv = x @ W1 + b1
    gemm_hmma3_kernel<<<dim3(3 * CD / 128, M / 128), 256, HSMEM>>>(
        xh, xl, w1th, w1tl, b1, qkv, 3 * CD, CD);

    // attention
    attn_kernel<<<dim3(CT / 64, CH, CB), 256>>>(qkv, y);

    // out = y @ W2 + b2
    split_kernel<<<(n4x + 255) / 256, 256>>>(y, yh, yl, n4x);
    gemm_hmma3_kernel<<<dim3(CD / 128, M / 128), 256, HSMEM>>>(
        yh, yl, w2th, w2tl, b2, out, CD, CD);
}

// round 4
// speedup vs baseline: 2.8802x; 1.9172x over previous
#include <cuda_runtime.h>
#include <cuda_bf16.h>
#include <math.h>
#include <stdint.h>

#define CB 2
#define CT 2048
#define CD 1024
#define CH 16
#define CHD 64

// ---------------------------------------------------------------------------
// Device scratch (no cudaMalloc allowed)
// ---------------------------------------------------------------------------
__device__ __align__(128) __nv_bfloat16 g_qkvh[(size_t)CB * CT * 3 * CD];
__device__ __align__(128) __nv_bfloat16 g_qkvl[(size_t)CB * CT * 3 * CD];
__device__ __align__(128) __nv_bfloat16 g_xh[(size_t)CB * CT * CD];
__device__ __align__(128) __nv_bfloat16 g_xl[(size_t)CB * CT * CD];
__device__ __align__(128) __nv_bfloat16 g_yh[(size_t)CB * CT * CD];
__device__ __align__(128) __nv_bfloat16 g_yl[(size_t)CB * CT * CD];
__device__ __align__(128) __nv_bfloat16 g_w1th[(size_t)3 * CD * CD];
__device__ __align__(128) __nv_bfloat16 g_w1tl[(size_t)3 * CD * CD];
__device__ __align__(128) __nv_bfloat16 g_w2th[(size_t)CD * CD];
__device__ __align__(128) __nv_bfloat16 g_w2tl[(size_t)CD * CD];

// ---------------------------------------------------------------------------
// Low-level helpers (sm_80+ : cp.async, ldmatrix, mma.sync)
// ---------------------------------------------------------------------------
__device__ __forceinline__ uint32_t smem_u32(const void* p) {
    uint32_t a;
    asm("{ .reg .u64 t; cvta.to.shared.u64 t, %1; cvt.u32.u64 %0, t; }" : "=r"(a) : "l"(p));
    return a;
}
__device__ __forceinline__ void cpasync16(uint32_t s, const void* g) {
    asm volatile("cp.async.cg.shared.global [%0], [%1], 16;" :: "r"(s), "l"(g));
}
__device__ __forceinline__ void cp_commit() {
    asm volatile("cp.async.commit_group;" ::: "memory");
}
template <int N>
__device__ __forceinline__ void cp_wait() {
    asm volatile("cp.async.wait_group %0;" :: "n"(N) : "memory");
}
__device__ __forceinline__ void ldsm4(uint32_t* r, uint32_t addr) {
    asm volatile("ldmatrix.sync.aligned.m8n8.x4.shared.b16 {%0,%1,%2,%3}, [%4];"
                 : "=r"(r[0]), "=r"(r[1]), "=r"(r[2]), "=r"(r[3]) : "r"(addr));
}
__device__ __forceinline__ void ldsm4t(uint32_t* r, uint32_t addr) {
    asm volatile("ldmatrix.sync.aligned.m8n8.x4.trans.shared.b16 {%0,%1,%2,%3}, [%4];"
                 : "=r"(r[0]), "=r"(r[1]), "=r"(r[2]), "=r"(r[3]) : "r"(addr));
}
__device__ __forceinline__ void mma16816(float* d, const uint32_t* a, const uint32_t* b) {
    asm volatile(
        "mma.sync.aligned.m16n8k16.row.col.f32.bf16.bf16.f32 "
        "{%0,%1,%2,%3}, {%4,%5,%6,%7}, {%8,%9}, {%0,%1,%2,%3};"
        : "+f"(d[0]), "+f"(d[1]), "+f"(d[2]), "+f"(d[3])
        : "r"(a[0]), "r"(a[1]), "r"(a[2]), "r"(a[3]), "r"(b[0]), "r"(b[1]));
}
__device__ __forceinline__ uint32_t swz128(uint32_t b) { return b ^ ((b >> 3) & 0x70); }
__device__ __forceinline__ uint32_t pack_bf16(float lo, float hi) {
    __nv_bfloat162 v = __floats2bfloat162_rn(lo, hi);
    return *(uint32_t*)&v;
}

// ---------------------------------------------------------------------------
// fp32 -> bf16 hi/lo split (x only)
// ---------------------------------------------------------------------------
__global__ __launch_bounds__(256) void split_kernel(
    const float* __restrict__ in, __nv_bfloat16* __restrict__ hi,
    __nv_bfloat16* __restrict__ lo, int n4)
{
    int i = blockIdx.x * blockDim.x + threadIdx.x;
    if (i >= n4) return;
    float4 v = ((const float4*)in)[i];
    __nv_bfloat16 h0 = __float2bfloat16(v.x), h1 = __float2bfloat16(v.y);
    __nv_bfloat16 h2 = __float2bfloat16(v.z), h3 = __float2bfloat16(v.w);
    __nv_bfloat16 l0 = __float2bfloat16(v.x - __bfloat162float(h0));
    __nv_bfloat16 l1 = __float2bfloat16(v.y - __bfloat162float(h1));
    __nv_bfloat16 l2 = __float2bfloat16(v.z - __bfloat162float(h2));
    __nv_bfloat16 l3 = __float2bfloat16(v.w - __bfloat162float(h3));
    __nv_bfloat162 hv0 = __nv_bfloat162(h0, h1), hv1 = __nv_bfloat162(h2, h3);
    __nv_bfloat162 lv0 = __nv_bfloat162(l0, l1), lv1 = __nv_bfloat162(l2, l3);
    ((uint2*)hi)[i] = make_uint2(*(uint32_t*)&hv0, *(uint32_t*)&hv1);
    ((uint2*)lo)[i] = make_uint2(*(uint32_t*)&lv0, *(uint32_t*)&lv1);
}

// ---------------------------------------------------------------------------
// W [K,N] fp32 -> Wt hi/lo [N,K] bf16 (split + transpose)
// ---------------------------------------------------------------------------
__global__ __launch_bounds__(256) void split_transpose_kernel(
    const float* __restrict__ W, __nv_bfloat16* __restrict__ outh,
    __nv_bfloat16* __restrict__ outl, int K, int N)
{
    __shared__ float t[32][33];
    int n0 = blockIdx.x * 32, k0 = blockIdx.y * 32;
    int tx = threadIdx.x, ty = threadIdx.y;
#pragma unroll
    for (int j = 0; j < 4; j++)
        t[ty + j * 8][tx] = W[(size_t)(k0 + ty + j * 8) * N + n0 + tx];
    __syncthreads();
#pragma unroll
    for (int j = 0; j < 4; j++) {
        int n = n0 + ty + j * 8;
        float v = t[tx][ty + j * 8];
        __nv_bfloat16 h = __float2bfloat16(v);
        __nv_bfloat16 l = __float2bfloat16(v - __bfloat162float(h));
        outh[(size_t)n * K + k0 + tx] = h;
        outl[(size_t)n * K + k0 + tx] = l;
    }
}

// ---------------------------------------------------------------------------
// HMMA split-bf16 GEMM: C = A @ Bt^T + bias. BF16OUT: write hi/lo bf16; else fp32.
// ---------------------------------------------------------------------------
#define HTILE 16384
#define HSTAGE (4 * HTILE)
#define HSMEM (2 * HSTAGE)

template <bool BF16OUT>
__global__ __launch_bounds__(256) void gemm_hmma3_kernel(
    const __nv_bfloat16* __restrict__ Ahg, const __nv_bfloat16* __restrict__ Alg,
    const __nv_bfloat16* __restrict__ Bhg, const __nv_bfloat16* __restrict__ Blg,
    const float* __restrict__ bias, float* __restrict__ Cf,
    __nv_bfloat16* __restrict__ Ch, __nv_bfloat16* __restrict__ Cl, int N, int K)
{
    extern __shared__ char smem[];
    const uint32_t sbase = smem_u32(smem);
    const int tid = threadIdx.x;
    const int wid = tid >> 5;
    const int lid = tid & 31;
    const int wm = wid & 3;
    const int wn = wid >> 2;
    const int bm = blockIdx.y * 128;
    const int bn = blockIdx.x * 128;

    const int nch = K >> 6;

    auto load_stage = [&](int buf, int k0) {
        uint32_t sb = sbase + buf * HSTAGE;
#pragma unroll
        for (int i = 0; i < 4; i++) {
            int c = tid + (i << 8);
            int row = c >> 3, seg = c & 7;
            uint32_t so = swz128((row << 7) + (seg << 4));
            size_t ka = (size_t)(bm + row) * K + k0 + (seg << 3);
            size_t kb = (size_t)(bn + row) * K + k0 + (seg << 3);
            cpasync16(sb + 0 * HTILE + so, Ahg + ka);
            cpasync16(sb + 1 * HTILE + so, Alg + ka);
            cpasync16(sb + 2 * HTILE + so, Bhg + kb);
            cpasync16(sb + 3 * HTILE + so, Blg + kb);
        }
        cp_commit();
    };

    float d[2][8][4];
#pragma unroll
    for (int mi = 0; mi < 2; mi++)
#pragma unroll
        for (int ni = 0; ni < 8; ni++)
#pragma unroll
            for (int r = 0; r < 4; r++) d[mi][ni][r] = 0.0f;

    load_stage(0, 0);
    load_stage(1, 64);

    for (int c = 0; c < nch; c++) {
        if (c + 1 < nch) cp_wait<1>(); else cp_wait<0>();
        __syncthreads();

        const uint32_t sb = sbase + (c & 1) * HSTAGE;
        const uint32_t aTh = sb + 0 * HTILE, aTl = sb + 1 * HTILE;
        const uint32_t bTh = sb + 2 * HTILE, bTl = sb + 3 * HTILE;

#pragma unroll
        for (int ks = 0; ks < 4; ks++) {
            uint32_t ah[2][4], al[2][4];
#pragma unroll
            for (int mi = 0; mi < 2; mi++) {
                uint32_t off = swz128(((wm * 32 + mi * 16 + (lid & 15)) << 7) +
                                      ((ks * 2 + (lid >> 4)) << 4));
                ldsm4(ah[mi], aTh + off);
                ldsm4(al[mi], aTl + off);
            }
#pragma unroll
            for (int pi = 0; pi < 4; pi++) {
                uint32_t boff = swz128(((wn * 64 + pi * 16 + (lid & 7) + ((lid >> 4) << 3)) << 7) +
                                       ((ks * 2 + ((lid >> 3) & 1)) << 4));
                uint32_t bh4[4], bl4[4];
                ldsm4(bh4, bTh + boff);
                ldsm4(bl4, bTl + boff);
#pragma unroll
                for (int mi = 0; mi < 2; mi++) {
#pragma unroll
                    for (int sub = 0; sub < 2; sub++) {
                        float* acc = d[mi][pi * 2 + sub];
                        mma16816(acc, ah[mi], bh4 + sub * 2);
                        mma16816(acc, ah[mi], bl4 + sub * 2);
                        mma16816(acc, al[mi], bh4 + sub * 2);
                    }
                }
            }
        }
        __syncthreads();
        if (c + 2 < nch) load_stage(c & 1, (c + 2) << 6);
    }

#pragma unroll
    for (int mi = 0; mi < 2; mi++) {
        int row = bm + wm * 32 + mi * 16 + (lid >> 2);
#pragma unroll
        for (int ni = 0; ni < 8; ni++) {
            int col = bn + wn * 64 + ni * 8 + ((lid & 3) << 1);
            float2 bv = *(const float2*)&bias[col];
            float v00 = d[mi][ni][0] + bv.x, v01 = d[mi][ni][1] + bv.y;
            float v10 = d[mi][ni][2] + bv.x, v11 = d[mi][ni][3] + bv.y;
            if (BF16OUT) {
                float h00 = __bfloat162float(__float2bfloat16(v00));
                float h01 = __bfloat162float(__float2bfloat16(v01));
                float h10 = __bfloat162float(__float2bfloat16(v10));
                float h11 = __bfloat162float(__float2bfloat16(v11));
                *(uint32_t*)&Ch[(size_t)row * N + col] = pack_bf16(h00, h01);
                *(uint32_t*)&Ch[(size_t)(row + 8) * N + col] = pack_bf16(h10, h11);
                *(uint32_t*)&Cl[(size_t)row * N + col] = pack_bf16(v00 - h00, v01 - h01);
                *(uint32_t*)&Cl[(size_t)(row + 8) * N + col] = pack_bf16(v10 - h10, v11 - h11);
            } else {
                *(float2*)&Cf[(size_t)row * N + col] = make_float2(v00, v01);
                *(float2*)&Cf[(size_t)(row + 8) * N + col] = make_float2(v10, v11);
            }
        }
    }
}

// ---------------------------------------------------------------------------
// HMMA flash attention. CTA = 128 q-rows x 1 head x 1 batch. 8 warps x 16 rows.
// KV chunks of 64 keys, double-buffered. Split-bf16 3-pass on both GEMMs.
// qkv layout: [B,T,3D] bf16 hi/lo; output y [B,T,D] bf16 hi/lo.
// ---------------------------------------------------------------------------
#define AQT 16384                     // 128 x 128B
#define AKT 8192                      // 64 x 128B
#define AKV_STAGE (4 * AKT)           // Kh,Kl,Vh,Vl
#define ASMEM (2 * AQT + 2 * AKV_STAGE)

__global__ __launch_bounds__(256) void attn_hmma_kernel(
    const __nv_bfloat16* __restrict__ qkvh, const __nv_bfloat16* __restrict__ qkvl,
    __nv_bfloat16* __restrict__ yh, __nv_bfloat16* __restrict__ yl)
{
    extern __shared__ char smem[];
    const uint32_t sbase = smem_u32(smem);
    const int tid = threadIdx.x;
    const int w = tid >> 5;
    const int lid = tid & 31;
    const int qt = blockIdx.x;        // 0..15
    const int h  = blockIdx.y;
    const int b  = blockIdx.z;
    const int qbase = qt * 128;
    const int nch = 2 * (qt + 1);

    const uint32_t sQh = sbase, sQl = sbase + AQT;
    const uint32_t sKV = sbase + 2 * AQT;

    const size_t rowbase = (size_t)b * CT * 3 * CD + (size_t)h * CHD;

    // --- Q load (once) ---
    {
#pragma unroll
        for (int i = 0; i < 8; i++) {
            int c = tid + (i << 8);            // 0..2047
            int t2 = c >> 10;                  // 0=h,1=l
            int row = (c >> 3) & 127;
            int seg = c & 7;
            uint32_t so = swz128((row << 7) + (seg << 4));
            size_t ga = rowbase + (size_t)(qbase + row) * (3 * CD) + (seg << 3);
            cpasync16((t2 ? sQl : sQh) + so, (t2 ? qkvl : qkvh) + ga);
        }
    }

    auto load_kv = [&](int buf, int kt0) {
        uint32_t sb = sKV + buf * AKV_STAGE;
#pragma unroll
        for (int i = 0; i < 8; i++) {
            int c = tid + (i << 8);            // 0..2047
            int tile = c >> 9;                 // 0 Kh,1 Kl,2 Vh,3 Vl
            int row = (c >> 3) & 63;
            int seg = c & 7;
            uint32_t so = swz128((row << 7) + (seg << 4));
            size_t ga = rowbase + (size_t)(kt0 + row) * (3 * CD) + (seg << 3) +
                        ((tile & 2) ? 2 * CD : CD);
            const __nv_bfloat16* src = (tile & 1) ? qkvl : qkvh;
            cpasync16(sb + tile * AKT + so, src + ga);
        }
        cp_commit();
    };

    load_kv(0, 0);                     // group 0 includes Q
    if (nch > 1) load_kv(1, 64);       // group 1

    float m0 = -INFINITY, m1 = -INFINITY, l0 = 0.0f, l1 = 0.0f;
    float oacc[8][4];
#pragma unroll
    for (int nb = 0; nb < 8; nb++)
#pragma unroll
        for (int r = 0; r < 4; r++) oacc[nb][r] = 0.0f;

    uint32_t qh[4][4], ql[4][4];       // Q fragments, preloaded after first wait
    const float scale = 0.125f;

    for (int c = 0; c < nch; c++) {
        if (c + 1 < nch) cp_wait<1>(); else cp_wait<0>();
        __syncthreads();

        if (c == 0) {
#pragma unroll
            for (int ks = 0; ks < 4; ks++) {
                uint32_t off = swz128(((w * 16 + (lid & 15)) << 7) +
                                      ((ks * 2 + (lid >> 4)) << 4));
                ldsm4(qh[ks], sQh + off);
                ldsm4(ql[ks], sQl + off);
            }
        }

        const uint32_t sb = sKV + (c & 1) * AKV_STAGE;
        const uint32_t sKh = sb, sKl = sb + AKT, sVh = sb + 2 * AKT, sVl = sb + 3 * AKT;

        // ---- S = Q @ K^T (3-pass) ----
        float sacc[8][4];
#pragma unroll
        for (int nb = 0; nb < 8; nb++)
#pragma unroll
            for (int r = 0; r < 4; r++) sacc[nb][r] = 0.0f;

#pragma unroll
        for (int ks = 0; ks < 4; ks++) {
#pragma unroll
            for (int pi = 0; pi < 4; pi++) {
                uint32_t boff = swz128(((pi * 16 + (lid & 7) + ((lid >> 4) << 3)) << 7) +
                                       ((ks * 2 + ((lid >> 3) & 1)) << 4));
                uint32_t kh4[4], kl4[4];
                ldsm4(kh4, sKh + boff);
                ldsm4(kl4, sKl + boff);
#pragma unroll
                for (int sub = 0; sub < 2; sub++) {
                    float* acc = sacc[pi * 2 + sub];
                    mma16816(acc, qh[ks], kh4 + sub * 2);
                    mma16816(acc, qh[ks], kl4 + sub * 2);
                    mma16816(acc, ql[ks], kh4 + sub * 2);
                }
            }
        }

        // ---- scale + causal mask ----
        const int row0 = qbase + w * 16 + (lid >> 2);
        const int row1 = row0 + 8;
        const bool diag = (c >= 2 * qt);
#pragma unroll
        for (int nb = 0; nb < 8; nb++) {
            int col = c * 64 + nb * 8 + ((lid & 3) << 1);
            sacc[nb][0] *= scale; sacc[nb][1] *= scale;
            sacc[nb][2] *= scale; sacc[nb][3] *= scale;
            if (diag) {
                if (col > row0)     sacc[nb][0] = -INFINITY;
                if (col + 1 > row0) sacc[nb][1] = -INFINITY;
                if (col > row1)     sacc[nb][2] = -INFINITY;
                if (col + 1 > row1) sacc[nb][3] = -INFINITY;
            }
        }

        // ---- online softmax (rows row0 via [0,1], row1 via [2,3]) ----
        {
            float mx0 = -INFINITY, mx1 = -INFINITY;
#pragma unroll
            for (int nb = 0; nb < 8; nb++) {
                mx0 = fmaxf(mx0, fmaxf(sacc[nb][0], sacc[nb][1]));
                mx1 = fmaxf(mx1, fmaxf(sacc[nb][2], sacc[nb][3]));
            }
            mx0 = fmaxf(mx0, __shfl_xor_sync(0xffffffffu, mx0, 1));
            mx0 = fmaxf(mx0, __shfl_xor_sync(0xffffffffu, mx0, 2));
            mx1 = fmaxf(mx1, __shfl_xor_sync(0xffffffffu, mx1, 1));
            mx1 = fmaxf(mx1, __shfl_xor_sync(0xffffffffu, mx1, 2));
            float mn0 = fmaxf(m0, mx0), mn1 = fmaxf(m1, mx1);
            float f0 = __expf(m0 - mn0), f1 = __expf(m1 - mn1);
            float s0 = 0.0f, s1 = 0.0f;
#pragma unroll
            for (int nb = 0; nb < 8; nb++) {
                sacc[nb][0] = __expf(sacc[nb][0] - mn0);
                sacc[nb][1] = __expf(sacc[nb][1] - mn0);
                sacc[nb][2] = __expf(sacc[nb][2] - mn1);
                sacc[nb][3] = __expf(sacc[nb][3] - mn1);
                s0 += sacc[nb][0] + sacc[nb][1];
                s1 += sacc[nb][2] + sacc[nb][3];
            }
            s0 += __shfl_xor_sync(0xffffffffu, s0, 1);
            s0 += __shfl_xor_sync(0xffffffffu, s0, 2);
            s1 += __shfl_xor_sync(0xffffffffu, s1, 1);
            s1 += __shfl_xor_sync(0xffffffffu, s1, 2);
            l0 = l0 * f0 + s0; l1 = l1 * f1 + s1;
            m0 = mn0; m1 = mn1;
#pragma unroll
            for (int nb = 0; nb < 8; nb++) {
                oacc[nb][0] *= f0; oacc[nb][1] *= f0;
                oacc[nb][2] *= f1; oacc[nb][3] *= f1;
            }
        }

        // ---- O += P @ V (3-pass; P from sacc, V via trans ldmatrix) ----
#pragma unroll
        for (int kp = 0; kp < 4; kp++) {
            uint32_t ph[4], pl[4];
            {
                float p00 = sacc[2 * kp][0], p01 = sacc[2 * kp][1];
                float p10 = sacc[2 * kp][2], p11 = sacc[2 * kp][3];
                float p20 = sacc[2 * kp + 1][0], p21 = sacc[2 * kp + 1][1];
                float p30 = sacc[2 * kp + 1][2], p31 = sacc[2 * kp + 1][3];
                float h00 = __bfloat162float(__float2bfloat16(p00));
                float h01 = __bfloat162float(__float2bfloat16(p01));
                float h10 = __bfloat162float(__float2bfloat16(p10));
                float h11 = __bfloat162float(__float2bfloat16(p11));
                float h20 = __bfloat162float(__float2bfloat16(p20));
                float h21 = __bfloat162float(__float2bfloat16(p21));
                float h30 = __bfloat162float(__float2bfloat16(p30));
                float h31 = __bfloat162float(__float2bfloat16(p31));
                ph[0] = pack_bf16(h00, h01); ph[1] = pack_bf16(h10, h11);
                ph[2] = pack_bf16(h20, h21); ph[3] = pack_bf16(h30, h31);
                pl[0] = pack_bf16(p00 - h00, p01 - h01);
                pl[1] = pack_bf16(p10 - h10, p11 - h11);
                pl[2] = pack_bf16(p20 - h20, p21 - h21);
                pl[3] = pack_bf16(p30 - h30, p31 - h31);
            }
            const int mi = lid >> 3, r8 = lid & 7;
#pragma unroll
            for (int pi = 0; pi < 4; pi++) {
                // trans ldmatrix: lane -> V[key = kp*16 + (mi&1)*8 + r8][hd = pi*16 + (mi>>1)*8]
                uint32_t voff = swz128(((kp * 16 + ((mi & 1) << 3) + r8) << 7) +
                                       ((pi * 16 + ((mi >> 1) << 3)) << 1));
                uint32_t vh4[4], vl4[4];
                ldsm4t(vh4, sVh + voff);
                ldsm4t(vl4, sVl + voff);
#pragma unroll
                for (int sub = 0; sub < 2; sub++) {
                    float* acc = oacc[pi * 2 + sub];
                    mma16816(acc, ph, vh4 + sub * 2);
                    mma16816(acc, ph, vl4 + sub * 2);
                    mma16816(acc, pl, vh4 + sub * 2);
                }
            }
        }

        __syncthreads();
        if (c + 2 < nch) load_kv(c & 1, (c + 2) << 6);
    }

    // ---- epilogue: normalize, split to bf16 hi/lo, store ----
    const float inv0 = 1.0f / l0, inv1 = 1.0f / l1;
    const int row0 = qbase + w * 16 + (lid >> 2);
    __nv_bfloat16* yhb = yh + (size_t)b * CT * CD + (size_t)h * CHD;
    __nv_bfloat16* ylb = yl + (size_t)b * CT * CD + (size_t)h * CHD;
#pragma unroll
    for (int nb = 0; nb < 8; nb++) {
        int col = nb * 8 + ((lid & 3) << 1);
        float v00 = oacc[nb][0] * inv0, v01 = oacc[nb][1] * inv0;
        float v10 = oacc[nb][2] * inv1, v11 = oacc[nb][3] * inv1;
        float h00 = __bfloat162float(__float2bfloat16(v00));
        float h01 = __bfloat162float(__float2bfloat16(v01));
        float h10 = __bfloat162float(__float2bfloat16(v10));
        float h11 = __bfloat162float(__float2bfloat16(v11));
        *(uint32_t*)&yhb[(size_t)row0 * CD + col] = pack_bf16(h00, h01);
        *(uint32_t*)&yhb[(size_t)(row0 + 8) * CD + col] = pack_bf16(h10, h11);
        *(uint32_t*)&ylb[(size_t)row0 * CD + col] = pack_bf16(v00 - h00, v01 - h01);
        *(uint32_t*)&ylb[(size_t)(row0 + 8) * CD + col] = pack_bf16(v10 - h10, v11 - h11);
    }
}

// ---------------------------------------------------------------------------
// Launch
// ---------------------------------------------------------------------------
extern "C" void kernel_launch(void* const* d_in, const int* in_sizes, int n_in,
                              void* d_out, int out_size)
{
    (void)in_sizes; (void)n_in; (void)out_size;
    const float* x  = (const float*)d_in[0];
    const float* W1 = (const float*)d_in[1];
    const float* b1 = (const float*)d_in[2];
    const float* W2 = (const float*)d_in[3];
    const float* b2 = (const float*)d_in[4];
    float* out = (float*)d_out;

    __nv_bfloat16 *qkvh, *qkvl, *xh, *xl, *yh, *yl, *w1th, *w1tl, *w2th, *w2tl;
    cudaGetSymbolAddress((void**)&qkvh, g_qkvh);
    cudaGetSymbolAddress((void**)&qkvl, g_qkvl);
    cudaGetSymbolAddress((void**)&xh, g_xh);
    cudaGetSymbolAddress((void**)&xl, g_xl);
    cudaGetSymbolAddress((void**)&yh, g_yh);
    cudaGetSymbolAddress((void**)&yl, g_yl);
    cudaGetSymbolAddress((void**)&w1th, g_w1th);
    cudaGetSymbolAddress((void**)&w1tl, g_w1tl);
    cudaGetSymbolAddress((void**)&w2th, g_w2th);
    cudaGetSymbolAddress((void**)&w2tl, g_w2tl);

    static int smem_set = 0;
    if (!smem_set) {
        cudaFuncSetAttribute(gemm_hmma3_kernel<true>,
                             cudaFuncAttributeMaxDynamicSharedMemorySize, HSMEM);
        cudaFuncSetAttribute(gemm_hmma3_kernel<false>,
                             cudaFuncAttributeMaxDynamicSharedMemorySize, HSMEM);
        cudaFuncSetAttribute(attn_hmma_kernel,
                             cudaFuncAttributeMaxDynamicSharedMemorySize, ASMEM);
        smem_set = 1;
    }

    const int M = CB * CT;                 // 4096
    const int n4x = M * CD / 4;

    split_kernel<<<(n4x + 255) / 256, 256>>>(x, xh, xl, n4x);
    split_transpose_kernel<<<dim3(3 * CD / 32, CD / 32), dim3(32, 8)>>>(W1, w1th, w1tl, CD, 3 * CD);
    split_transpose_kernel<<<dim3(CD / 32, CD / 32), dim3(32, 8)>>>(W2, w2th, w2tl, CD, CD);

    // qkv (bf16 hi/lo) = x @ W1 + b1
    gemm_hmma3_kernel<true><<<dim3(3 * CD / 128, M / 128), 256, HSMEM>>>(
        xh, xl, w1th, w1tl, b1, nullptr, qkvh, qkvl, 3 * CD, CD);

    // flash attention -> y (bf16 hi/lo)
    attn_hmma_kernel<<<dim3(CT / 128, CH, CB), 256, ASMEM>>>(qkvh, qkvl, yh, yl);

    // out (fp32) = y @ W2 + b2
    gemm_hmma3_kernel<false><<<dim3(CD / 128, M / 128), 256, HSMEM>>>(
        yh, yl, w2th, w2tl, b2, out, nullptr, nullptr, CD, CD);
}

// round 5
// speedup vs baseline: 4.1358x; 1.4360x over previous
#include <cuda_runtime.h>
#include <cuda_fp16.h>
#include <math.h>
#include <stdint.h>

#define CB 2
#define CT 2048
#define CD 1024
#define CH 16
#define CHD 64

// ---------------------------------------------------------------------------
// Device scratch (no cudaMalloc allowed)
// A-side operands are split fp16 hi/lo; B-side single fp16.
// ---------------------------------------------------------------------------
__device__ __align__(128) __half g_qkvh[(size_t)CB * CT * 3 * CD];
__device__ __align__(128) __half g_qkvl[(size_t)CB * CT * 3 * CD];  // lo used for Q cols only
__device__ __align__(128) __half g_xh[(size_t)CB * CT * CD];
__device__ __align__(128) __half g_xl[(size_t)CB * CT * CD];
__device__ __align__(128) __half g_yh[(size_t)CB * CT * CD];
__device__ __align__(128) __half g_yl[(size_t)CB * CT * CD];
__device__ __align__(128) __half g_w1t[(size_t)3 * CD * CD];        // W1^T [N,K]
__device__ __align__(128) __half g_w2t[(size_t)CD * CD];            // W2^T [N,K]

// ---------------------------------------------------------------------------
// Low-level helpers (sm_80+ : cp.async, ldmatrix, mma.sync)
// ---------------------------------------------------------------------------
__device__ __forceinline__ uint32_t smem_u32(const void* p) {
    uint32_t a;
    asm("{ .reg .u64 t; cvta.to.shared.u64 t, %1; cvt.u32.u64 %0, t; }" : "=r"(a) : "l"(p));
    return a;
}
__device__ __forceinline__ void cpasync16(uint32_t s, const void* g) {
    asm volatile("cp.async.cg.shared.global [%0], [%1], 16;" :: "r"(s), "l"(g));
}
__device__ __forceinline__ void cp_commit() {
    asm volatile("cp.async.commit_group;" ::: "memory");
}
template <int N>
__device__ __forceinline__ void cp_wait() {
    asm volatile("cp.async.wait_group %0;" :: "n"(N) : "memory");
}
__device__ __forceinline__ void ldsm4(uint32_t* r, uint32_t addr) {
    asm volatile("ldmatrix.sync.aligned.m8n8.x4.shared.b16 {%0,%1,%2,%3}, [%4];"
                 : "=r"(r[0]), "=r"(r[1]), "=r"(r[2]), "=r"(r[3]) : "r"(addr));
}
__device__ __forceinline__ void ldsm4t(uint32_t* r, uint32_t addr) {
    asm volatile("ldmatrix.sync.aligned.m8n8.x4.trans.shared.b16 {%0,%1,%2,%3}, [%4];"
                 : "=r"(r[0]), "=r"(r[1]), "=r"(r[2]), "=r"(r[3]) : "r"(addr));
}
__device__ __forceinline__ void mma16816(float* d, const uint32_t* a, const uint32_t* b) {
    asm volatile(
        "mma.sync.aligned.m16n8k16.row.col.f32.f16.f16.f32 "
        "{%0,%1,%2,%3}, {%4,%5,%6,%7}, {%8,%9}, {%0,%1,%2,%3};"
        : "+f"(d[0]), "+f"(d[1]), "+f"(d[2]), "+f"(d[3])
        : "r"(a[0]), "r"(a[1]), "r"(a[2]), "r"(a[3]), "r"(b[0]), "r"(b[1]));
}
__device__ __forceinline__ uint32_t swz128(uint32_t b) { return b ^ ((b >> 3) & 0x70); }
__device__ __forceinline__ uint32_t pack_f16(float a, float b) {
    __half2 v = __floats2half2_rn(a, b);
    return *(uint32_t*)&v;
}
__device__ __forceinline__ float f16round(float v) {
    return __half2float(__float2half_rn(v));
}

// ---------------------------------------------------------------------------
// fp32 -> fp16 hi/lo split (x)
// ---------------------------------------------------------------------------
__global__ __launch_bounds__(256) void split_kernel(
    const float* __restrict__ in, __half* __restrict__ hi,
    __half* __restrict__ lo, int n4)
{
    int i = blockIdx.x * blockDim.x + threadIdx.x;
    if (i >= n4) return;
    float4 v = ((const float4*)in)[i];
    float h0 = f16round(v.x), h1 = f16round(v.y), h2 = f16round(v.z), h3 = f16round(v.w);
    ((uint2*)hi)[i] = make_uint2(pack_f16(h0, h1), pack_f16(h2, h3));
    ((uint2*)lo)[i] = make_uint2(pack_f16(v.x - h0, v.y - h1), pack_f16(v.z - h2, v.w - h3));
}

// ---------------------------------------------------------------------------
// W [K,N] fp32 -> Wt [N,K] single fp16 (transpose)
// ---------------------------------------------------------------------------
__global__ __launch_bounds__(256) void transpose_f16_kernel(
    const float* __restrict__ W, __half* __restrict__ outh, int K, int N)
{
    __shared__ float t[32][33];
    int n0 = blockIdx.x * 32, k0 = blockIdx.y * 32;
    int tx = threadIdx.x, ty = threadIdx.y;
#pragma unroll
    for (int j = 0; j < 4; j++)
        t[ty + j * 8][tx] = W[(size_t)(k0 + ty + j * 8) * N + n0 + tx];
    __syncthreads();
#pragma unroll
    for (int j = 0; j < 4; j++)
        outh[(size_t)(n0 + ty + j * 8) * K + k0 + tx] = __float2half_rn(t[tx][ty + j * 8]);
}

// ---------------------------------------------------------------------------
// HMMA fp16 2-pass GEMM: C = (Ah+Al) @ Bt^T + bias.
// CTA 128x128, BK=64, 8 warps (4m x 2n); stage = Ah+Al+B = 48KB, 2 stages.
// F16OUT: write hi fp16 always, lo fp16 when bn < loN; else fp32.
// ---------------------------------------------------------------------------
#define HTILE 16384
#define HSTAGE (3 * HTILE)
#define HSMEM (2 * HSTAGE)          // 98304 -> 2 CTAs/SM

template <bool F16OUT>
__global__ __launch_bounds__(256, 2) void gemm_f16x2_kernel(
    const __half* __restrict__ Ahg, const __half* __restrict__ Alg,
    const __half* __restrict__ Bg, const float* __restrict__ bias,
    float* __restrict__ Cf, __half* __restrict__ Ch, __half* __restrict__ Cl,
    int loN, int N, int K)
{
    extern __shared__ char smem[];
    const uint32_t sbase = smem_u32(smem);
    const int tid = threadIdx.x;
    const int wid = tid >> 5;
    const int lid = tid & 31;
    const int wm = wid & 3;
    const int wn = wid >> 2;
    const int bm = blockIdx.y * 128;
    const int bn = blockIdx.x * 128;

    const int nch = K >> 6;

    auto load_stage = [&](int buf, int k0) {
        uint32_t sb = sbase + buf * HSTAGE;
#pragma unroll
        for (int i = 0; i < 12; i++) {
            int c = tid + (i << 8);              // 0..3071
            int tile = c >> 10;                  // 0 Ah, 1 Al, 2 B
            int row = (c >> 3) & 127;
            int seg = c & 7;
            uint32_t so = swz128((row << 7) + (seg << 4));
            const __half* src = (tile == 0) ? Ahg : (tile == 1) ? Alg : Bg;
            size_t g = (size_t)((tile == 2 ? bn : bm) + row) * K + k0 + (seg << 3);
            cpasync16(sb + tile * HTILE + so, src + g);
        }
        cp_commit();
    };

    float d[2][8][4];
#pragma unroll
    for (int mi = 0; mi < 2; mi++)
#pragma unroll
        for (int ni = 0; ni < 8; ni++)
#pragma unroll
            for (int r = 0; r < 4; r++) d[mi][ni][r] = 0.0f;

    load_stage(0, 0);
    load_stage(1, 64);

    for (int c = 0; c < nch; c++) {
        if (c + 1 < nch) cp_wait<1>(); else cp_wait<0>();
        __syncthreads();

        const uint32_t sb = sbase + (c & 1) * HSTAGE;
        const uint32_t aTh = sb, aTl = sb + HTILE, bT = sb + 2 * HTILE;

#pragma unroll
        for (int ks = 0; ks < 4; ks++) {
            uint32_t ah[2][4], al[2][4];
#pragma unroll
            for (int mi = 0; mi < 2; mi++) {
                uint32_t off = swz128(((wm * 32 + mi * 16 + (lid & 15)) << 7) +
                                      ((ks * 2 + (lid >> 4)) << 4));
                ldsm4(ah[mi], aTh + off);
                ldsm4(al[mi], aTl + off);
            }
#pragma unroll
            for (int pi = 0; pi < 4; pi++) {
                uint32_t boff = swz128(((wn * 64 + pi * 16 + (lid & 7) + ((lid >> 4) << 3)) << 7) +
                                       ((ks * 2 + ((lid >> 3) & 1)) << 4));
                uint32_t b4[4];
                ldsm4(b4, bT + boff);
#pragma unroll
                for (int mi = 0; mi < 2; mi++) {
#pragma unroll
                    for (int sub = 0; sub < 2; sub++) {
                        float* acc = d[mi][pi * 2 + sub];
                        mma16816(acc, ah[mi], b4 + sub * 2);   // Ah*B
                        mma16816(acc, al[mi], b4 + sub * 2);   // Al*B
                    }
                }
            }
        }
        __syncthreads();
        if (c + 2 < nch) load_stage(c & 1, (c + 2) << 6);
    }

    const bool writeLo = F16OUT && (bn < loN);
#pragma unroll
    for (int mi = 0; mi < 2; mi++) {
        int row = bm + wm * 32 + mi * 16 + (lid >> 2);
#pragma unroll
        for (int ni = 0; ni < 8; ni++) {
            int col = bn + wn * 64 + ni * 8 + ((lid & 3) << 1);
            float2 bv = *(const float2*)&bias[col];
            float v00 = d[mi][ni][0] + bv.x, v01 = d[mi][ni][1] + bv.y;
            float v10 = d[mi][ni][2] + bv.x, v11 = d[mi][ni][3] + bv.y;
            if (F16OUT) {
                float h00 = f16round(v00), h01 = f16round(v01);
                float h10 = f16round(v10), h11 = f16round(v11);
                *(uint32_t*)&Ch[(size_t)row * N + col] = pack_f16(h00, h01);
                *(uint32_t*)&Ch[(size_t)(row + 8) * N + col] = pack_f16(h10, h11);
                if (writeLo) {
                    *(uint32_t*)&Cl[(size_t)row * N + col] = pack_f16(v00 - h00, v01 - h01);
                    *(uint32_t*)&Cl[(size_t)(row + 8) * N + col] = pack_f16(v10 - h10, v11 - h11);
                }
            } else {
                *(float2*)&Cf[(size_t)row * N + col] = make_float2(v00, v01);
                *(float2*)&Cf[(size_t)(row + 8) * N + col] = make_float2(v10, v11);
            }
        }
    }
}

// ---------------------------------------------------------------------------
// HMMA fp16 flash attention. CTA = 128 q-rows. Q split hi/lo, K/V single fp16.
// P split hi/lo in registers. 2-pass on both MMAs. Big q-tiles scheduled first.
// ---------------------------------------------------------------------------
#define AQT 16384                     // 128 x 128B
#define AKT 8192                      // 64 x 128B
#define AKV_STAGE (2 * AKT)           // K, V
#define ASMEM (2 * AQT + 2 * AKV_STAGE)   // 65536 -> 2 CTAs/SM

__global__ __launch_bounds__(256, 2) void attn_f16_kernel(
    const __half* __restrict__ qkvh, const __half* __restrict__ qkvl,
    __half* __restrict__ yh, __half* __restrict__ yl)
{
    extern __shared__ char smem[];
    const uint32_t sbase = smem_u32(smem);
    const int tid = threadIdx.x;
    const int w = tid >> 5;
    const int lid = tid & 31;
    const int qt = gridDim.x - 1 - blockIdx.x;   // biggest causal tiles first
    const int h  = blockIdx.y;
    const int b  = blockIdx.z;
    const int qbase = qt * 128;
    const int nch = 2 * (qt + 1);

    const uint32_t sQh = sbase, sQl = sbase + AQT;
    const uint32_t sKV = sbase + 2 * AQT;

    const size_t rowbase = (size_t)b * CT * 3 * CD + (size_t)h * CHD;

    // --- Q load (once) ---
#pragma unroll
    for (int i = 0; i < 8; i++) {
        int c = tid + (i << 8);            // 0..2047
        int t2 = c >> 10;                  // 0=h,1=l
        int row = (c >> 3) & 127;
        int seg = c & 7;
        uint32_t so = swz128((row << 7) + (seg << 4));
        size_t ga = rowbase + (size_t)(qbase + row) * (3 * CD) + (seg << 3);
        cpasync16((t2 ? sQl : sQh) + so, (t2 ? qkvl : qkvh) + ga);
    }

    auto load_kv = [&](int buf, int kt0) {
        uint32_t sb = sKV + buf * AKV_STAGE;
#pragma unroll
        for (int i = 0; i < 4; i++) {
            int c = tid + (i << 8);            // 0..1023
            int tile = c >> 9;                 // 0 K, 1 V
            int row = (c >> 3) & 63;
            int seg = c & 7;
            uint32_t so = swz128((row << 7) + (seg << 4));
            size_t ga = rowbase + (size_t)(kt0 + row) * (3 * CD) + (seg << 3) +
                        (tile ? 2 * CD : CD);
            cpasync16(sb + tile * AKT + so, qkvh + ga);
        }
        cp_commit();
    };

    load_kv(0, 0);
    if (nch > 1) load_kv(1, 64);

    float m0 = -INFINITY, m1 = -INFINITY, l0 = 0.0f, l1 = 0.0f;
    float oacc[8][4];
#pragma unroll
    for (int nb = 0; nb < 8; nb++)
#pragma unroll
        for (int r = 0; r < 4; r++) oacc[nb][r] = 0.0f;

    uint32_t qh[4][4], ql[4][4];
    const float scale = 0.125f;

    for (int c = 0; c < nch; c++) {
        if (c + 1 < nch) cp_wait<1>(); else cp_wait<0>();
        __syncthreads();

        if (c == 0) {
#pragma unroll
            for (int ks = 0; ks < 4; ks++) {
                uint32_t off = swz128(((w * 16 + (lid & 15)) << 7) +
                                      ((ks * 2 + (lid >> 4)) << 4));
                ldsm4(qh[ks], sQh + off);
                ldsm4(ql[ks], sQl + off);
            }
        }

        const uint32_t sb = sKV + (c & 1) * AKV_STAGE;
        const uint32_t sK = sb, sV = sb + AKT;

        // ---- S = Q @ K^T (2-pass) ----
        float sacc[8][4];
#pragma unroll
        for (int nb = 0; nb < 8; nb++)
#pragma unroll
            for (int r = 0; r < 4; r++) sacc[nb][r] = 0.0f;

#pragma unroll
        for (int ks = 0; ks < 4; ks++) {
#pragma unroll
            for (int pi = 0; pi < 4; pi++) {
                uint32_t boff = swz128(((pi * 16 + (lid & 7) + ((lid >> 4) << 3)) << 7) +
                                       ((ks * 2 + ((lid >> 3) & 1)) << 4));
                uint32_t k4[4];
                ldsm4(k4, sK + boff);
#pragma unroll
                for (int sub = 0; sub < 2; sub++) {
                    float* acc = sacc[pi * 2 + sub];
                    mma16816(acc, qh[ks], k4 + sub * 2);
                    mma16816(acc, ql[ks], k4 + sub * 2);
                }
            }
        }

        // ---- scale + causal mask ----
        const int row0 = qbase + w * 16 + (lid >> 2);
        const int row1 = row0 + 8;
        const bool diag = (c >= 2 * qt);
#pragma unroll
        for (int nb = 0; nb < 8; nb++) {
            int col = c * 64 + nb * 8 + ((lid & 3) << 1);
            sacc[nb][0] *= scale; sacc[nb][1] *= scale;
            sacc[nb][2] *= scale; sacc[nb][3] *= scale;
            if (diag) {
                if (col > row0)     sacc[nb][0] = -INFINITY;
                if (col + 1 > row0) sacc[nb][1] = -INFINITY;
                if (col > row1)     sacc[nb][2] = -INFINITY;
                if (col + 1 > row1) sacc[nb][3] = -INFINITY;
            }
        }

        // ---- online softmax ----
        {
            float mx0 = -INFINITY, mx1 = -INFINITY;
#pragma unroll
            for (int nb = 0; nb < 8; nb++) {
                mx0 = fmaxf(mx0, fmaxf(sacc[nb][0], sacc[nb][1]));
                mx1 = fmaxf(mx1, fmaxf(sacc[nb][2], sacc[nb][3]));
            }
            mx0 = fmaxf(mx0, __shfl_xor_sync(0xffffffffu, mx0, 1));
            mx0 = fmaxf(mx0, __shfl_xor_sync(0xffffffffu, mx0, 2));
            mx1 = fmaxf(mx1, __shfl_xor_sync(0xffffffffu, mx1, 1));
            mx1 = fmaxf(mx1, __shfl_xor_sync(0xffffffffu, mx1, 2));
            float mn0 = fmaxf(m0, mx0), mn1 = fmaxf(m1, mx1);
            float f0 = __expf(m0 - mn0), f1 = __expf(m1 - mn1);
            float s0 = 0.0f, s1 = 0.0f;
#pragma unroll
            for (int nb = 0; nb < 8; nb++) {
                sacc[nb][0] = __expf(sacc[nb][0] - mn0);
                sacc[nb][1] = __expf(sacc[nb][1] - mn0);
                sacc[nb][2] = __expf(sacc[nb][2] - mn1);
                sacc[nb][3] = __expf(sacc[nb][3] - mn1);
                s0 += sacc[nb][0] + sacc[nb][1];
                s1 += sacc[nb][2] + sacc[nb][3];
            }
            s0 += __shfl_xor_sync(0xffffffffu, s0, 1);
            s0 += __shfl_xor_sync(0xffffffffu, s0, 2);
            s1 += __shfl_xor_sync(0xffffffffu, s1, 1);
            s1 += __shfl_xor_sync(0xffffffffu, s1, 2);
            l0 = l0 * f0 + s0; l1 = l1 * f1 + s1;
            m0 = mn0; m1 = mn1;
#pragma unroll
            for (int nb = 0; nb < 8; nb++) {
                oacc[nb][0] *= f0; oacc[nb][1] *= f0;
                oacc[nb][2] *= f1; oacc[nb][3] *= f1;
            }
        }

        // ---- O += P @ V (2-pass; P hi/lo, V single) ----
#pragma unroll
        for (int kp = 0; kp < 4; kp++) {
            uint32_t ph[4], pl[4];
            {
                float p00 = sacc[2 * kp][0], p01 = sacc[2 * kp][1];
                float p10 = sacc[2 * kp][2], p11 = sacc[2 * kp][3];
                float p20 = sacc[2 * kp + 1][0], p21 = sacc[2 * kp + 1][1];
                float p30 = sacc[2 * kp + 1][2], p31 = sacc[2 * kp + 1][3];
                float h00 = f16round(p00), h01 = f16round(p01);
                float h10 = f16round(p10), h11 = f16round(p11);
                float h20 = f16round(p20), h21 = f16round(p21);
                float h30 = f16round(p30), h31 = f16round(p31);
                ph[0] = pack_f16(h00, h01); ph[1] = pack_f16(h10, h11);
                ph[2] = pack_f16(h20, h21); ph[3] = pack_f16(h30, h31);
                pl[0] = pack_f16(p00 - h00, p01 - h01);
                pl[1] = pack_f16(p10 - h10, p11 - h11);
                pl[2] = pack_f16(p20 - h20, p21 - h21);
                pl[3] = pack_f16(p30 - h30, p31 - h31);
            }
            const int mi = lid >> 3, r8 = lid & 7;
#pragma unroll
            for (int pi = 0; pi < 4; pi++) {
                uint32_t voff = swz128(((kp * 16 + ((mi & 1) << 3) + r8) << 7) +
                                       ((pi * 16 + ((mi >> 1) << 3)) << 1));
                uint32_t v4[4];
                ldsm4t(v4, sV + voff);
#pragma unroll
                for (int sub = 0; sub < 2; sub++) {
                    float* acc = oacc[pi * 2 + sub];
                    mma16816(acc, ph, v4 + sub * 2);
                    mma16816(acc, pl, v4 + sub * 2);
                }
            }
        }

        __syncthreads();
        if (c + 2 < nch) load_kv(c & 1, (c + 2) << 6);
    }

    // ---- epilogue: normalize, split to fp16 hi/lo ----
    const float inv0 = 1.0f / l0, inv1 = 1.0f / l1;
    const int row0 = qbase + w * 16 + (lid >> 2);
    __half* yhb = yh + (size_t)b * CT * CD + (size_t)h * CHD;
    __half* ylb = yl + (size_t)b * CT * CD + (size_t)h * CHD;
#pragma unroll
    for (int nb = 0; nb < 8; nb++) {
        int col = nb * 8 + ((lid & 3) << 1);
        float v00 = oacc[nb][0] * inv0, v01 = oacc[nb][1] * inv0;
        float v10 = oacc[nb][2] * inv1, v11 = oacc[nb][3] * inv1;
        float h00 = f16round(v00), h01 = f16round(v01);
        float h10 = f16round(v10), h11 = f16round(v11);
        *(uint32_t*)&yhb[(size_t)row0 * CD + col] = pack_f16(h00, h01);
        *(uint32_t*)&yhb[(size_t)(row0 + 8) * CD + col] = pack_f16(h10, h11);
        *(uint32_t*)&ylb[(size_t)row0 * CD + col] = pack_f16(v00 - h00, v01 - h01);
        *(uint32_t*)&ylb[(size_t)(row0 + 8) * CD + col] = pack_f16(v10 - h10, v11 - h11);
    }
}

// ---------------------------------------------------------------------------
// Launch
// ---------------------------------------------------------------------------
extern "C" void kernel_launch(void* const* d_in, const int* in_sizes, int n_in,
                              void* d_out, int out_size)
{
    (void)in_sizes; (void)n_in; (void)out_size;
    const float* x  = (const float*)d_in[0];
    const float* W1 = (const float*)d_in[1];
    const float* b1 = (const float*)d_in[2];
    const float* W2 = (const float*)d_in[3];
    const float* b2 = (const float*)d_in[4];
    float* out = (float*)d_out;

    __half *qkvh, *qkvl, *xh, *xl, *yh, *yl, *w1t, *w2t;
    cudaGetSymbolAddress((void**)&qkvh, g_qkvh);
    cudaGetSymbolAddress((void**)&qkvl, g_qkvl);
    cudaGetSymbolAddress((void**)&xh, g_xh);
    cudaGetSymbolAddress((void**)&xl, g_xl);
    cudaGetSymbolAddress((void**)&yh, g_yh);
    cudaGetSymbolAddress((void**)&yl, g_yl);
    cudaGetSymbolAddress((void**)&w1t, g_w1t);
    cudaGetSymbolAddress((void**)&w2t, g_w2t);

    cudaFuncSetAttribute(gemm_f16x2_kernel<true>,
                         cudaFuncAttributeMaxDynamicSharedMemorySize, HSMEM);
    cudaFuncSetAttribute(gemm_f16x2_kernel<false>,
                         cudaFuncAttributeMaxDynamicSharedMemorySize, HSMEM);
    cudaFuncSetAttribute(attn_f16_kernel,
                         cudaFuncAttributeMaxDynamicSharedMemorySize, ASMEM);

    const int M = CB * CT;                 // 4096
    const int n4x = M * CD / 4;

    split_kernel<<<(n4x + 255) / 256, 256>>>(x, xh, xl, n4x);
    transpose_f16_kernel<<<dim3(3 * CD / 32, CD / 32), dim3(32, 8)>>>(W1, w1t, CD, 3 * CD);
    transpose_f16_kernel<<<dim3(CD / 32, CD / 32), dim3(32, 8)>>>(W2, w2t, CD, CD);

    // qkv (fp16 hi, + lo for Q cols) = x @ W1 + b1
    gemm_f16x2_kernel<true><<<dim3(3 * CD / 128, M / 128), 256, HSMEM>>>(
        xh, xl, w1t, b1, nullptr, qkvh, qkvl, CD, 3 * CD, CD);

    // flash attention -> y (fp16 hi/lo)
    attn_f16_kernel<<<dim3(CT / 128, CH, CB), 256, ASMEM>>>(qkvh, qkvl, yh, yl);

    // out (fp32) = y @ W2 + b2
    gemm_f16x2_kernel<false><<<dim3(CD / 128, M / 128), 256, HSMEM>>>(
        yh, yl, w2t, b2, out, nullptr, nullptr, 0, CD, CD);
}

// round 6
// speedup vs baseline: 4.7024x; 1.1370x over previous
#include <cuda_runtime.h>
#include <cuda_fp16.h>
#include <math.h>
#include <stdint.h>

#define CB 2
#define CT 2048
#define CD 1024
#define CH 16
#define CHD 64

// ---------------------------------------------------------------------------
// Device scratch (no cudaMalloc allowed)
// A-side operands split fp16 hi/lo; B-side single fp16.
// ---------------------------------------------------------------------------
__device__ __align__(128) __half g_qkvh[(size_t)CB * CT * 3 * CD];
__device__ __align__(128) __half g_qkvl[(size_t)CB * CT * 3 * CD];  // lo written for Q cols only
__device__ __align__(128) __half g_xh[(size_t)CB * CT * CD];
__device__ __align__(128) __half g_xl[(size_t)CB * CT * CD];
__device__ __align__(128) __half g_yh[(size_t)CB * CT * CD];
__device__ __align__(128) __half g_yl[(size_t)CB * CT * CD];
__device__ __align__(128) __half g_w1t[(size_t)3 * CD * CD];        // W1^T [N,K]
__device__ __align__(128) __half g_w2t[(size_t)CD * CD];            // W2^T [N,K]

// ---------------------------------------------------------------------------
// Low-level helpers
// ---------------------------------------------------------------------------
__device__ __forceinline__ uint32_t smem_u32(const void* p) {
    uint32_t a;
    asm("{ .reg .u64 t; cvta.to.shared.u64 t, %1; cvt.u32.u64 %0, t; }" : "=r"(a) : "l"(p));
    return a;
}
__device__ __forceinline__ void cpasync16(uint32_t s, const void* g) {
    asm volatile("cp.async.cg.shared.global [%0], [%1], 16;" :: "r"(s), "l"(g));
}
__device__ __forceinline__ void cp_commit() {
    asm volatile("cp.async.commit_group;" ::: "memory");
}
template <int N>
__device__ __forceinline__ void cp_wait() {
    asm volatile("cp.async.wait_group %0;" :: "n"(N) : "memory");
}
__device__ __forceinline__ void ldsm4(uint32_t* r, uint32_t addr) {
    asm volatile("ldmatrix.sync.aligned.m8n8.x4.shared.b16 {%0,%1,%2,%3}, [%4];"
                 : "=r"(r[0]), "=r"(r[1]), "=r"(r[2]), "=r"(r[3]) : "r"(addr));
}
__device__ __forceinline__ void ldsm4t(uint32_t* r, uint32_t addr) {
    asm volatile("ldmatrix.sync.aligned.m8n8.x4.trans.shared.b16 {%0,%1,%2,%3}, [%4];"
                 : "=r"(r[0]), "=r"(r[1]), "=r"(r[2]), "=r"(r[3]) : "r"(addr));
}
__device__ __forceinline__ void mma16816(float* d, const uint32_t* a, const uint32_t* b) {
    asm volatile(
        "mma.sync.aligned.m16n8k16.row.col.f32.f16.f16.f32 "
        "{%0,%1,%2,%3}, {%4,%5,%6,%7}, {%8,%9}, {%0,%1,%2,%3};"
        : "+f"(d[0]), "+f"(d[1]), "+f"(d[2]), "+f"(d[3])
        : "r"(a[0]), "r"(a[1]), "r"(a[2]), "r"(a[3]), "r"(b[0]), "r"(b[1]));
}
__device__ __forceinline__ uint32_t swz128(uint32_t b) { return b ^ ((b >> 3) & 0x70); }
__device__ __forceinline__ uint32_t pack_f16(float a, float b) {
    __half2 v = __floats2half2_rn(a, b);
    return *(uint32_t*)&v;
}
__device__ __forceinline__ float f16round(float v) {
    return __half2float(__float2half_rn(v));
}

// ---------------------------------------------------------------------------
// fp32 -> fp16 hi/lo split (x)
// ---------------------------------------------------------------------------
__global__ __launch_bounds__(256) void split_kernel(
    const float* __restrict__ in, __half* __restrict__ hi,
    __half* __restrict__ lo, int n4)
{
    int i = blockIdx.x * blockDim.x + threadIdx.x;
    if (i >= n4) return;
    float4 v = ((const float4*)in)[i];
    float h0 = f16round(v.x), h1 = f16round(v.y), h2 = f16round(v.z), h3 = f16round(v.w);
    ((uint2*)hi)[i] = make_uint2(pack_f16(h0, h1), pack_f16(h2, h3));
    ((uint2*)lo)[i] = make_uint2(pack_f16(v.x - h0, v.y - h1), pack_f16(v.z - h2, v.w - h3));
}

// ---------------------------------------------------------------------------
// W [K,N] fp32 -> Wt [N,K] single fp16 (transpose)
// ---------------------------------------------------------------------------
__global__ __launch_bounds__(256) void transpose_f16_kernel(
    const float* __restrict__ W, __half* __restrict__ outh, int K, int N)
{
    __shared__ float t[32][33];
    int n0 = blockIdx.x * 32, k0 = blockIdx.y * 32;
    int tx = threadIdx.x, ty = threadIdx.y;
#pragma unroll
    for (int j = 0; j < 4; j++)
        t[ty + j * 8][tx] = W[(size_t)(k0 + ty + j * 8) * N + n0 + tx];
    __syncthreads();
#pragma unroll
    for (int j = 0; j < 4; j++)
        outh[(size_t)(n0 + ty + j * 8) * K + k0 + tx] = __float2half_rn(t[tx][ty + j * 8]);
}

// ---------------------------------------------------------------------------
// HMMA fp16 GEMM: C = (Ah[+Al]) @ Bt^T + bias.
// Al pass + lo output only for column blocks bn < loN (Q columns / full GEMM2).
// CTA 128x128, BK=64, 8 warps; stage = Ah+Al+B = 48KB x 2 -> 2 CTAs/SM.
// ---------------------------------------------------------------------------
#define HTILE 16384
#define HSTAGE (3 * HTILE)
#define HSMEM (2 * HSTAGE)

template <bool F16OUT>
__global__ __launch_bounds__(256, 2) void gemm_f16x2_kernel(
    const __half* __restrict__ Ahg, const __half* __restrict__ Alg,
    const __half* __restrict__ Bg, const float* __restrict__ bias,
    float* __restrict__ Cf, __half* __restrict__ Ch, __half* __restrict__ Cl,
    int loN, int N, int K)
{
    extern __shared__ char smem[];
    const uint32_t sbase = smem_u32(smem);
    const int tid = threadIdx.x;
    const int wid = tid >> 5;
    const int lid = tid & 31;
    const int wm = wid & 3;
    const int wn = wid >> 2;
    const int bm = blockIdx.y * 128;
    const int bn = blockIdx.x * 128;
    const bool useAl = (bn < loN);     // 2-pass region

    const int nch = K >> 6;

    auto load_stage = [&](int buf, int k0) {
        uint32_t sb = sbase + buf * HSTAGE;
#pragma unroll
        for (int i = 0; i < 12; i++) {
            int c = tid + (i << 8);              // 0..3071
            int tile = c >> 10;                  // 0 Ah, 1 Al, 2 B
            if (tile == 1 && !useAl) continue;
            int row = (c >> 3) & 127;
            int seg = c & 7;
            uint32_t so = swz128((row << 7) + (seg << 4));
            const __half* src = (tile == 0) ? Ahg : (tile == 1) ? Alg : Bg;
            size_t g = (size_t)((tile == 2 ? bn : bm) + row) * K + k0 + (seg << 3);
            cpasync16(sb + tile * HTILE + so, src + g);
        }
        cp_commit();
    };

    float d[2][8][4];
#pragma unroll
    for (int mi = 0; mi < 2; mi++)
#pragma unroll
        for (int ni = 0; ni < 8; ni++)
#pragma unroll
            for (int r = 0; r < 4; r++) d[mi][ni][r] = 0.0f;

    load_stage(0, 0);
    load_stage(1, 64);

    for (int c = 0; c < nch; c++) {
        if (c + 1 < nch) cp_wait<1>(); else cp_wait<0>();
        __syncthreads();

        const uint32_t sb = sbase + (c & 1) * HSTAGE;
        const uint32_t aTh = sb, aTl = sb + HTILE, bT = sb + 2 * HTILE;

#pragma unroll
        for (int ks = 0; ks < 4; ks++) {
            uint32_t ah[2][4], al[2][4];
#pragma unroll
            for (int mi = 0; mi < 2; mi++) {
                uint32_t off = swz128(((wm * 32 + mi * 16 + (lid & 15)) << 7) +
                                      ((ks * 2 + (lid >> 4)) << 4));
                ldsm4(ah[mi], aTh + off);
                if (useAl) ldsm4(al[mi], aTl + off);
            }
#pragma unroll
            for (int pi = 0; pi < 4; pi++) {
                uint32_t boff = swz128(((wn * 64 + pi * 16 + (lid & 7) + ((lid >> 4) << 3)) << 7) +
                                       ((ks * 2 + ((lid >> 3) & 1)) << 4));
                uint32_t b4[4];
                ldsm4(b4, bT + boff);
#pragma unroll
                for (int mi = 0; mi < 2; mi++) {
#pragma unroll
                    for (int sub = 0; sub < 2; sub++) {
                        float* acc = d[mi][pi * 2 + sub];
                        mma16816(acc, ah[mi], b4 + sub * 2);
                        if (useAl) mma16816(acc, al[mi], b4 + sub * 2);
                    }
                }
            }
        }
        __syncthreads();
        if (c + 2 < nch) load_stage(c & 1, (c + 2) << 6);
    }

    const bool writeLo = F16OUT && useAl;
#pragma unroll
    for (int mi = 0; mi < 2; mi++) {
        int row = bm + wm * 32 + mi * 16 + (lid >> 2);
#pragma unroll
        for (int ni = 0; ni < 8; ni++) {
            int col = bn + wn * 64 + ni * 8 + ((lid & 3) << 1);
            float2 bv = *(const float2*)&bias[col];
            float v00 = d[mi][ni][0] + bv.x, v01 = d[mi][ni][1] + bv.y;
            float v10 = d[mi][ni][2] + bv.x, v11 = d[mi][ni][3] + bv.y;
            if (F16OUT) {
                float h00 = f16round(v00), h01 = f16round(v01);
                float h10 = f16round(v10), h11 = f16round(v11);
                *(uint32_t*)&Ch[(size_t)row * N + col] = pack_f16(h00, h01);
                *(uint32_t*)&Ch[(size_t)(row + 8) * N + col] = pack_f16(h10, h11);
                if (writeLo) {
                    *(uint32_t*)&Cl[(size_t)row * N + col] = pack_f16(v00 - h00, v01 - h01);
                    *(uint32_t*)&Cl[(size_t)(row + 8) * N + col] = pack_f16(v10 - h10, v11 - h11);
                }
            } else {
                *(float2*)&Cf[(size_t)row * N + col] = make_float2(v00, v01);
                *(float2*)&Cf[(size_t)(row + 8) * N + col] = make_float2(v10, v11);
            }
        }
    }
}

// ---------------------------------------------------------------------------
// HMMA fp16 flash attention. Q split hi/lo (2-pass S); P single fp16 (1-pass PV);
// K/V single fp16. Big causal tiles scheduled first.
// ---------------------------------------------------------------------------
#define AQT 16384
#define AKT 8192
#define AKV_STAGE (2 * AKT)
#define ASMEM (2 * AQT + 2 * AKV_STAGE)   // 65536 -> 2 CTAs/SM

__global__ __launch_bounds__(256, 2) void attn_f16_kernel(
    const __half* __restrict__ qkvh, const __half* __restrict__ qkvl,
    __half* __restrict__ yh, __half* __restrict__ yl)
{
    extern __shared__ char smem[];
    const uint32_t sbase = smem_u32(smem);
    const int tid = threadIdx.x;
    const int w = tid >> 5;
    const int lid = tid & 31;
    const int qt = gridDim.x - 1 - blockIdx.x;
    const int h  = blockIdx.y;
    const int b  = blockIdx.z;
    const int qbase = qt * 128;
    const int nch = 2 * (qt + 1);

    const uint32_t sQh = sbase, sQl = sbase + AQT;
    const uint32_t sKV = sbase + 2 * AQT;

    const size_t rowbase = (size_t)b * CT * 3 * CD + (size_t)h * CHD;

#pragma unroll
    for (int i = 0; i < 8; i++) {
        int c = tid + (i << 8);
        int t2 = c >> 10;
        int row = (c >> 3) & 127;
        int seg = c & 7;
        uint32_t so = swz128((row << 7) + (seg << 4));
        size_t ga = rowbase + (size_t)(qbase + row) * (3 * CD) + (seg << 3);
        cpasync16((t2 ? sQl : sQh) + so, (t2 ? qkvl : qkvh) + ga);
    }

    auto load_kv = [&](int buf, int kt0) {
        uint32_t sb = sKV + buf * AKV_STAGE;
#pragma unroll
        for (int i = 0; i < 4; i++) {
            int c = tid + (i << 8);
            int tile = c >> 9;
            int row = (c >> 3) & 63;
            int seg = c & 7;
            uint32_t so = swz128((row << 7) + (seg << 4));
            size_t ga = rowbase + (size_t)(kt0 + row) * (3 * CD) + (seg << 3) +
                        (tile ? 2 * CD : CD);
            cpasync16(sb + tile * AKT + so, qkvh + ga);
        }
        cp_commit();
    };

    load_kv(0, 0);
    if (nch > 1) load_kv(1, 64);

    float m0 = -INFINITY, m1 = -INFINITY, l0 = 0.0f, l1 = 0.0f;
    float oacc[8][4];
#pragma unroll
    for (int nb = 0; nb < 8; nb++)
#pragma unroll
        for (int r = 0; r < 4; r++) oacc[nb][r] = 0.0f;

    uint32_t qh[4][4], ql[4][4];
    const float scale = 0.125f;

    for (int c = 0; c < nch; c++) {
        if (c + 1 < nch) cp_wait<1>(); else cp_wait<0>();
        __syncthreads();

        if (c == 0) {
#pragma unroll
            for (int ks = 0; ks < 4; ks++) {
                uint32_t off = swz128(((w * 16 + (lid & 15)) << 7) +
                                      ((ks * 2 + (lid >> 4)) << 4));
                ldsm4(qh[ks], sQh + off);
                ldsm4(ql[ks], sQl + off);
            }
        }

        const uint32_t sb = sKV + (c & 1) * AKV_STAGE;
        const uint32_t sK = sb, sV = sb + AKT;

        // ---- S = Q @ K^T (2-pass) ----
        float sacc[8][4];
#pragma unroll
        for (int nb = 0; nb < 8; nb++)
#pragma unroll
            for (int r = 0; r < 4; r++) sacc[nb][r] = 0.0f;

#pragma unroll
        for (int ks = 0; ks < 4; ks++) {
#pragma unroll
            for (int pi = 0; pi < 4; pi++) {
                uint32_t boff = swz128(((pi * 16 + (lid & 7) + ((lid >> 4) << 3)) << 7) +
                                       ((ks * 2 + ((lid >> 3) & 1)) << 4));
                uint32_t k4[4];
                ldsm4(k4, sK + boff);
#pragma unroll
                for (int sub = 0; sub < 2; sub++) {
                    float* acc = sacc[pi * 2 + sub];
                    mma16816(acc, qh[ks], k4 + sub * 2);
                    mma16816(acc, ql[ks], k4 + sub * 2);
                }
            }
        }

        // ---- scale + causal mask ----
        const int row0 = qbase + w * 16 + (lid >> 2);
        const int row1 = row0 + 8;
        const bool diag = (c >= 2 * qt);
#pragma unroll
        for (int nb = 0; nb < 8; nb++) {
            int col = c * 64 + nb * 8 + ((lid & 3) << 1);
            sacc[nb][0] *= scale; sacc[nb][1] *= scale;
            sacc[nb][2] *= scale; sacc[nb][3] *= scale;
            if (diag) {
                if (col > row0)     sacc[nb][0] = -INFINITY;
                if (col + 1 > row0) sacc[nb][1] = -INFINITY;
                if (col > row1)     sacc[nb][2] = -INFINITY;
                if (col + 1 > row1) sacc[nb][3] = -INFINITY;
            }
        }

        // ---- online softmax ----
        {
            float mx0 = -INFINITY, mx1 = -INFINITY;
#pragma unroll
            for (int nb = 0; nb < 8; nb++) {
                mx0 = fmaxf(mx0, fmaxf(sacc[nb][0], sacc[nb][1]));
                mx1 = fmaxf(mx1, fmaxf(sacc[nb][2], sacc[nb][3]));
            }
            mx0 = fmaxf(mx0, __shfl_xor_sync(0xffffffffu, mx0, 1));
            mx0 = fmaxf(mx0, __shfl_xor_sync(0xffffffffu, mx0, 2));
            mx1 = fmaxf(mx1, __shfl_xor_sync(0xffffffffu, mx1, 1));
            mx1 = fmaxf(mx1, __shfl_xor_sync(0xffffffffu, mx1, 2));
            float mn0 = fmaxf(m0, mx0), mn1 = fmaxf(m1, mx1);
            float f0 = __expf(m0 - mn0), f1 = __expf(m1 - mn1);
            float s0 = 0.0f, s1 = 0.0f;
#pragma unroll
            for (int nb = 0; nb < 8; nb++) {
                sacc[nb][0] = __expf(sacc[nb][0] - mn0);
                sacc[nb][1] = __expf(sacc[nb][1] - mn0);
                sacc[nb][2] = __expf(sacc[nb][2] - mn1);
                sacc[nb][3] = __expf(sacc[nb][3] - mn1);
                s0 += sacc[nb][0] + sacc[nb][1];
                s1 += sacc[nb][2] + sacc[nb][3];
            }
            s0 += __shfl_xor_sync(0xffffffffu, s0, 1);
            s0 += __shfl_xor_sync(0xffffffffu, s0, 2);
            s1 += __shfl_xor_sync(0xffffffffu, s1, 1);
            s1 += __shfl_xor_sync(0xffffffffu, s1, 2);
            l0 = l0 * f0 + s0; l1 = l1 * f1 + s1;
            m0 = mn0; m1 = mn1;
#pragma unroll
            for (int nb = 0; nb < 8; nb++) {
                oacc[nb][0] *= f0; oacc[nb][1] *= f0;
                oacc[nb][2] *= f1; oacc[nb][3] *= f1;
            }
        }

        // ---- O += P @ V (1-pass; P single fp16) ----
#pragma unroll
        for (int kp = 0; kp < 4; kp++) {
            uint32_t ph[4];
            ph[0] = pack_f16(sacc[2 * kp][0], sacc[2 * kp][1]);
            ph[1] = pack_f16(sacc[2 * kp][2], sacc[2 * kp][3]);
            ph[2] = pack_f16(sacc[2 * kp + 1][0], sacc[2 * kp + 1][1]);
            ph[3] = pack_f16(sacc[2 * kp + 1][2], sacc[2 * kp + 1][3]);
            const int mi = lid >> 3, r8 = lid & 7;
#pragma unroll
            for (int pi = 0; pi < 4; pi++) {
                uint32_t voff = swz128(((kp * 16 + ((mi & 1) << 3) + r8) << 7) +
                                       ((pi * 16 + ((mi >> 1) << 3)) << 1));
                uint32_t v4[4];
                ldsm4t(v4, sV + voff);
#pragma unroll
                for (int sub = 0; sub < 2; sub++)
                    mma16816(oacc[pi * 2 + sub], ph, v4 + sub * 2);
            }
        }

        __syncthreads();
        if (c + 2 < nch) load_kv(c & 1, (c + 2) << 6);
    }

    // ---- epilogue ----
    const float inv0 = 1.0f / l0, inv1 = 1.0f / l1;
    const int row0 = qbase + w * 16 + (lid >> 2);
    __half* yhb = yh + (size_t)b * CT * CD + (size_t)h * CHD;
    __half* ylb = yl + (size_t)b * CT * CD + (size_t)h * CHD;
#pragma unroll
    for (int nb = 0; nb < 8; nb++) {
        int col = nb * 8 + ((lid & 3) << 1);
        float v00 = oacc[nb][0] * inv0, v01 = oacc[nb][1] * inv0;
        float v10 = oacc[nb][2] * inv1, v11 = oacc[nb][3] * inv1;
        float h00 = f16round(v00), h01 = f16round(v01);
        float h10 = f16round(v10), h11 = f16round(v11);
        *(uint32_t*)&yhb[(size_t)row0 * CD + col] = pack_f16(h00, h01);
        *(uint32_t*)&yhb[(size_t)(row0 + 8) * CD + col] = pack_f16(h10, h11);
        *(uint32_t*)&ylb[(size_t)row0 * CD + col] = pack_f16(v00 - h00, v01 - h01);
        *(uint32_t*)&ylb[(size_t)(row0 + 8) * CD + col] = pack_f16(v10 - h10, v11 - h11);
    }
}

// ---------------------------------------------------------------------------
// Launch
// ---------------------------------------------------------------------------
extern "C" void kernel_launch(void* const* d_in, const int* in_sizes, int n_in,
                              void* d_out, int out_size)
{
    (void)in_sizes; (void)n_in; (void)out_size;
    const float* x  = (const float*)d_in[0];
    const float* W1 = (const float*)d_in[1];
    const float* b1 = (const float*)d_in[2];
    const float* W2 = (const float*)d_in[3];
    const float* b2 = (const float*)d_in[4];
    float* out = (float*)d_out;

    __half *qkvh, *qkvl, *xh, *xl, *yh, *yl, *w1t, *w2t;
    cudaGetSymbolAddress((void**)&qkvh, g_qkvh);
    cudaGetSymbolAddress((void**)&qkvl, g_qkvl);
    cudaGetSymbolAddress((void**)&xh, g_xh);
    cudaGetSymbolAddress((void**)&xl, g_xl);
    cudaGetSymbolAddress((void**)&yh, g_yh);
    cudaGetSymbolAddress((void**)&yl, g_yl);
    cudaGetSymbolAddress((void**)&w1t, g_w1t);
    cudaGetSymbolAddress((void**)&w2t, g_w2t);

    cudaFuncSetAttribute(gemm_f16x2_kernel<true>,
                         cudaFuncAttributeMaxDynamicSharedMemorySize, HSMEM);
    cudaFuncSetAttribute(gemm_f16x2_kernel<false>,
                         cudaFuncAttributeMaxDynamicSharedMemorySize, HSMEM);
    cudaFuncSetAttribute(attn_f16_kernel,
                         cudaFuncAttributeMaxDynamicSharedMemorySize, ASMEM);

    const int M = CB * CT;                 // 4096
    const int n4x = M * CD / 4;

    split_kernel<<<(n4x + 255) / 256, 256>>>(x, xh, xl, n4x);
    transpose_f16_kernel<<<dim3(3 * CD / 32, CD / 32), dim3(32, 8)>>>(W1, w1t, CD, 3 * CD);
    transpose_f16_kernel<<<dim3(CD / 32, CD / 32), dim3(32, 8)>>>(W2, w2t, CD, CD);

    // qkv = x @ W1 + b1 : 2-pass + lo output for Q cols (N<CD), 1-pass for K/V
    gemm_f16x2_kernel<true><<<dim3(3 * CD / 128, M / 128), 256, HSMEM>>>(
        xh, xl, w1t, b1, nullptr, qkvh, qkvl, CD, 3 * CD, CD);

    // flash attention -> y (fp16 hi/lo)
    attn_f16_kernel<<<dim3(CT / 128, CH, CB), 256, ASMEM>>>(qkvh, qkvl, yh, yl);

    // out (fp32) = y @ W2 + b2 : full 2-pass (loN = N)
    gemm_f16x2_kernel<false><<<dim3(CD / 128, M / 128), 256, HSMEM>>>(
        yh, yl, w2t, b2, out, nullptr, nullptr, CD, CD, CD);
}

// round 7
// speedup vs baseline: 5.9295x; 1.2610x over previous
#include <cuda_runtime.h>
#include <cuda_fp16.h>
#include <math.h>
#include <stdint.h>

#define CB 2
#define CT 2048
#define CD 1024
#define CH 16
#define CHD 64

// ---------------------------------------------------------------------------
// Device scratch (no cudaMalloc allowed)
// ---------------------------------------------------------------------------
__device__ __align__(128) __half g_qkvh[(size_t)CB * CT * 3 * CD];  // qkv fp16
__device__ __align__(128) __half g_xh[(size_t)CB * CT * CD];        // x fp16
__device__ __align__(128) __half g_yh[(size_t)CB * CT * CD];        // y hi fp16
__device__ __align__(128) __half g_yl[(size_t)CB * CT * CD];        // y lo fp16
__device__ __align__(128) __half g_w1t[(size_t)3 * CD * CD];        // W1^T [N,K]
__device__ __align__(128) __half g_w2t[(size_t)CD * CD];            // W2^T [N,K]

// ---------------------------------------------------------------------------
// Low-level helpers
// ---------------------------------------------------------------------------
__device__ __forceinline__ uint32_t smem_u32(const void* p) {
    uint32_t a;
    asm("{ .reg .u64 t; cvta.to.shared.u64 t, %1; cvt.u32.u64 %0, t; }" : "=r"(a) : "l"(p));
    return a;
}
__device__ __forceinline__ void cpasync16(uint32_t s, const void* g) {
    asm volatile("cp.async.cg.shared.global [%0], [%1], 16;" :: "r"(s), "l"(g));
}
__device__ __forceinline__ void cp_commit() {
    asm volatile("cp.async.commit_group;" ::: "memory");
}
template <int N>
__device__ __forceinline__ void cp_wait() {
    asm volatile("cp.async.wait_group %0;" :: "n"(N) : "memory");
}
__device__ __forceinline__ void ldsm4(uint32_t* r, uint32_t addr) {
    asm volatile("ldmatrix.sync.aligned.m8n8.x4.shared.b16 {%0,%1,%2,%3}, [%4];"
                 : "=r"(r[0]), "=r"(r[1]), "=r"(r[2]), "=r"(r[3]) : "r"(addr));
}
__device__ __forceinline__ void ldsm4t(uint32_t* r, uint32_t addr) {
    asm volatile("ldmatrix.sync.aligned.m8n8.x4.trans.shared.b16 {%0,%1,%2,%3}, [%4];"
                 : "=r"(r[0]), "=r"(r[1]), "=r"(r[2]), "=r"(r[3]) : "r"(addr));
}
__device__ __forceinline__ void mma16816(float* d, const uint32_t* a, const uint32_t* b) {
    asm volatile(
        "mma.sync.aligned.m16n8k16.row.col.f32.f16.f16.f32 "
        "{%0,%1,%2,%3}, {%4,%5,%6,%7}, {%8,%9}, {%0,%1,%2,%3};"
        : "+f"(d[0]), "+f"(d[1]), "+f"(d[2]), "+f"(d[3])
        : "r"(a[0]), "r"(a[1]), "r"(a[2]), "r"(a[3]), "r"(b[0]), "r"(b[1]));
}
__device__ __forceinline__ uint32_t swz128(uint32_t b) { return b ^ ((b >> 3) & 0x70); }
__device__ __forceinline__ uint32_t pack_f16(float a, float b) {
    __half2 v = __floats2half2_rn(a, b);
    return *(uint32_t*)&v;
}
__device__ __forceinline__ float f16round(float v) {
    return __half2float(__float2half_rn(v));
}

// ---------------------------------------------------------------------------
// fp32 -> fp16 convert (x)
// ---------------------------------------------------------------------------
__global__ __launch_bounds__(256) void convert_f16_kernel(
    const float* __restrict__ in, __half* __restrict__ hi, int n4)
{
    int i = blockIdx.x * blockDim.x + threadIdx.x;
    if (i >= n4) return;
    float4 v = ((const float4*)in)[i];
    ((uint2*)hi)[i] = make_uint2(pack_f16(v.x, v.y), pack_f16(v.z, v.w));
}

// ---------------------------------------------------------------------------
// W [K,N] fp32 -> Wt [N,K] fp16 (transpose)
// ---------------------------------------------------------------------------
__global__ __launch_bounds__(256) void transpose_f16_kernel(
    const float* __restrict__ W, __half* __restrict__ outh, int K, int N)
{
    __shared__ float t[32][33];
    int n0 = blockIdx.x * 32, k0 = blockIdx.y * 32;
    int tx = threadIdx.x, ty = threadIdx.y;
#pragma unroll
    for (int j = 0; j < 4; j++)
        t[ty + j * 8][tx] = W[(size_t)(k0 + ty + j * 8) * N + n0 + tx];
    __syncthreads();
#pragma unroll
    for (int j = 0; j < 4; j++)
        outh[(size_t)(n0 + ty + j * 8) * K + k0 + tx] = __float2half_rn(t[tx][ty + j * 8]);
}

// ---------------------------------------------------------------------------
// HMMA fp16 GEMM: C = (Ah[+Al]) @ Bt^T + bias.
// AL: 2-pass with Al correction (GEMM2); else 1-pass (GEMM1).
// F16OUT: fp16 output; else fp32. CTA 128x128, BK=64, 8 warps.
// ---------------------------------------------------------------------------
#define HTILE 16384

template <bool AL, bool F16OUT>
__global__ __launch_bounds__(256, 2) void gemm_f16_kernel(
    const __half* __restrict__ Ahg, const __half* __restrict__ Alg,
    const __half* __restrict__ Bg, const float* __restrict__ bias,
    float* __restrict__ Cf, __half* __restrict__ Ch, int N, int K)
{
    constexpr int NT = AL ? 3 : 2;                 // tiles per stage
    constexpr uint32_t STAGE = NT * HTILE;
    constexpr uint32_t BOFF = (AL ? 2 : 1) * HTILE;

    extern __shared__ char smem[];
    const uint32_t sbase = smem_u32(smem);
    const int tid = threadIdx.x;
    const int wid = tid >> 5;
    const int lid = tid & 31;
    const int wm = wid & 3;
    const int wn = wid >> 2;
    const int bm = blockIdx.y * 128;
    const int bn = blockIdx.x * 128;

    const int nch = K >> 6;

    auto load_stage = [&](int buf, int k0) {
        uint32_t sb = sbase + buf * STAGE;
#pragma unroll
        for (int i = 0; i < NT * 4; i++) {
            int c = tid + (i << 8);
            int tile = c >> 10;                    // 0 Ah, [1 Al,] last B
            int row = (c >> 3) & 127;
            int seg = c & 7;
            uint32_t so = swz128((row << 7) + (seg << 4));
            const __half* src = (tile == 0) ? Ahg : (tile == NT - 1) ? Bg : Alg;
            size_t g = (size_t)((tile == NT - 1 ? bn : bm) + row) * K + k0 + (seg << 3);
            cpasync16(sb + tile * HTILE + so, src + g);
        }
        cp_commit();
    };

    float d[2][8][4];
#pragma unroll
    for (int mi = 0; mi < 2; mi++)
#pragma unroll
        for (int ni = 0; ni < 8; ni++)
#pragma unroll
            for (int r = 0; r < 4; r++) d[mi][ni][r] = 0.0f;

    load_stage(0, 0);
    load_stage(1, 64);

    for (int c = 0; c < nch; c++) {
        if (c + 1 < nch) cp_wait<1>(); else cp_wait<0>();
        __syncthreads();

        const uint32_t sb = sbase + (c & 1) * STAGE;
        const uint32_t aTh = sb, aTl = sb + HTILE, bT = sb + BOFF;

#pragma unroll
        for (int ks = 0; ks < 4; ks++) {
            uint32_t ah[2][4], al[2][4];
#pragma unroll
            for (int mi = 0; mi < 2; mi++) {
                uint32_t off = swz128(((wm * 32 + mi * 16 + (lid & 15)) << 7) +
                                      ((ks * 2 + (lid >> 4)) << 4));
                ldsm4(ah[mi], aTh + off);
                if (AL) ldsm4(al[mi], aTl + off);
            }
#pragma unroll
            for (int pi = 0; pi < 4; pi++) {
                uint32_t boff = swz128(((wn * 64 + pi * 16 + (lid & 7) + ((lid >> 4) << 3)) << 7) +
                                       ((ks * 2 + ((lid >> 3) & 1)) << 4));
                uint32_t b4[4];
                ldsm4(b4, bT + boff);
#pragma unroll
                for (int mi = 0; mi < 2; mi++) {
#pragma unroll
                    for (int sub = 0; sub < 2; sub++) {
                        float* acc = d[mi][pi * 2 + sub];
                        mma16816(acc, ah[mi], b4 + sub * 2);
                        if (AL) mma16816(acc, al[mi], b4 + sub * 2);
                    }
                }
            }
        }
        __syncthreads();
        if (c + 2 < nch) load_stage(c & 1, (c + 2) << 6);
    }

#pragma unroll
    for (int mi = 0; mi < 2; mi++) {
        int row = bm + wm * 32 + mi * 16 + (lid >> 2);
#pragma unroll
        for (int ni = 0; ni < 8; ni++) {
            int col = bn + wn * 64 + ni * 8 + ((lid & 3) << 1);
            float2 bv = *(const float2*)&bias[col];
            float v00 = d[mi][ni][0] + bv.x, v01 = d[mi][ni][1] + bv.y;
            float v10 = d[mi][ni][2] + bv.x, v11 = d[mi][ni][3] + bv.y;
            if (F16OUT) {
                *(uint32_t*)&Ch[(size_t)row * N + col] = pack_f16(v00, v01);
                *(uint32_t*)&Ch[(size_t)(row + 8) * N + col] = pack_f16(v10, v11);
            } else {
                *(float2*)&Cf[(size_t)row * N + col] = make_float2(v00, v01);
                *(float2*)&Cf[(size_t)(row + 8) * N + col] = make_float2(v10, v11);
            }
        }
    }
}

// ---------------------------------------------------------------------------
// HMMA fp16 flash attention. Q/K/V/P all single fp16 (1-pass MMAs).
// Output y split fp16 hi/lo (feeds 2-pass GEMM2). Big causal tiles first.
// ---------------------------------------------------------------------------
#define AQT 16384
#define AKT 8192
#define AKV_STAGE (2 * AKT)
#define ASMEM (AQT + 2 * AKV_STAGE)   // 49152

__global__ __launch_bounds__(256, 2) void attn_f16_kernel(
    const __half* __restrict__ qkvh, __half* __restrict__ yh, __half* __restrict__ yl)
{
    extern __shared__ char smem[];
    const uint32_t sbase = smem_u32(smem);
    const int tid = threadIdx.x;
    const int w = tid >> 5;
    const int lid = tid & 31;
    const int qt = gridDim.x - 1 - blockIdx.x;
    const int h  = blockIdx.y;
    const int b  = blockIdx.z;
    const int qbase = qt * 128;
    const int nch = 2 * (qt + 1);

    const uint32_t sQ = sbase;
    const uint32_t sKV = sbase + AQT;

    const size_t rowbase = (size_t)b * CT * 3 * CD + (size_t)h * CHD;

    // Q load (once)
#pragma unroll
    for (int i = 0; i < 4; i++) {
        int c = tid + (i << 8);            // 0..1023
        int row = c >> 3;
        int seg = c & 7;
        uint32_t so = swz128((row << 7) + (seg << 4));
        cpasync16(sQ + so, qkvh + rowbase + (size_t)(qbase + row) * (3 * CD) + (seg << 3));
    }

    auto load_kv = [&](int buf, int kt0) {
        uint32_t sb = sKV + buf * AKV_STAGE;
#pragma unroll
        for (int i = 0; i < 4; i++) {
            int c = tid + (i << 8);
            int tile = c >> 9;
            int row = (c >> 3) & 63;
            int seg = c & 7;
            uint32_t so = swz128((row << 7) + (seg << 4));
            size_t ga = rowbase + (size_t)(kt0 + row) * (3 * CD) + (seg << 3) +
                        (tile ? 2 * CD : CD);
            cpasync16(sb + tile * AKT + so, qkvh + ga);
        }
        cp_commit();
    };

    load_kv(0, 0);
    if (nch > 1) load_kv(1, 64);

    float m0 = -INFINITY, m1 = -INFINITY, l0 = 0.0f, l1 = 0.0f;
    float oacc[8][4];
#pragma unroll
    for (int nb = 0; nb < 8; nb++)
#pragma unroll
        for (int r = 0; r < 4; r++) oacc[nb][r] = 0.0f;

    uint32_t qf[4][4];
    const float scale = 0.125f;

    for (int c = 0; c < nch; c++) {
        if (c + 1 < nch) cp_wait<1>(); else cp_wait<0>();
        __syncthreads();

        if (c == 0) {
#pragma unroll
            for (int ks = 0; ks < 4; ks++) {
                uint32_t off = swz128(((w * 16 + (lid & 15)) << 7) +
                                      ((ks * 2 + (lid >> 4)) << 4));
                ldsm4(qf[ks], sQ + off);
            }
        }

        const uint32_t sb = sKV + (c & 1) * AKV_STAGE;
        const uint32_t sK = sb, sV = sb + AKT;

        // ---- S = Q @ K^T (1-pass) ----
        float sacc[8][4];
#pragma unroll
        for (int nb = 0; nb < 8; nb++)
#pragma unroll
            for (int r = 0; r < 4; r++) sacc[nb][r] = 0.0f;

#pragma unroll
        for (int ks = 0; ks < 4; ks++) {
#pragma unroll
            for (int pi = 0; pi < 4; pi++) {
                uint32_t boff = swz128(((pi * 16 + (lid & 7) + ((lid >> 4) << 3)) << 7) +
                                       ((ks * 2 + ((lid >> 3) & 1)) << 4));
                uint32_t k4[4];
                ldsm4(k4, sK + boff);
#pragma unroll
                for (int sub = 0; sub < 2; sub++)
                    mma16816(sacc[pi * 2 + sub], qf[ks], k4 + sub * 2);
            }
        }

        // ---- scale + causal mask ----
        const int row0 = qbase + w * 16 + (lid >> 2);
        const int row1 = row0 + 8;
        const bool diag = (c >= 2 * qt);
#pragma unroll
        for (int nb = 0; nb < 8; nb++) {
            int col = c * 64 + nb * 8 + ((lid & 3) << 1);
            sacc[nb][0] *= scale; sacc[nb][1] *= scale;
            sacc[nb][2] *= scale; sacc[nb][3] *= scale;
            if (diag) {
                if (col > row0)     sacc[nb][0] = -INFINITY;
                if (col + 1 > row0) sacc[nb][1] = -INFINITY;
                if (col > row1)     sacc[nb][2] = -INFINITY;
                if (col + 1 > row1) sacc[nb][3] = -INFINITY;
            }
        }

        // ---- online softmax ----
        {
            float mx0 = -INFINITY, mx1 = -INFINITY;
#pragma unroll
            for (int nb = 0; nb < 8; nb++) {
                mx0 = fmaxf(mx0, fmaxf(sacc[nb][0], sacc[nb][1]));
                mx1 = fmaxf(mx1, fmaxf(sacc[nb][2], sacc[nb][3]));
            }
            mx0 = fmaxf(mx0, __shfl_xor_sync(0xffffffffu, mx0, 1));
            mx0 = fmaxf(mx0, __shfl_xor_sync(0xffffffffu, mx0, 2));
            mx1 = fmaxf(mx1, __shfl_xor_sync(0xffffffffu, mx1, 1));
            mx1 = fmaxf(mx1, __shfl_xor_sync(0xffffffffu, mx1, 2));
            float mn0 = fmaxf(m0, mx0), mn1 = fmaxf(m1, mx1);
            float f0 = __expf(m0 - mn0), f1 = __expf(m1 - mn1);
            float s0 = 0.0f, s1 = 0.0f;
#pragma unroll
            for (int nb = 0; nb < 8; nb++) {
                sacc[nb][0] = __expf(sacc[nb][0] - mn0);
                sacc[nb][1] = __expf(sacc[nb][1] - mn0);
                sacc[nb][2] = __expf(sacc[nb][2] - mn1);
                sacc[nb][3] = __expf(sacc[nb][3] - mn1);
                s0 += sacc[nb][0] + sacc[nb][1];
                s1 += sacc[nb][2] + sacc[nb][3];
            }
            s0 += __shfl_xor_sync(0xffffffffu, s0, 1);
            s0 += __shfl_xor_sync(0xffffffffu, s0, 2);
            s1 += __shfl_xor_sync(0xffffffffu, s1, 1);
            s1 += __shfl_xor_sync(0xffffffffu, s1, 2);
            l0 = l0 * f0 + s0; l1 = l1 * f1 + s1;
            m0 = mn0; m1 = mn1;
#pragma unroll
            for (int nb = 0; nb < 8; nb++) {
                oacc[nb][0] *= f0; oacc[nb][1] *= f0;
                oacc[nb][2] *= f1; oacc[nb][3] *= f1;
            }
        }

        // ---- O += P @ V (1-pass) ----
#pragma unroll
        for (int kp = 0; kp < 4; kp++) {
            uint32_t ph[4];
            ph[0] = pack_f16(sacc[2 * kp][0], sacc[2 * kp][1]);
            ph[1] = pack_f16(sacc[2 * kp][2], sacc[2 * kp][3]);
            ph[2] = pack_f16(sacc[2 * kp + 1][0], sacc[2 * kp + 1][1]);
            ph[3] = pack_f16(sacc[2 * kp + 1][2], sacc[2 * kp + 1][3]);
            const int mi = lid >> 3, r8 = lid & 7;
#pragma unroll
            for (int pi = 0; pi < 4; pi++) {
                uint32_t voff = swz128(((kp * 16 + ((mi & 1) << 3) + r8) << 7) +
                                       ((pi * 16 + ((mi >> 1) << 3)) << 1));
                uint32_t v4[4];
                ldsm4t(v4, sV + voff);
#pragma unroll
                for (int sub = 0; sub < 2; sub++)
                    mma16816(oacc[pi * 2 + sub], ph, v4 + sub * 2);
            }
        }

        __syncthreads();
        if (c + 2 < nch) load_kv(c & 1, (c + 2) << 6);
    }

    // ---- epilogue: normalize, split fp16 hi/lo for 2-pass GEMM2 ----
    const float inv0 = 1.0f / l0, inv1 = 1.0f / l1;
    const int row0 = qbase + w * 16 + (lid >> 2);
    __half* yhb = yh + (size_t)b * CT * CD + (size_t)h * CHD;
    __half* ylb = yl + (size_t)b * CT * CD + (size_t)h * CHD;
#pragma unroll
    for (int nb = 0; nb < 8; nb++) {
        int col = nb * 8 + ((lid & 3) << 1);
        float v00 = oacc[nb][0] * inv0, v01 = oacc[nb][1] * inv0;
        float v10 = oacc[nb][2] * inv1, v11 = oacc[nb][3] * inv1;
        float h00 = f16round(v00), h01 = f16round(v01);
        float h10 = f16round(v10), h11 = f16round(v11);
        *(uint32_t*)&yhb[(size_t)row0 * CD + col] = pack_f16(h00, h01);
        *(uint32_t*)&yhb[(size_t)(row0 + 8) * CD + col] = pack_f16(h10, h11);
        *(uint32_t*)&ylb[(size_t)row0 * CD + col] = pack_f16(v00 - h00, v01 - h01);
        *(uint32_t*)&ylb[(size_t)(row0 + 8) * CD + col] = pack_f16(v10 - h10, v11 - h11);
    }
}

// ---------------------------------------------------------------------------
// Launch
// ---------------------------------------------------------------------------
extern "C" void kernel_launch(void* const* d_in, const int* in_sizes, int n_in,
                              void* d_out, int out_size)
{
    (void)in_sizes; (void)n_in; (void)out_size;
    const float* x  = (const float*)d_in[0];
    const float* W1 = (const float*)d_in[1];
    const float* b1 = (const float*)d_in[2];
    const float* W2 = (const float*)d_in[3];
    const float* b2 = (const float*)d_in[4];
    float* out = (float*)d_out;

    __half *qkvh, *xh, *yh, *yl, *w1t, *w2t;
    cudaGetSymbolAddress((void**)&qkvh, g_qkvh);
    cudaGetSymbolAddress((void**)&xh, g_xh);
    cudaGetSymbolAddress((void**)&yh, g_yh);
    cudaGetSymbolAddress((void**)&yl, g_yl);
    cudaGetSymbolAddress((void**)&w1t, g_w1t);
    cudaGetSymbolAddress((void**)&w2t, g_w2t);

    const int SMEM1 = 2 * 2 * HTILE;       // 1-pass: Ah+B, 2 stages = 64KB
    const int SMEM2 = 2 * 3 * HTILE;       // 2-pass: Ah+Al+B, 2 stages = 96KB
    cudaFuncSetAttribute(gemm_f16_kernel<false, true>,
                         cudaFuncAttributeMaxDynamicSharedMemorySize, SMEM1);
    cudaFuncSetAttribute(gemm_f16_kernel<true, false>,
                         cudaFuncAttributeMaxDynamicSharedMemorySize, SMEM2);
    cudaFuncSetAttribute(attn_f16_kernel,
                         cudaFuncAttributeMaxDynamicSharedMemorySize, ASMEM);

    const int M = CB * CT;                 // 4096
    const int n4x = M * CD / 4;

    convert_f16_kernel<<<(n4x + 255) / 256, 256>>>(x, xh, n4x);
    transpose_f16_kernel<<<dim3(3 * CD / 32, CD / 32), dim3(32, 8)>>>(W1, w1t, CD, 3 * CD);
    transpose_f16_kernel<<<dim3(CD / 32, CD / 32), dim3(32, 8)>>>(W2, w2t, CD, CD);

    // qkv (fp16) = x @ W1 + b1 : 1-pass
    gemm_f16_kernel<false, true><<<dim3(3 * CD / 128, M / 128), 256, SMEM1>>>(
        xh, nullptr, w1t, b1, nullptr, qkvh, 3 * CD, CD);

    // flash attention -> y (fp16 hi/lo)
    attn_f16_kernel<<<dim3(CT / 128, CH, CB), 256, ASMEM>>>(qkvh, yh, yl);

    // out (fp32) = y @ W2 + b2 : 2-pass
    gemm_f16_kernel<true, false><<<dim3(CD / 128, M / 128), 256, SMEM2>>>(
        yh, yl, w2t, b2, out, nullptr, CD, CD);
}

// round 9
// speedup vs baseline: 6.6791x; 1.1264x over previous
#include <cuda_runtime.h>
#include <cuda_fp16.h>
#include <math.h>
#include <stdint.h>

#define CB 2
#define CT 2048
#define CD 1024
#define CH 16
#define CHD 64

// ---------------------------------------------------------------------------
// Device scratch (no cudaMalloc allowed)
// ---------------------------------------------------------------------------
__device__ __align__(128) __half g_qkvh[(size_t)CB * CT * 3 * CD];  // qkv fp16
__device__ __align__(128) __half g_xh[(size_t)CB * CT * CD];        // x fp16
__device__ __align__(128) __half g_yh[(size_t)CB * CT * CD];        // y fp16
__device__ __align__(128) __half g_w1t[(size_t)3 * CD * CD];        // W1^T [N,K]
__device__ __align__(128) __half g_w2t[(size_t)CD * CD];            // W2^T [N,K]

// ---------------------------------------------------------------------------
// Low-level helpers
// ---------------------------------------------------------------------------
__device__ __forceinline__ uint32_t smem_u32(const void* p) {
    uint32_t a;
    asm("{ .reg .u64 t; cvta.to.shared.u64 t, %1; cvt.u32.u64 %0, t; }" : "=r"(a) : "l"(p));
    return a;
}
__device__ __forceinline__ void cpasync16(uint32_t s, const void* g) {
    asm volatile("cp.async.cg.shared.global [%0], [%1], 16;" :: "r"(s), "l"(g));
}
__device__ __forceinline__ void cp_commit() {
    asm volatile("cp.async.commit_group;" ::: "memory");
}
template <int N>
__device__ __forceinline__ void cp_wait() {
    asm volatile("cp.async.wait_group %0;" :: "n"(N) : "memory");
}
__device__ __forceinline__ void ldsm4(uint32_t* r, uint32_t addr) {
    asm volatile("ldmatrix.sync.aligned.m8n8.x4.shared.b16 {%0,%1,%2,%3}, [%4];"
                 : "=r"(r[0]), "=r"(r[1]), "=r"(r[2]), "=r"(r[3]) : "r"(addr));
}
__device__ __forceinline__ void ldsm4t(uint32_t* r, uint32_t addr) {
    asm volatile("ldmatrix.sync.aligned.m8n8.x4.trans.shared.b16 {%0,%1,%2,%3}, [%4];"
                 : "=r"(r[0]), "=r"(r[1]), "=r"(r[2]), "=r"(r[3]) : "r"(addr));
}
__device__ __forceinline__ void mma16816(float* d, const uint32_t* a, const uint32_t* b) {
    asm volatile(
        "mma.sync.aligned.m16n8k16.row.col.f32.f16.f16.f32 "
        "{%0,%1,%2,%3}, {%4,%5,%6,%7}, {%8,%9}, {%0,%1,%2,%3};"
        : "+f"(d[0]), "+f"(d[1]), "+f"(d[2]), "+f"(d[3])
        : "r"(a[0]), "r"(a[1]), "r"(a[2]), "r"(a[3]), "r"(b[0]), "r"(b[1]));
}
__device__ __forceinline__ uint32_t swz128(uint32_t b) { return b ^ ((b >> 3) & 0x70); }
__device__ __forceinline__ uint32_t pack_f16(float a, float b) {
    __half2 v = __floats2half2_rn(a, b);
    return *(uint32_t*)&v;
}

// ---------------------------------------------------------------------------
// fp32 -> fp16 convert (x)
// ---------------------------------------------------------------------------
__global__ __launch_bounds__(256) void convert_f16_kernel(
    const float* __restrict__ in, __half* __restrict__ hi, int n4)
{
    int i = blockIdx.x * blockDim.x + threadIdx.x;
    if (i >= n4) return;
    float4 v = ((const float4*)in)[i];
    ((uint2*)hi)[i] = make_uint2(pack_f16(v.x, v.y), pack_f16(v.z, v.w));
}

// ---------------------------------------------------------------------------
// W [K,N] fp32 -> Wt [N,K] fp16 (transpose)
// ---------------------------------------------------------------------------
__global__ __launch_bounds__(256) void transpose_f16_kernel(
    const float* __restrict__ W, __half* __restrict__ outh, int K, int N)
{
    __shared__ float t[32][33];
    int n0 = blockIdx.x * 32, k0 = blockIdx.y * 32;
    int tx = threadIdx.x, ty = threadIdx.y;
#pragma unroll
    for (int j = 0; j < 4; j++)
        t[ty + j * 8][tx] = W[(size_t)(k0 + ty + j * 8) * N + n0 + tx];
    __syncthreads();
#pragma unroll
    for (int j = 0; j < 4; j++)
        outh[(size_t)(n0 + ty + j * 8) * K + k0 + tx] = __float2half_rn(t[tx][ty + j * 8]);
}

// ---------------------------------------------------------------------------
// HMMA fp16 GEMM: C = A @ Bt^T + bias. 1-pass fp16.
// CTA 128x128, BK=64, 8 warps; 3-stage cp.async pipeline (stage 32KB).
// ---------------------------------------------------------------------------
#define HTILE 16384
#define GSTAGE (2 * HTILE)          // A + B
#define GSMEM (3 * GSTAGE)          // 98304; 2 CTAs/SM -> 192KB

template <bool F16OUT>
__global__ __launch_bounds__(256, 2) void gemm_f16_kernel(
    const __half* __restrict__ Ag, const __half* __restrict__ Bg,
    const float* __restrict__ bias, float* __restrict__ Cf,
    __half* __restrict__ Ch, int N, int K)
{
    extern __shared__ char smem[];
    const uint32_t sbase = smem_u32(smem);
    const int tid = threadIdx.x;
    const int wid = tid >> 5;
    const int lid = tid & 31;
    const int wm = wid & 3;
    const int wn = wid >> 2;
    const int bm = blockIdx.y * 128;
    const int bn = blockIdx.x * 128;

    const int nch = K >> 6;

    auto load_stage = [&](int buf, int k0) {
        uint32_t sb = sbase + buf * GSTAGE;
#pragma unroll
        for (int i = 0; i < 8; i++) {
            int c = tid + (i << 8);              // 0..2047
            int tile = c >> 10;                  // 0 A, 1 B
            int row = (c >> 3) & 127;
            int seg = c & 7;
            uint32_t so = swz128((row << 7) + (seg << 4));
            const __half* src = tile ? Bg : Ag;
            size_t g = (size_t)((tile ? bn : bm) + row) * K + k0 + (seg << 3);
            cpasync16(sb + tile * HTILE + so, src + g);
        }
        cp_commit();
    };

    float d[2][8][4];
#pragma unroll
    for (int mi = 0; mi < 2; mi++)
#pragma unroll
        for (int ni = 0; ni < 8; ni++)
#pragma unroll
            for (int r = 0; r < 4; r++) d[mi][ni][r] = 0.0f;

    load_stage(0, 0);
    load_stage(1, 64);

    int buf = 0;
    for (int c = 0; c < nch; c++) {
        // Issue load c+2 BEFORE waiting on chunk c (buffer freed by trailing
        // __syncthreads of iteration c-1), then drain to chunk c's group.
        if (c + 2 < nch) { load_stage((c + 2) % 3, (c + 2) << 6); cp_wait<2>(); }
        else if (c + 1 < nch) cp_wait<1>();
        else cp_wait<0>();
        __syncthreads();

        const uint32_t sb = sbase + buf * GSTAGE;
        const uint32_t aT = sb, bT = sb + HTILE;

#pragma unroll
        for (int ks = 0; ks < 4; ks++) {
            uint32_t a4[2][4];
#pragma unroll
            for (int mi = 0; mi < 2; mi++) {
                uint32_t off = swz128(((wm * 32 + mi * 16 + (lid & 15)) << 7) +
                                      ((ks * 2 + (lid >> 4)) << 4));
                ldsm4(a4[mi], aT + off);
            }
#pragma unroll
            for (int pi = 0; pi < 4; pi++) {
                uint32_t boff = swz128(((wn * 64 + pi * 16 + (lid & 7) + ((lid >> 4) << 3)) << 7) +
                                       ((ks * 2 + ((lid >> 3) & 1)) << 4));
                uint32_t b4[4];
                ldsm4(b4, bT + boff);
#pragma unroll
                for (int mi = 0; mi < 2; mi++)
#pragma unroll
                    for (int sub = 0; sub < 2; sub++)
                        mma16816(d[mi][pi * 2 + sub], a4[mi], b4 + sub * 2);
            }
        }
        __syncthreads();
        buf = (buf + 1) % 3;
    }

#pragma unroll
    for (int mi = 0; mi < 2; mi++) {
        int row = bm + wm * 32 + mi * 16 + (lid >> 2);
#pragma unroll
        for (int ni = 0; ni < 8; ni++) {
            int col = bn + wn * 64 + ni * 8 + ((lid & 3) << 1);
            float2 bv = *(const float2*)&bias[col];
            float v00 = d[mi][ni][0] + bv.x, v01 = d[mi][ni][1] + bv.y;
            float v10 = d[mi][ni][2] + bv.x, v11 = d[mi][ni][3] + bv.y;
            if (F16OUT) {
                *(uint32_t*)&Ch[(size_t)row * N + col] = pack_f16(v00, v01);
                *(uint32_t*)&Ch[(size_t)(row + 8) * N + col] = pack_f16(v10, v11);
            } else {
                *(float2*)&Cf[(size_t)row * N + col] = make_float2(v00, v01);
                *(float2*)&Cf[(size_t)(row + 8) * N + col] = make_float2(v10, v11);
            }
        }
    }
}

// ---------------------------------------------------------------------------
// HMMA fp16 flash attention. All operands single fp16; fp32 accumulate.
// 3-stage KV pipeline; big causal tiles scheduled first; y fp16 out.
// ---------------------------------------------------------------------------
#define AQT 16384
#define AKT 8192
#define AKV_STAGE (2 * AKT)               // K + V = 16KB
#define ASMEM (AQT + 3 * AKV_STAGE)       // 65536; 2 CTAs/SM -> 128KB

__global__ __launch_bounds__(256, 2) void attn_f16_kernel(
    const __half* __restrict__ qkvh, __half* __restrict__ yh)
{
    extern __shared__ char smem[];
    const uint32_t sbase = smem_u32(smem);
    const int tid = threadIdx.x;
    const int w = tid >> 5;
    const int lid = tid & 31;
    const int qt = gridDim.x - 1 - blockIdx.x;
    const int h  = blockIdx.y;
    const int b  = blockIdx.z;
    const int qbase = qt * 128;
    const int nch = 2 * (qt + 1);

    const uint32_t sQ = sbase;
    const uint32_t sKV = sbase + AQT;

    const size_t rowbase = (size_t)b * CT * 3 * CD + (size_t)h * CHD;

    // Q load (joins KV group 0's commit)
#pragma unroll
    for (int i = 0; i < 4; i++) {
        int c = tid + (i << 8);
        int row = c >> 3;
        int seg = c & 7;
        uint32_t so = swz128((row << 7) + (seg << 4));
        cpasync16(sQ + so, qkvh + rowbase + (size_t)(qbase + row) * (3 * CD) + (seg << 3));
    }

    auto load_kv = [&](int buf, int kt0) {
        uint32_t sb = sKV + buf * AKV_STAGE;
#pragma unroll
        for (int i = 0; i < 4; i++) {
            int c = tid + (i << 8);
            int tile = c >> 9;
            int row = (c >> 3) & 63;
            int seg = c & 7;
            uint32_t so = swz128((row << 7) + (seg << 4));
            size_t ga = rowbase + (size_t)(kt0 + row) * (3 * CD) + (seg << 3) +
                        (tile ? 2 * CD : CD);
            cpasync16(sb + tile * AKT + so, qkvh + ga);
        }
        cp_commit();
    };

    load_kv(0, 0);
    load_kv(1, 64);                     // nch >= 2 always

    float m0 = -INFINITY, m1 = -INFINITY, l0 = 0.0f, l1 = 0.0f;
    float oacc[8][4];
#pragma unroll
    for (int nb = 0; nb < 8; nb++)
#pragma unroll
        for (int r = 0; r < 4; r++) oacc[nb][r] = 0.0f;

    uint32_t qf[4][4];
    const float scale = 0.125f;

    int buf = 0;
    for (int c = 0; c < nch; c++) {
        if (c + 2 < nch) { load_kv((c + 2) % 3, (c + 2) << 6); cp_wait<2>(); }
        else if (c + 1 < nch) cp_wait<1>();
        else cp_wait<0>();
        __syncthreads();

        if (c == 0) {
#pragma unroll
            for (int ks = 0; ks < 4; ks++) {
                uint32_t off = swz128(((w * 16 + (lid & 15)) << 7) +
                                      ((ks * 2 + (lid >> 4)) << 4));
                ldsm4(qf[ks], sQ + off);
            }
        }

        const uint32_t sb = sKV + buf * AKV_STAGE;
        const uint32_t sK = sb, sV = sb + AKT;

        // ---- S = Q @ K^T (1-pass) ----
        float sacc[8][4];
#pragma unroll
        for (int nb = 0; nb < 8; nb++)
#pragma unroll
            for (int r = 0; r < 4; r++) sacc[nb][r] = 0.0f;

#pragma unroll
        for (int ks = 0; ks < 4; ks++) {
#pragma unroll
            for (int pi = 0; pi < 4; pi++) {
                uint32_t boff = swz128(((pi * 16 + (lid & 7) + ((lid >> 4) << 3)) << 7) +
                                       ((ks * 2 + ((lid >> 3) & 1)) << 4));
                uint32_t k4[4];
                ldsm4(k4, sK + boff);
#pragma unroll
                for (int sub = 0; sub < 2; sub++)
                    mma16816(sacc[pi * 2 + sub], qf[ks], k4 + sub * 2);
            }
        }

        // ---- scale + causal mask ----
        const int row0 = qbase + w * 16 + (lid >> 2);
        const int row1 = row0 + 8;
        const bool diag = (c >= 2 * qt);
#pragma unroll
        for (int nb = 0; nb < 8; nb++) {
            int col = c * 64 + nb * 8 + ((lid & 3) << 1);
            sacc[nb][0] *= scale; sacc[nb][1] *= scale;
            sacc[nb][2] *= scale; sacc[nb][3] *= scale;
            if (diag) {
                if (col > row0)     sacc[nb][0] = -INFINITY;
                if (col + 1 > row0) sacc[nb][1] = -INFINITY;
                if (col > row1)     sacc[nb][2] = -INFINITY;
                if (col + 1 > row1) sacc[nb][3] = -INFINITY;
            }
        }

        // ---- online softmax ----
        {
            float mx0 = -INFINITY, mx1 = -INFINITY;
#pragma unroll
            for (int nb = 0; nb < 8; nb++) {
                mx0 = fmaxf(mx0, fmaxf(sacc[nb][0], sacc[nb][1]));
                mx1 = fmaxf(mx1, fmaxf(sacc[nb][2], sacc[nb][3]));
            }
            mx0 = fmaxf(mx0, __shfl_xor_sync(0xffffffffu, mx0, 1));
            mx0 = fmaxf(mx0, __shfl_xor_sync(0xffffffffu, mx0, 2));
            mx1 = fmaxf(mx1, __shfl_xor_sync(0xffffffffu, mx1, 1));
            mx1 = fmaxf(mx1, __shfl_xor_sync(0xffffffffu, mx1, 2));
            float mn0 = fmaxf(m0, mx0), mn1 = fmaxf(m1, mx1);
            float f0 = __expf(m0 - mn0), f1 = __expf(m1 - mn1);
            float s0 = 0.0f, s1 = 0.0f;
#pragma unroll
            for (int nb = 0; nb < 8; nb++) {
                sacc[nb][0] = __expf(sacc[nb][0] - mn0);
                sacc[nb][1] = __expf(sacc[nb][1] - mn0);
                sacc[nb][2] = __expf(sacc[nb][2] - mn1);
                sacc[nb][3] = __expf(sacc[nb][3] - mn1);
                s0 += sacc[nb][0] + sacc[nb][1];
                s1 += sacc[nb][2] + sacc[nb][3];
            }
            s0 += __shfl_xor_sync(0xffffffffu, s0, 1);
            s0 += __shfl_xor_sync(0xffffffffu, s0, 2);
            s1 += __shfl_xor_sync(0xffffffffu, s1, 1);
            s1 += __shfl_xor_sync(0xffffffffu, s1, 2);
            l0 = l0 * f0 + s0; l1 = l1 * f1 + s1;
            m0 = mn0; m1 = mn1;
#pragma unroll
            for (int nb = 0; nb < 8; nb++) {
                oacc[nb][0] *= f0; oacc[nb][1] *= f0;
                oacc[nb][2] *= f1; oacc[nb][3] *= f1;
            }
        }

        // ---- O += P @ V (1-pass) ----
#pragma unroll
        for (int kp = 0; kp < 4; kp++) {
            uint32_t ph[4];
            ph[0] = pack_f16(sacc[2 * kp][0], sacc[2 * kp][1]);
            ph[1] = pack_f16(sacc[2 * kp][2], sacc[2 * kp][3]);
            ph[2] = pack_f16(sacc[2 * kp + 1][0], sacc[2 * kp + 1][1]);
            ph[3] = pack_f16(sacc[2 * kp + 1][2], sacc[2 * kp + 1][3]);
            const int mi = lid >> 3, r8 = lid & 7;
#pragma unroll
            for (int pi = 0; pi < 4; pi++) {
                uint32_t voff = swz128(((kp * 16 + ((mi & 1) << 3) + r8) << 7) +
                                       ((pi * 16 + ((mi >> 1) << 3)) << 1));
                uint32_t v4[4];
                ldsm4t(v4, sV + voff);
#pragma unroll
                for (int sub = 0; sub < 2; sub++)
                    mma16816(oacc[pi * 2 + sub], ph, v4 + sub * 2);
            }
        }

        __syncthreads();
        buf = (buf + 1) % 3;
    }

    // ---- epilogue: normalize, fp16 store ----
    const float inv0 = 1.0f / l0, inv1 = 1.0f / l1;
    const int row0 = qbase + w * 16 + (lid >> 2);
    __half* yhb = yh + (size_t)b * CT * CD + (size_t)h * CHD;
#pragma unroll
    for (int nb = 0; nb < 8; nb++) {
        int col = nb * 8 + ((lid & 3) << 1);
        *(uint32_t*)&yhb[(size_t)row0 * CD + col] =
            pack_f16(oacc[nb][0] * inv0, oacc[nb][1] * inv0);
        *(uint32_t*)&yhb[(size_t)(row0 + 8) * CD + col] =
            pack_f16(oacc[nb][2] * inv1, oacc[nb][3] * inv1);
    }
}

// ---------------------------------------------------------------------------
// Launch
// ---------------------------------------------------------------------------
extern "C" void kernel_launch(void* const* d_in, const int* in_sizes, int n_in,
                              void* d_out, int out_size)
{
    (void)in_sizes; (void)n_in; (void)out_size;
    const float* x  = (const float*)d_in[0];
    const float* W1 = (const float*)d_in[1];
    const float* b1 = (const float*)d_in[2];
    const float* W2 = (const float*)d_in[3];
    const float* b2 = (const float*)d_in[4];
    float* out = (float*)d_out;

    __half *qkvh, *xh, *yh, *w1t, *w2t;
    cudaGetSymbolAddress((void**)&qkvh, g_qkvh);
    cudaGetSymbolAddress((void**)&xh, g_xh);
    cudaGetSymbolAddress((void**)&yh, g_yh);
    cudaGetSymbolAddress((void**)&w1t, g_w1t);
    cudaGetSymbolAddress((void**)&w2t, g_w2t);

    cudaFuncSetAttribute(gemm_f16_kernel<true>,
                         cudaFuncAttributeMaxDynamicSharedMemorySize, GSMEM);
    cudaFuncSetAttribute(gemm_f16_kernel<false>,
                         cudaFuncAttributeMaxDynamicSharedMemorySize, GSMEM);
    cudaFuncSetAttribute(attn_f16_kernel,
                         cudaFuncAttributeMaxDynamicSharedMemorySize, ASMEM);

    const int M = CB * CT;                 // 4096
    const int n4x = M * CD / 4;

    convert_f16_kernel<<<(n4x + 255) / 256, 256>>>(x, xh, n4x);
    transpose_f16_kernel<<<dim3(3 * CD / 32, CD / 32), dim3(32, 8)>>>(W1, w1t, CD, 3 * CD);
    transpose_f16_kernel<<<dim3(CD / 32, CD / 32), dim3(32, 8)>>>(W2, w2t, CD, CD);

    // qkv (fp16) = x @ W1 + b1
    gemm_f16_kernel<true><<<dim3(3 * CD / 128, M / 128), 256, GSMEM>>>(
        xh, w1t, b1, nullptr, qkvh, 3 * CD, CD);

    // flash attention -> y (fp16)
    attn_f16_kernel<<<dim3(CT / 128, CH, CB), 256, ASMEM>>>(qkvh, yh);

    // out (fp32) = y @ W2 + b2
    gemm_f16_kernel<false><<<dim3(CD / 128, M / 128), 256, GSMEM>>>(
        yh, w2t, b2, out, nullptr, CD, CD);
}

// round 10
// speedup vs baseline: 6.9740x; 1.0441x over previous
#include <cuda_runtime.h>
#include <cuda_fp16.h>
#include <math.h>
#include <stdint.h>

#define CB 2
#define CT 2048
#define CD 1024
#define CH 16
#define CHD 64

// ---------------------------------------------------------------------------
// Device scratch (no cudaMalloc allowed)
// ---------------------------------------------------------------------------
__device__ __align__(128) __half g_qkvh[(size_t)CB * CT * 3 * CD];  // qkv fp16 (Q cols pre-scaled)
__device__ __align__(128) __half g_xh[(size_t)CB * CT * CD];        // x fp16
__device__ __align__(128) __half g_yh[(size_t)CB * CT * CD];        // y fp16
__device__ __align__(128) __half g_w1t[(size_t)3 * CD * CD];        // W1^T [N,K]
__device__ __align__(128) __half g_w2t[(size_t)CD * CD];            // W2^T [N,K]

// Q pre-scale: 1/sqrt(64) * log2(e)  (softmax uses exp2 directly)
#define QSCALE 0.1803368801111244f

// ---------------------------------------------------------------------------
// Low-level helpers
// ---------------------------------------------------------------------------
__device__ __forceinline__ uint32_t smem_u32(const void* p) {
    uint32_t a;
    asm("{ .reg .u64 t; cvta.to.shared.u64 t, %1; cvt.u32.u64 %0, t; }" : "=r"(a) : "l"(p));
    return a;
}
__device__ __forceinline__ void cpasync16(uint32_t s, const void* g) {
    asm volatile("cp.async.cg.shared.global [%0], [%1], 16;" :: "r"(s), "l"(g));
}
__device__ __forceinline__ void cp_commit() {
    asm volatile("cp.async.commit_group;" ::: "memory");
}
template <int N>
__device__ __forceinline__ void cp_wait() {
    asm volatile("cp.async.wait_group %0;" :: "n"(N) : "memory");
}
__device__ __forceinline__ void ldsm4(uint32_t* r, uint32_t addr) {
    asm volatile("ldmatrix.sync.aligned.m8n8.x4.shared.b16 {%0,%1,%2,%3}, [%4];"
                 : "=r"(r[0]), "=r"(r[1]), "=r"(r[2]), "=r"(r[3]) : "r"(addr));
}
__device__ __forceinline__ void ldsm4t(uint32_t* r, uint32_t addr) {
    asm volatile("ldmatrix.sync.aligned.m8n8.x4.trans.shared.b16 {%0,%1,%2,%3}, [%4];"
                 : "=r"(r[0]), "=r"(r[1]), "=r"(r[2]), "=r"(r[3]) : "r"(addr));
}
__device__ __forceinline__ void mma16816(float* d, const uint32_t* a, const uint32_t* b) {
    asm volatile(
        "mma.sync.aligned.m16n8k16.row.col.f32.f16.f16.f32 "
        "{%0,%1,%2,%3}, {%4,%5,%6,%7}, {%8,%9}, {%0,%1,%2,%3};"
        : "+f"(d[0]), "+f"(d[1]), "+f"(d[2]), "+f"(d[3])
        : "r"(a[0]), "r"(a[1]), "r"(a[2]), "r"(a[3]), "r"(b[0]), "r"(b[1]));
}
__device__ __forceinline__ uint32_t swz128(uint32_t b) { return b ^ ((b >> 3) & 0x70); }
__device__ __forceinline__ uint32_t pack_f16(float a, float b) {
    __half2 v = __floats2half2_rn(a, b);
    return *(uint32_t*)&v;
}
__device__ __forceinline__ float fexp2(float x) {
    float y;
    asm("ex2.approx.ftz.f32 %0, %1;" : "=f"(y) : "f"(x));
    return y;
}

// ---------------------------------------------------------------------------
// fp32 -> fp16 convert (x)
// ---------------------------------------------------------------------------
__global__ __launch_bounds__(256) void convert_f16_kernel(
    const float* __restrict__ in, __half* __restrict__ hi, int n4)
{
    int i = blockIdx.x * blockDim.x + threadIdx.x;
    if (i >= n4) return;
    float4 v = ((const float4*)in)[i];
    ((uint2*)hi)[i] = make_uint2(pack_f16(v.x, v.y), pack_f16(v.z, v.w));
}

// ---------------------------------------------------------------------------
// W [K,N] fp32 -> Wt [N,K] fp16 (transpose)
// ---------------------------------------------------------------------------
__global__ __launch_bounds__(256) void transpose_f16_kernel(
    const float* __restrict__ W, __half* __restrict__ outh, int K, int N)
{
    __shared__ float t[32][33];
    int n0 = blockIdx.x * 32, k0 = blockIdx.y * 32;
    int tx = threadIdx.x, ty = threadIdx.y;
#pragma unroll
    for (int j = 0; j < 4; j++)
        t[ty + j * 8][tx] = W[(size_t)(k0 + ty + j * 8) * N + n0 + tx];
    __syncthreads();
#pragma unroll
    for (int j = 0; j < 4; j++)
        outh[(size_t)(n0 + ty + j * 8) * K + k0 + tx] = __float2half_rn(t[tx][ty + j * 8]);
}

// ---------------------------------------------------------------------------
// HMMA fp16 GEMM: C = A @ Bt^T + bias. 1-pass fp16.
// CTA 256x128, BK=64, 8 warps; each warp: 64x64 output as two 32x64 halves
// (B fragments reused across halves -> +47% MAC per smem byte).
// 3-stage cp.async pipeline, stage = A(32KB)+B(16KB) = 48KB. 1 CTA/SM.
// F16OUT: fp16 out; cols < qcols additionally scaled by QSCALE (Q pre-scale).
// ---------------------------------------------------------------------------
#define GA_TILE 32768               // 256 rows x 128B
#define GB_TILE 16384               // 128 rows x 128B
#define GSTAGE (GA_TILE + GB_TILE)  // 49152
#define GSMEM (3 * GSTAGE)          // 147456

template <bool F16OUT>
__global__ __launch_bounds__(256, 1) void gemm_f16_kernel(
    const __half* __restrict__ Ag, const __half* __restrict__ Bg,
    const float* __restrict__ bias, float* __restrict__ Cf,
    __half* __restrict__ Ch, int qcols, int N, int K)
{
    extern __shared__ char smem[];
    const uint32_t sbase = smem_u32(smem);
    const int tid = threadIdx.x;
    const int wid = tid >> 5;
    const int lid = tid & 31;
    const int wm = wid & 3;          // warp m-row (32 rows per half)
    const int wn = wid >> 2;         // warp n-col (64 cols)
    const int bm = blockIdx.y * 256;
    const int bn = blockIdx.x * 128;

    const int nch = K >> 6;

    auto load_stage = [&](int buf, int k0) {
        uint32_t sb = sbase + buf * GSTAGE;
#pragma unroll
        for (int i = 0; i < 12; i++) {
            int c = tid + (i << 8);              // 0..3071
            uint32_t dst;
            size_t g;
            if (c < 2048) {                      // A: 256 rows
                int row = c >> 3, seg = c & 7;
                dst = sb + swz128((row << 7) + (seg << 4));
                g = (size_t)(bm + row) * K + k0 + (seg << 3);
                cpasync16(dst, Ag + g);
            } else {                             // B: 128 rows
                int cc = c - 2048;
                int row = cc >> 3, seg = cc & 7;
                dst = sb + GA_TILE + swz128((row << 7) + (seg << 4));
                g = (size_t)(bn + row) * K + k0 + (seg << 3);
                cpasync16(dst, Bg + g);
            }
        }
        cp_commit();
    };

    float d[2][2][8][4];
#pragma unroll
    for (int hf = 0; hf < 2; hf++)
#pragma unroll
        for (int mi = 0; mi < 2; mi++)
#pragma unroll
            for (int ni = 0; ni < 8; ni++)
#pragma unroll
                for (int r = 0; r < 4; r++) d[hf][mi][ni][r] = 0.0f;

    load_stage(0, 0);
    load_stage(1, 64);

    int buf = 0;
    for (int c = 0; c < nch; c++) {
        if (c + 2 < nch) { load_stage((c + 2) % 3, (c + 2) << 6); cp_wait<2>(); }
        else if (c + 1 < nch) cp_wait<1>();
        else cp_wait<0>();
        __syncthreads();

        const uint32_t sb = sbase + buf * GSTAGE;
        const uint32_t aT = sb, bT = sb + GA_TILE;

#pragma unroll
        for (int ks = 0; ks < 4; ks++) {
            uint32_t b4[4][4];
#pragma unroll
            for (int pi = 0; pi < 4; pi++) {
                uint32_t boff = swz128(((wn * 64 + pi * 16 + (lid & 7) + ((lid >> 4) << 3)) << 7) +
                                       ((ks * 2 + ((lid >> 3) & 1)) << 4));
                ldsm4(b4[pi], bT + boff);
            }
#pragma unroll
            for (int hf = 0; hf < 2; hf++) {
                uint32_t a4[2][4];
#pragma unroll
                for (int mi = 0; mi < 2; mi++) {
                    uint32_t off = swz128(((hf * 128 + wm * 32 + mi * 16 + (lid & 15)) << 7) +
                                          ((ks * 2 + (lid >> 4)) << 4));
                    ldsm4(a4[mi], aT + off);
                }
#pragma unroll
                for (int pi = 0; pi < 4; pi++)
#pragma unroll
                    for (int mi = 0; mi < 2; mi++)
#pragma unroll
                        for (int sub = 0; sub < 2; sub++)
                            mma16816(d[hf][mi][pi * 2 + sub], a4[mi], b4[pi] + sub * 2);
            }
        }
        __syncthreads();
        buf = (buf + 1) % 3;
    }

#pragma unroll
    for (int hf = 0; hf < 2; hf++) {
#pragma unroll
        for (int mi = 0; mi < 2; mi++) {
            int row = bm + hf * 128 + wm * 32 + mi * 16 + (lid >> 2);
#pragma unroll
            for (int ni = 0; ni < 8; ni++) {
                int col = bn + wn * 64 + ni * 8 + ((lid & 3) << 1);
                float2 bv = *(const float2*)&bias[col];
                float v00 = d[hf][mi][ni][0] + bv.x, v01 = d[hf][mi][ni][1] + bv.y;
                float v10 = d[hf][mi][ni][2] + bv.x, v11 = d[hf][mi][ni][3] + bv.y;
                if (F16OUT) {
                    float qs = (col < qcols) ? QSCALE : 1.0f;
                    v00 *= qs; v01 *= qs; v10 *= qs; v11 *= qs;
                    *(uint32_t*)&Ch[(size_t)row * N + col] = pack_f16(v00, v01);
                    *(uint32_t*)&Ch[(size_t)(row + 8) * N + col] = pack_f16(v10, v11);
                } else {
                    *(float2*)&Cf[(size_t)row * N + col] = make_float2(v00, v01);
                    *(float2*)&Cf[(size_t)(row + 8) * N + col] = make_float2(v10, v11);
                }
            }
        }
    }
}

// ---------------------------------------------------------------------------
// HMMA fp16 flash attention. Q pre-scaled by 1/8*log2e -> softmax uses exp2.
// All operands single fp16; fp32 accumulate. 3-stage KV pipeline;
// big causal tiles scheduled first; y fp16 out.
// ---------------------------------------------------------------------------
#define AQT 16384
#define AKT 8192
#define AKV_STAGE (2 * AKT)               // K + V = 16KB
#define ASMEM (AQT + 3 * AKV_STAGE)       // 65536; 2 CTAs/SM

__global__ __launch_bounds__(256, 2) void attn_f16_kernel(
    const __half* __restrict__ qkvh, __half* __restrict__ yh)
{
    extern __shared__ char smem[];
    const uint32_t sbase = smem_u32(smem);
    const int tid = threadIdx.x;
    const int w = tid >> 5;
    const int lid = tid & 31;
    const int qt = gridDim.x - 1 - blockIdx.x;
    const int h  = blockIdx.y;
    const int b  = blockIdx.z;
    const int qbase = qt * 128;
    const int nch = 2 * (qt + 1);

    const uint32_t sQ = sbase;
    const uint32_t sKV = sbase + AQT;

    const size_t rowbase = (size_t)b * CT * 3 * CD + (size_t)h * CHD;

    // Q load (joins KV group 0's commit)
#pragma unroll
    for (int i = 0; i < 4; i++) {
        int c = tid + (i << 8);
        int row = c >> 3;
        int seg = c & 7;
        uint32_t so = swz128((row << 7) + (seg << 4));
        cpasync16(sQ + so, qkvh + rowbase + (size_t)(qbase + row) * (3 * CD) + (seg << 3));
    }

    auto load_kv = [&](int buf, int kt0) {
        uint32_t sb = sKV + buf * AKV_STAGE;
#pragma unroll
        for (int i = 0; i < 4; i++) {
            int c = tid + (i << 8);
            int tile = c >> 9;
            int row = (c >> 3) & 63;
            int seg = c & 7;
            uint32_t so = swz128((row << 7) + (seg << 4));
            size_t ga = rowbase + (size_t)(kt0 + row) * (3 * CD) + (seg << 3) +
                        (tile ? 2 * CD : CD);
            cpasync16(sb + tile * AKT + so, qkvh + ga);
        }
        cp_commit();
    };

    load_kv(0, 0);
    load_kv(1, 64);                     // nch >= 2 always

    float m0 = -INFINITY, m1 = -INFINITY, l0 = 0.0f, l1 = 0.0f;
    float oacc[8][4];
#pragma unroll
    for (int nb = 0; nb < 8; nb++)
#pragma unroll
        for (int r = 0; r < 4; r++) oacc[nb][r] = 0.0f;

    uint32_t qf[4][4];

    int buf = 0;
    for (int c = 0; c < nch; c++) {
        if (c + 2 < nch) { load_kv((c + 2) % 3, (c + 2) << 6); cp_wait<2>(); }
        else if (c + 1 < nch) cp_wait<1>();
        else cp_wait<0>();
        __syncthreads();

        if (c == 0) {
#pragma unroll
            for (int ks = 0; ks < 4; ks++) {
                uint32_t off = swz128(((w * 16 + (lid & 15)) << 7) +
                                      ((ks * 2 + (lid >> 4)) << 4));
                ldsm4(qf[ks], sQ + off);
            }
        }

        const uint32_t sb = sKV + buf * AKV_STAGE;
        const uint32_t sK = sb, sV = sb + AKT;

        // ---- S = Q' @ K^T (logits already x log2e/8 via Q pre-scale) ----
        float sacc[8][4];
#pragma unroll
        for (int nb = 0; nb < 8; nb++)
#pragma unroll
            for (int r = 0; r < 4; r++) sacc[nb][r] = 0.0f;

#pragma unroll
        for (int ks = 0; ks < 4; ks++) {
#pragma unroll
            for (int pi = 0; pi < 4; pi++) {
                uint32_t boff = swz128(((pi * 16 + (lid & 7) + ((lid >> 4) << 3)) << 7) +
                                       ((ks * 2 + ((lid >> 3) & 1)) << 4));
                uint32_t k4[4];
                ldsm4(k4, sK + boff);
#pragma unroll
                for (int sub = 0; sub < 2; sub++)
                    mma16816(sacc[pi * 2 + sub], qf[ks], k4 + sub * 2);
            }
        }

        // ---- causal mask (diagonal super-chunks only) ----
        const int row0 = qbase + w * 16 + (lid >> 2);
        const int row1 = row0 + 8;
        const bool diag = (c >= 2 * qt);
        if (diag) {
#pragma unroll
            for (int nb = 0; nb < 8; nb++) {
                int col = c * 64 + nb * 8 + ((lid & 3) << 1);
                if (col > row0)     sacc[nb][0] = -INFINITY;
                if (col + 1 > row0) sacc[nb][1] = -INFINITY;
                if (col > row1)     sacc[nb][2] = -INFINITY;
                if (col + 1 > row1) sacc[nb][3] = -INFINITY;
            }
        }

        // ---- online softmax (base-2) ----
        {
            float mx0 = -INFINITY, mx1 = -INFINITY;
#pragma unroll
            for (int nb = 0; nb < 8; nb++) {
                mx0 = fmaxf(mx0, fmaxf(sacc[nb][0], sacc[nb][1]));
                mx1 = fmaxf(mx1, fmaxf(sacc[nb][2], sacc[nb][3]));
            }
            mx0 = fmaxf(mx0, __shfl_xor_sync(0xffffffffu, mx0, 1));
            mx0 = fmaxf(mx0, __shfl_xor_sync(0xffffffffu, mx0, 2));
            mx1 = fmaxf(mx1, __shfl_xor_sync(0xffffffffu, mx1, 1));
            mx1 = fmaxf(mx1, __shfl_xor_sync(0xffffffffu, mx1, 2));
            float mn0 = fmaxf(m0, mx0), mn1 = fmaxf(m1, mx1);
            float f0 = fexp2(m0 - mn0), f1 = fexp2(m1 - mn1);
            float s0 = 0.0f, s1 = 0.0f;
#pragma unroll
            for (int nb = 0; nb < 8; nb++) {
                sacc[nb][0] = fexp2(sacc[nb][0] - mn0);
                sacc[nb][1] = fexp2(sacc[nb][1] - mn0);
                sacc[nb][2] = fexp2(sacc[nb][2] - mn1);
                sacc[nb][3] = fexp2(sacc[nb][3] - mn1);
                s0 += sacc[nb][0] + sacc[nb][1];
                s1 += sacc[nb][2] + sacc[nb][3];
            }
            s0 += __shfl_xor_sync(0xffffffffu, s0, 1);
            s0 += __shfl_xor_sync(0xffffffffu, s0, 2);
            s1 += __shfl_xor_sync(0xffffffffu, s1, 1);
            s1 += __shfl_xor_sync(0xffffffffu, s1, 2);
            l0 = l0 * f0 + s0; l1 = l1 * f1 + s1;
            m0 = mn0; m1 = mn1;
#pragma unroll
            for (int nb = 0; nb < 8; nb++) {
                oacc[nb][0] *= f0; oacc[nb][1] *= f0;
                oacc[nb][2] *= f1; oacc[nb][3] *= f1;
            }
        }

        // ---- O += P @ V (1-pass) ----
#pragma unroll
        for (int kp = 0; kp < 4; kp++) {
            uint32_t ph[4];
            ph[0] = pack_f16(sacc[2 * kp][0], sacc[2 * kp][1]);
            ph[1] = pack_f16(sacc[2 * kp][2], sacc[2 * kp][3]);
            ph[2] = pack_f16(sacc[2 * kp + 1][0], sacc[2 * kp + 1][1]);
            ph[3] = pack_f16(sacc[2 * kp + 1][2], sacc[2 * kp + 1][3]);
            const int mi = lid >> 3, r8 = lid & 7;
#pragma unroll
            for (int pi = 0; pi < 4; pi++) {
                uint32_t voff = swz128(((kp * 16 + ((mi & 1) << 3) + r8) << 7) +
                                       ((pi * 16 + ((mi >> 1) << 3)) << 1));
                uint32_t v4[4];
                ldsm4t(v4, sV + voff);
#pragma unroll
                for (int sub = 0; sub < 2; sub++)
                    mma16816(oacc[pi * 2 + sub], ph, v4 + sub * 2);
            }
        }

        __syncthreads();
        buf = (buf + 1) % 3;
    }

    // ---- epilogue: normalize, fp16 store ----
    const float inv0 = 1.0f / l0, inv1 = 1.0f / l1;
    const int row0 = qbase + w * 16 + (lid >> 2);
    __half* yhb = yh + (size_t)b * CT * CD + (size_t)h * CHD;
#pragma unroll
    for (int nb = 0; nb < 8; nb++) {
        int col = nb * 8 + ((lid & 3) << 1);
        *(uint32_t*)&yhb[(size_t)row0 * CD + col] =
            pack_f16(oacc[nb][0] * inv0, oacc[nb][1] * inv0);
        *(uint32_t*)&yhb[(size_t)(row0 + 8) * CD + col] =
            pack_f16(oacc[nb][2] * inv1, oacc[nb][3] * inv1);
    }
}

// ---------------------------------------------------------------------------
// Launch
// ---------------------------------------------------------------------------
extern "C" void kernel_launch(void* const* d_in, const int* in_sizes, int n_in,
                              void* d_out, int out_size)
{
    (void)in_sizes; (void)n_in; (void)out_size;
    const float* x  = (const float*)d_in[0];
    const float* W1 = (const float*)d_in[1];
    const float* b1 = (const float*)d_in[2];
    const float* W2 = (const float*)d_in[3];
    const float* b2 = (const float*)d_in[4];
    float* out = (float*)d_out;

    __half *qkvh, *xh, *yh, *w1t, *w2t;
    cudaGetSymbolAddress((void**)&qkvh, g_qkvh);
    cudaGetSymbolAddress((void**)&xh, g_xh);
    cudaGetSymbolAddress((void**)&yh, g_yh);
    cudaGetSymbolAddress((void**)&w1t, g_w1t);
    cudaGetSymbolAddress((void**)&w2t, g_w2t);

    cudaFuncSetAttribute(gemm_f16_kernel<true>,
                         cudaFuncAttributeMaxDynamicSharedMemorySize, GSMEM);
    cudaFuncSetAttribute(gemm_f16_kernel<false>,
                         cudaFuncAttributeMaxDynamicSharedMemorySize, GSMEM);
    cudaFuncSetAttribute(attn_f16_kernel,
                         cudaFuncAttributeMaxDynamicSharedMemorySize, ASMEM);

    const int M = CB * CT;                 // 4096
    const int n4x = M * CD / 4;

    convert_f16_kernel<<<(n4x + 255) / 256, 256>>>(x, xh, n4x);
    transpose_f16_kernel<<<dim3(3 * CD / 32, CD / 32), dim3(32, 8)>>>(W1, w1t, CD, 3 * CD);
    transpose_f16_kernel<<<dim3(CD / 32, CD / 32), dim3(32, 8)>>>(W2, w2t, CD, CD);

    // qkv (fp16) = x @ W1 + b1 ; Q columns (col < CD) pre-scaled by QSCALE
    gemm_f16_kernel<true><<<dim3(3 * CD / 128, M / 256), 256, GSMEM>>>(
        xh, w1t, b1, nullptr, qkvh, CD, 3 * CD, CD);

    // flash attention -> y (fp16)
    attn_f16_kernel<<<dim3(CT / 128, CH, CB), 256, ASMEM>>>(qkvh, yh);

    // out (fp32) = y @ W2 + b2
    gemm_f16_kernel<false><<<dim3(CD / 128, M / 256), 256, GSMEM>>>(
        yh, w2t, b2, out, nullptr, 0, CD, CD);
}

// round 12
// speedup vs baseline: 7.0906x; 1.0167x over previous
#include <cuda_runtime.h>
#include <cuda_fp16.h>
#include <math.h>
#include <stdint.h>

#define CB 2
#define CT 2048
#define CD 1024
#define CH 16
#define CHD 64

// ---------------------------------------------------------------------------
// Device scratch (no cudaMalloc allowed)
// ---------------------------------------------------------------------------
__device__ __align__(128) __half g_qkvh[(size_t)CB * CT * 3 * CD];  // qkv fp16 (Q cols pre-scaled)
__device__ __align__(128) __half g_xh[(size_t)CB * CT * CD];        // x fp16
__device__ __align__(128) __half g_yh[(size_t)CB * CT * CD];        // y fp16
__device__ __align__(128) __half g_w1t[(size_t)3 * CD * CD];        // W1^T [N,K]
__device__ __align__(128) __half g_w2t[(size_t)CD * CD];            // W2^T [N,K]

// Q pre-scale: 1/sqrt(64) * log2(e)
#define QSCALE 0.1803368801111244f

// ---------------------------------------------------------------------------
// Low-level helpers
// ---------------------------------------------------------------------------
__device__ __forceinline__ uint32_t smem_u32(const void* p) {
    uint32_t a;
    asm("{ .reg .u64 t; cvta.to.shared.u64 t, %1; cvt.u32.u64 %0, t; }" : "=r"(a) : "l"(p));
    return a;
}
__device__ __forceinline__ void cpasync16(uint32_t s, const void* g) {
    asm volatile("cp.async.cg.shared.global [%0], [%1], 16;" :: "r"(s), "l"(g));
}
__device__ __forceinline__ void cp_commit() {
    asm volatile("cp.async.commit_group;" ::: "memory");
}
template <int N>
__device__ __forceinline__ void cp_wait() {
    asm volatile("cp.async.wait_group %0;" :: "n"(N) : "memory");
}
__device__ __forceinline__ void ldsm4(uint32_t* r, uint32_t addr) {
    asm volatile("ldmatrix.sync.aligned.m8n8.x4.shared.b16 {%0,%1,%2,%3}, [%4];"
                 : "=r"(r[0]), "=r"(r[1]), "=r"(r[2]), "=r"(r[3]) : "r"(addr));
}
__device__ __forceinline__ void ldsm4t(uint32_t* r, uint32_t addr) {
    asm volatile("ldmatrix.sync.aligned.m8n8.x4.trans.shared.b16 {%0,%1,%2,%3}, [%4];"
                 : "=r"(r[0]), "=r"(r[1]), "=r"(r[2]), "=r"(r[3]) : "r"(addr));
}
__device__ __forceinline__ void mma16816(float* d, const uint32_t* a, const uint32_t* b) {
    asm volatile(
        "mma.sync.aligned.m16n8k16.row.col.f32.f16.f16.f32 "
        "{%0,%1,%2,%3}, {%4,%5,%6,%7}, {%8,%9}, {%0,%1,%2,%3};"
        : "+f"(d[0]), "+f"(d[1]), "+f"(d[2]), "+f"(d[3])
        : "r"(a[0]), "r"(a[1]), "r"(a[2]), "r"(a[3]), "r"(b[0]), "r"(b[1]));
}
__device__ __forceinline__ uint32_t swz128(uint32_t b) { return b ^ ((b >> 3) & 0x70); }
__device__ __forceinline__ uint32_t pack_f16(float a, float b) {
    __half2 v = __floats2half2_rn(a, b);
    return *(uint32_t*)&v;
}
__device__ __forceinline__ float fexp2(float x) {
    float y;
    asm("ex2.approx.ftz.f32 %0, %1;" : "=f"(y) : "f"(x));
    return y;
}

// ---------------------------------------------------------------------------
// fp32 -> fp16 convert (x)
// ---------------------------------------------------------------------------
__global__ __launch_bounds__(256) void convert_f16_kernel(
    const float* __restrict__ in, __half* __restrict__ hi, int n4)
{
    int i = blockIdx.x * blockDim.x + threadIdx.x;
    if (i >= n4) return;
    float4 v = ((const float4*)in)[i];
    ((uint2*)hi)[i] = make_uint2(pack_f16(v.x, v.y), pack_f16(v.z, v.w));
}

// ---------------------------------------------------------------------------
// W [K,N] fp32 -> Wt [N,K] fp16 (transpose)
// ---------------------------------------------------------------------------
__global__ __launch_bounds__(256) void transpose_f16_kernel(
    const float* __restrict__ W, __half* __restrict__ outh, int K, int N)
{
    __shared__ float t[32][33];
    int n0 = blockIdx.x * 32, k0 = blockIdx.y * 32;
    int tx = threadIdx.x, ty = threadIdx.y;
#pragma unroll
    for (int j = 0; j < 4; j++)
        t[ty + j * 8][tx] = W[(size_t)(k0 + ty + j * 8) * N + n0 + tx];
    __syncthreads();
#pragma unroll
    for (int j = 0; j < 4; j++)
        outh[(size_t)(n0 + ty + j * 8) * K + k0 + tx] = __float2half_rn(t[tx][ty + j * 8]);
}

// ---------------------------------------------------------------------------
// HMMA fp16 GEMM: C = A @ Bt^T + bias. 1-pass fp16.
// CTA 256x128, 512 threads (16 warps: 8m x 2n, warp tile 32x64).
// Super-chunk BK=128 (two 64-k sub-tiles, 128B-row swizzle each).
// 2 super-stages (96KB each), ONE __syncthreads per super-chunk:
//   cp_wait -> sync (publish stage c + protect ring slot) -> issue c+1 -> compute c
// 2048 MMAs/SM per sync interval.
// ---------------------------------------------------------------------------
#define SUPA 32768                  // one 64-k A sub-tile (256 rows x 128B)
#define SUPB 16384                  // one 64-k B sub-tile (128 rows x 128B)
#define SUP_STAGE (2 * SUPA + 2 * SUPB)   // 98304
#define GSMEM (2 * SUP_STAGE)             // 196608

template <bool F16OUT>
__global__ __launch_bounds__(512, 1) void gemm_f16_kernel(
    const __half* __restrict__ Ag, const __half* __restrict__ Bg,
    const float* __restrict__ bias, float* __restrict__ Cf,
    __half* __restrict__ Ch, int qcols, int N, int K)
{
    extern __shared__ char smem[];
    const uint32_t sbase = smem_u32(smem);
    const int tid = threadIdx.x;
    const int wid = tid >> 5;
    const int lid = tid & 31;
    const int wm = wid & 7;          // 0..7 -> 32-row slice
    const int wn = wid >> 3;         // 0..1 -> 64-col slice
    const int bm = blockIdx.y * 256;
    const int bn = blockIdx.x * 128;

    const int nsup = K >> 7;         // super-chunks of 128 k

    auto load_super = [&](int buf, int k0) {
        uint32_t sb = sbase + buf * SUP_STAGE;
#pragma unroll
        for (int i = 0; i < 12; i++) {
            int c = tid + (i << 9);              // 0..6143 16B-chunks
            if (c < 4096) {                      // A: two sub-tiles, 256 rows each
                int sub = c >> 11;
                int cc = c & 2047;
                int row = cc >> 3, seg = cc & 7;
                uint32_t dst = sb + sub * SUPA + swz128((row << 7) + (seg << 4));
                cpasync16(dst, Ag + (size_t)(bm + row) * K + k0 + sub * 64 + (seg << 3));
            } else {                             // B: two sub-tiles, 128 rows each
                int cc = c - 4096;
                int sub = cc >> 10;
                int c2 = cc & 1023;
                int row = c2 >> 3, seg = c2 & 7;
                uint32_t dst = sb + 2 * SUPA + sub * SUPB + swz128((row << 7) + (seg << 4));
                cpasync16(dst, Bg + (size_t)(bn + row) * K + k0 + sub * 64 + (seg << 3));
            }
        }
        cp_commit();
    };

    float d[2][8][4];
#pragma unroll
    for (int mi = 0; mi < 2; mi++)
#pragma unroll
        for (int ni = 0; ni < 8; ni++)
#pragma unroll
            for (int r = 0; r < 4; r++) d[mi][ni][r] = 0.0f;

    load_super(0, 0);

    for (int c = 0; c < nsup; c++) {
        cp_wait<0>();                // my copies for stage c done (only group outstanding)
        __syncthreads();             // publish stage c; all warps done reading stage c-1
        if (c + 1 < nsup) load_super((c + 1) & 1, (c + 1) << 7);

        const uint32_t sb = sbase + (c & 1) * SUP_STAGE;
#pragma unroll
        for (int sub = 0; sub < 2; sub++) {
            const uint32_t aT = sb + sub * SUPA;
            const uint32_t bT = sb + 2 * SUPA + sub * SUPB;
#pragma unroll
            for (int ks = 0; ks < 4; ks++) {
                uint32_t a4[2][4];
#pragma unroll
                for (int mi = 0; mi < 2; mi++) {
                    uint32_t off = swz128(((wm * 32 + mi * 16 + (lid & 15)) << 7) +
                                          ((ks * 2 + (lid >> 4)) << 4));
                    ldsm4(a4[mi], aT + off);
                }
#pragma unroll
                for (int pi = 0; pi < 4; pi++) {
                    uint32_t boff = swz128(((wn * 64 + pi * 16 + (lid & 7) + ((lid >> 4) << 3)) << 7) +
                                           ((ks * 2 + ((lid >> 3) & 1)) << 4));
                    uint32_t b4[4];
                    ldsm4(b4, bT + boff);
#pragma unroll
                    for (int mi = 0; mi < 2; mi++)
#pragma unroll
                        for (int sub2 = 0; sub2 < 2; sub2++)
                            mma16816(d[mi][pi * 2 + sub2], a4[mi], b4 + sub2 * 2);
                }
            }
        }
    }

#pragma unroll
    for (int mi = 0; mi < 2; mi++) {
        int row = bm + wm * 32 + mi * 16 + (lid >> 2);
#pragma unroll
        for (int ni = 0; ni < 8; ni++) {
            int col = bn + wn * 64 + ni * 8 + ((lid & 3) << 1);
            float2 bv = *(const float2*)&bias[col];
            float v00 = d[mi][ni][0] + bv.x, v01 = d[mi][ni][1] + bv.y;
            float v10 = d[mi][ni][2] + bv.x, v11 = d[mi][ni][3] + bv.y;
            if (F16OUT) {
                float qs = (col < qcols) ? QSCALE : 1.0f;
                v00 *= qs; v01 *= qs; v10 *= qs; v11 *= qs;
                *(uint32_t*)&Ch[(size_t)row * N + col] = pack_f16(v00, v01);
                *(uint32_t*)&Ch[(size_t)(row + 8) * N + col] = pack_f16(v10, v11);
            } else {
                *(float2*)&Cf[(size_t)row * N + col] = make_float2(v00, v01);
                *(float2*)&Cf[(size_t)(row + 8) * N + col] = make_float2(v10, v11);
            }
        }
    }
}

// ---------------------------------------------------------------------------
// HMMA fp16 flash attention. Q pre-scaled -> softmax in base-2 (ex2.approx).
// 3-stage KV ring, ONE __syncthreads per chunk. Big causal tiles first.
// ---------------------------------------------------------------------------
#define AQT 16384
#define AKT 8192
#define AKV_STAGE (2 * AKT)               // K + V = 16KB
#define ASMEM (AQT + 3 * AKV_STAGE)       // 65536; 2 CTAs/SM

__global__ __launch_bounds__(256, 2) void attn_f16_kernel(
    const __half* __restrict__ qkvh, __half* __restrict__ yh)
{
    extern __shared__ char smem[];
    const uint32_t sbase = smem_u32(smem);
    const int tid = threadIdx.x;
    const int w = tid >> 5;
    const int lid = tid & 31;
    const int qt = gridDim.x - 1 - blockIdx.x;
    const int h  = blockIdx.y;
    const int b  = blockIdx.z;
    const int qbase = qt * 128;
    const int nch = 2 * (qt + 1);

    const uint32_t sQ = sbase;
    const uint32_t sKV = sbase + AQT;

    const size_t rowbase = (size_t)b * CT * 3 * CD + (size_t)h * CHD;

    // Q load (joins KV group 0's commit)
#pragma unroll
    for (int i = 0; i < 4; i++) {
        int c = tid + (i << 8);
        int row = c >> 3;
        int seg = c & 7;
        uint32_t so = swz128((row << 7) + (seg << 4));
        cpasync16(sQ + so, qkvh + rowbase + (size_t)(qbase + row) * (3 * CD) + (seg << 3));
    }

    auto load_kv = [&](int buf, int kt0) {
        uint32_t sb = sKV + buf * AKV_STAGE;
#pragma unroll
        for (int i = 0; i < 4; i++) {
            int c = tid + (i << 8);
            int tile = c >> 9;
            int row = (c >> 3) & 63;
            int seg = c & 7;
            uint32_t so = swz128((row << 7) + (seg << 4));
            size_t ga = rowbase + (size_t)(kt0 + row) * (3 * CD) + (seg << 3) +
                        (tile ? 2 * CD : CD);
            cpasync16(sb + tile * AKT + so, qkvh + ga);
        }
        cp_commit();
    };

    load_kv(0, 0);
    load_kv(1, 64);                     // nch >= 2 always

    float m0 = -INFINITY, m1 = -INFINITY, l0 = 0.0f, l1 = 0.0f;
    float oacc[8][4];
#pragma unroll
    for (int nb = 0; nb < 8; nb++)
#pragma unroll
        for (int r = 0; r < 4; r++) oacc[nb][r] = 0.0f;

    uint32_t qf[4][4];

    int buf = 0;
    for (int c = 0; c < nch; c++) {
        // wait stage c (leave group c+1 in flight when it exists)
        if (c + 1 < nch) cp_wait<1>(); else cp_wait<0>();
        __syncthreads();                 // publish stage c; ring slot (c+2)%3 free
        if (c + 2 < nch) load_kv((c + 2) % 3, (c + 2) << 6);

        if (c == 0) {
#pragma unroll
            for (int ks = 0; ks < 4; ks++) {
                uint32_t off = swz128(((w * 16 + (lid & 15)) << 7) +
                                      ((ks * 2 + (lid >> 4)) << 4));
                ldsm4(qf[ks], sQ + off);
            }
        }

        const uint32_t sb = sKV + buf * AKV_STAGE;
        const uint32_t sK = sb, sV = sb + AKT;

        // ---- S = Q' @ K^T ----
        float sacc[8][4];
#pragma unroll
        for (int nb = 0; nb < 8; nb++)
#pragma unroll
            for (int r = 0; r < 4; r++) sacc[nb][r] = 0.0f;

#pragma unroll
        for (int ks = 0; ks < 4; ks++) {
#pragma unroll
            for (int pi = 0; pi < 4; pi++) {
                uint32_t boff = swz128(((pi * 16 + (lid & 7) + ((lid >> 4) << 3)) << 7) +
                                       ((ks * 2 + ((lid >> 3) & 1)) << 4));
                uint32_t k4[4];
                ldsm4(k4, sK + boff);
#pragma unroll
                for (int sub = 0; sub < 2; sub++)
                    mma16816(sacc[pi * 2 + sub], qf[ks], k4 + sub * 2);
            }
        }

        // ---- causal mask (diagonal super-chunks only) ----
        const int row0 = qbase + w * 16 + (lid >> 2);
        const int row1 = row0 + 8;
        const bool diag = (c >= 2 * qt);
        if (diag) {
#pragma unroll
            for (int nb = 0; nb < 8; nb++) {
                int col = c * 64 + nb * 8 + ((lid & 3) << 1);
                if (col > row0)     sacc[nb][0] = -INFINITY;
                if (col + 1 > row0) sacc[nb][1] = -INFINITY;
                if (col > row1)     sacc[nb][2] = -INFINITY;
                if (col + 1 > row1) sacc[nb][3] = -INFINITY;
            }
        }

        // ---- online softmax (base-2) ----
        {
            float mx0 = -INFINITY, mx1 = -INFINITY;
#pragma unroll
            for (int nb = 0; nb < 8; nb++) {
                mx0 = fmaxf(mx0, fmaxf(sacc[nb][0], sacc[nb][1]));
                mx1 = fmaxf(mx1, fmaxf(sacc[nb][2], sacc[nb][3]));
            }
            mx0 = fmaxf(mx0, __shfl_xor_sync(0xffffffffu, mx0, 1));
            mx0 = fmaxf(mx0, __shfl_xor_sync(0xffffffffu, mx0, 2));
            mx1 = fmaxf(mx1, __shfl_xor_sync(0xffffffffu, mx1, 1));
            mx1 = fmaxf(mx1, __shfl_xor_sync(0xffffffffu, mx1, 2));
            float mn0 = fmaxf(m0, mx0), mn1 = fmaxf(m1, mx1);
            float f0 = fexp2(m0 - mn0), f1 = fexp2(m1 - mn1);
            float s0 = 0.0f, s1 = 0.0f;
#pragma unroll
            for (int nb = 0; nb < 8; nb++) {
                sacc[nb][0] = fexp2(sacc[nb][0] - mn0);
                sacc[nb][1] = fexp2(sacc[nb][1] - mn0);
                sacc[nb][2] = fexp2(sacc[nb][2] - mn1);
                sacc[nb][3] = fexp2(sacc[nb][3] - mn1);
                s0 += sacc[nb][0] + sacc[nb][1];
                s1 += sacc[nb][2] + sacc[nb][3];
            }
            s0 += __shfl_xor_sync(0xffffffffu, s0, 1);
            s0 += __shfl_xor_sync(0xffffffffu, s0, 2);
            s1 += __shfl_xor_sync(0xffffffffu, s1, 1);
            s1 += __shfl_xor_sync(0xffffffffu, s1, 2);
            l0 = l0 * f0 + s0; l1 = l1 * f1 + s1;
            m0 = mn0; m1 = mn1;
#pragma unroll
            for (int nb = 0; nb < 8; nb++) {
                oacc[nb][0] *= f0; oacc[nb][1] *= f0;
                oacc[nb][2] *= f1; oacc[nb][3] *= f1;
            }
        }

        // ---- O += P @ V (1-pass) ----
#pragma unroll
        for (int kp = 0; kp < 4; kp++) {
            uint32_t ph[4];
            ph[0] = pack_f16(sacc[2 * kp][0], sacc[2 * kp][1]);
            ph[1] = pack_f16(sacc[2 * kp][2], sacc[2 * kp][3]);
            ph[2] = pack_f16(sacc[2 * kp + 1][0], sacc[2 * kp + 1][1]);
            ph[3] = pack_f16(sacc[2 * kp + 1][2], sacc[2 * kp + 1][3]);
            const int mi = lid >> 3, r8 = lid & 7;
#pragma unroll
            for (int pi = 0; pi < 4; pi++) {
                uint32_t voff = swz128(((kp * 16 + ((mi & 1) << 3) + r8) << 7) +
                                       ((pi * 16 + ((mi >> 1) << 3)) << 1));
                uint32_t v4[4];
                ldsm4t(v4, sV + voff);
#pragma unroll
                for (int sub = 0; sub < 2; sub++)
                    mma16816(oacc[pi * 2 + sub], ph, v4 + sub * 2);
            }
        }

        buf = (buf + 1) % 3;
    }

    // ---- epilogue: normalize, fp16 store ----
    const float inv0 = 1.0f / l0, inv1 = 1.0f / l1;
    const int row0 = qbase + w * 16 + (lid >> 2);
    __half* yhb = yh + (size_t)b * CT * CD + (size_t)h * CHD;
#pragma unroll
    for (int nb = 0; nb < 8; nb++) {
        int col = nb * 8 + ((lid & 3) << 1);
        *(uint32_t*)&yhb[(size_t)row0 * CD + col] =
            pack_f16(oacc[nb][0] * inv0, oacc[nb][1] * inv0);
        *(uint32_t*)&yhb[(size_t)(row0 + 8) * CD + col] =
            pack_f16(oacc[nb][2] * inv1, oacc[nb][3] * inv1);
    }
}

// ---------------------------------------------------------------------------
// Launch
// ---------------------------------------------------------------------------
extern "C" void kernel_launch(void* const* d_in, const int* in_sizes, int n_in,
                              void* d_out, int out_size)
{
    (void)in_sizes; (void)n_in; (void)out_size;
    const float* x  = (const float*)d_in[0];
    const float* W1 = (const float*)d_in[1];
    const float* b1 = (const float*)d_in[2];
    const float* W2 = (const float*)d_in[3];
    const float* b2 = (const float*)d_in[4];
    float* out = (float*)d_out;

    __half *qkvh, *xh, *yh, *w1t, *w2t;
    cudaGetSymbolAddress((void**)&qkvh, g_qkvh);
    cudaGetSymbolAddress((void**)&xh, g_xh);
    cudaGetSymbolAddress((void**)&yh, g_yh);
    cudaGetSymbolAddress((void**)&w1t, g_w1t);
    cudaGetSymbolAddress((void**)&w2t, g_w2t);

    cudaFuncSetAttribute(gemm_f16_kernel<true>,
                         cudaFuncAttributeMaxDynamicSharedMemorySize, GSMEM);
    cudaFuncSetAttribute(gemm_f16_kernel<false>,
                         cudaFuncAttributeMaxDynamicSharedMemorySize, GSMEM);
    cudaFuncSetAttribute(attn_f16_kernel,
                         cudaFuncAttributeMaxDynamicSharedMemorySize, ASMEM);

    const int M = CB * CT;                 // 4096
    const int n4x = M * CD / 4;

    convert_f16_kernel<<<(n4x + 255) / 256, 256>>>(x, xh, n4x);
    transpose_f16_kernel<<<dim3(3 * CD / 32, CD / 32), dim3(32, 8)>>>(W1, w1t, CD, 3 * CD);
    transpose_f16_kernel<<<dim3(CD / 32, CD / 32), dim3(32, 8)>>>(W2, w2t, CD, CD);

    // qkv (fp16) = x @ W1 + b1 ; Q columns pre-scaled by QSCALE
    gemm_f16_kernel<true><<<dim3(3 * CD / 128, M / 256), 512, GSMEM>>>(
        xh, w1t, b1, nullptr, qkvh, CD, 3 * CD, CD);

    // flash attention -> y (fp16)
    attn_f16_kernel<<<dim3(CT / 128, CH, CB), 256, ASMEM>>>(qkvh, yh);

    // out (fp32) = y @ W2 + b2
    gemm_f16_kernel<false><<<dim3(CD / 128, M / 256), 512, GSMEM>>>(
        yh, w2t, b2, out, nullptr, 0, CD, CD);
}

// round 13
// speedup vs baseline: 7.4259x; 1.0473x over previous
#include <cuda_runtime.h>
#include <cuda_fp16.h>
#include <math.h>
#include <stdint.h>

#define CB 2
#define CT 2048
#define CD 1024
#define CH 16
#define CHD 64

// ---------------------------------------------------------------------------
// Device scratch (no cudaMalloc allowed)
// ---------------------------------------------------------------------------
__device__ __align__(128) __half g_qkvh[(size_t)CB * CT * 3 * CD];  // qkv fp16 (Q cols pre-scaled)
__device__ __align__(128) __half g_xh[(size_t)CB * CT * CD];        // x fp16
__device__ __align__(128) __half g_yh[(size_t)CB * CT * CD];        // y fp16
__device__ __align__(128) __half g_w1t[(size_t)3 * CD * CD];        // W1^T [N,K]
__device__ __align__(128) __half g_w2t[(size_t)CD * CD];            // W2^T [N,K]

// Q pre-scale: 1/sqrt(64) * log2(e)
#define QSCALE 0.1803368801111244f

// ---------------------------------------------------------------------------
// Low-level helpers
// ---------------------------------------------------------------------------
__device__ __forceinline__ uint32_t smem_u32(const void* p) {
    uint32_t a;
    asm("{ .reg .u64 t; cvta.to.shared.u64 t, %1; cvt.u32.u64 %0, t; }" : "=r"(a) : "l"(p));
    return a;
}
__device__ __forceinline__ void cpasync16(uint32_t s, const void* g) {
    asm volatile("cp.async.cg.shared.global [%0], [%1], 16;" :: "r"(s), "l"(g));
}
__device__ __forceinline__ void cp_commit() {
    asm volatile("cp.async.commit_group;" ::: "memory");
}
template <int N>
__device__ __forceinline__ void cp_wait() {
    asm volatile("cp.async.wait_group %0;" :: "n"(N) : "memory");
}
__device__ __forceinline__ void ldsm4(uint32_t* r, uint32_t addr) {
    asm volatile("ldmatrix.sync.aligned.m8n8.x4.shared.b16 {%0,%1,%2,%3}, [%4];"
                 : "=r"(r[0]), "=r"(r[1]), "=r"(r[2]), "=r"(r[3]) : "r"(addr));
}
__device__ __forceinline__ void ldsm4t(uint32_t* r, uint32_t addr) {
    asm volatile("ldmatrix.sync.aligned.m8n8.x4.trans.shared.b16 {%0,%1,%2,%3}, [%4];"
                 : "=r"(r[0]), "=r"(r[1]), "=r"(r[2]), "=r"(r[3]) : "r"(addr));
}
__device__ __forceinline__ void mma16816(float* d, const uint32_t* a, const uint32_t* b) {
    asm volatile(
        "mma.sync.aligned.m16n8k16.row.col.f32.f16.f16.f32 "
        "{%0,%1,%2,%3}, {%4,%5,%6,%7}, {%8,%9}, {%0,%1,%2,%3};"
        : "+f"(d[0]), "+f"(d[1]), "+f"(d[2]), "+f"(d[3])
        : "r"(a[0]), "r"(a[1]), "r"(a[2]), "r"(a[3]), "r"(b[0]), "r"(b[1]));
}
__device__ __forceinline__ uint32_t swz128(uint32_t b) { return b ^ ((b >> 3) & 0x70); }
__device__ __forceinline__ uint32_t pack_f16(float a, float b) {
    __half2 v = __floats2half2_rn(a, b);
    return *(uint32_t*)&v;
}
__device__ __forceinline__ float fexp2(float x) {
    float y;
    asm("ex2.approx.ftz.f32 %0, %1;" : "=f"(y) : "f"(x));
    return y;
}

// ---------------------------------------------------------------------------
// Merged prep: x fp32->fp16 convert + W1/W2 transpose-convert, one launch.
// Block ranges: [0, NB_X) convert; [NB_X, NB_X+NB_W1) W1^T; rest W2^T.
// ---------------------------------------------------------------------------
#define NB_X  4096                       // (4096*1024/4)/256
#define NB_W1 3072                       // (3072/32)*(1024/32)
#define NB_W2 1024                       // (1024/32)*(1024/32)

__global__ __launch_bounds__(256) void prep_kernel(
    const float* __restrict__ x, __half* __restrict__ xh,
    const float* __restrict__ W1, __half* __restrict__ w1t,
    const float* __restrict__ W2, __half* __restrict__ w2t)
{
    int bid = blockIdx.x;
    int tid = threadIdx.x;
    if (bid < NB_X) {
        int i = bid * 256 + tid;
        float4 v = ((const float4*)x)[i];
        ((uint2*)xh)[i] = make_uint2(pack_f16(v.x, v.y), pack_f16(v.z, v.w));
        return;
    }
    // transpose path: 32x32 tile, tx=tid&31, ty=tid>>5 (8 rows/pass)
    __shared__ float t[32][33];
    const float* W;
    __half* outp;
    int N, bx, by;
    if (bid < NB_X + NB_W1) {
        int r = bid - NB_X;
        W = W1; outp = w1t; N = 3 * CD;
        bx = r % 96; by = r / 96;
    } else {
        int r = bid - NB_X - NB_W1;
        W = W2; outp = w2t; N = CD;
        bx = r % 32; by = r / 32;
    }
    int n0 = bx * 32, k0 = by * 32;
    int tx = tid & 31, ty = tid >> 5;
#pragma unroll
    for (int j = 0; j < 4; j++)
        t[ty + j * 8][tx] = W[(size_t)(k0 + ty + j * 8) * N + n0 + tx];
    __syncthreads();
#pragma unroll
    for (int j = 0; j < 4; j++)
        outp[(size_t)(n0 + ty + j * 8) * CD + k0 + tx] = __float2half_rn(t[tx][ty + j * 8]);
}

// ---------------------------------------------------------------------------
// HMMA fp16 GEMM (unchanged from R12): CTA 256x128, 512 threads, BK=128
// super-chunks, 2 super-stages, one barrier per super-chunk.
// ---------------------------------------------------------------------------
#define SUPA 32768
#define SUPB 16384
#define SUP_STAGE (2 * SUPA + 2 * SUPB)   // 98304
#define GSMEM (2 * SUP_STAGE)             // 196608

template <bool F16OUT>
__global__ __launch_bounds__(512, 1) void gemm_f16_kernel(
    const __half* __restrict__ Ag, const __half* __restrict__ Bg,
    const float* __restrict__ bias, float* __restrict__ Cf,
    __half* __restrict__ Ch, int qcols, int N, int K)
{
    extern __shared__ char smem[];
    const uint32_t sbase = smem_u32(smem);
    const int tid = threadIdx.x;
    const int wid = tid >> 5;
    const int lid = tid & 31;
    const int wm = wid & 7;
    const int wn = wid >> 3;
    const int bm = blockIdx.y * 256;
    const int bn = blockIdx.x * 128;

    const int nsup = K >> 7;

    auto load_super = [&](int buf, int k0) {
        uint32_t sb = sbase + buf * SUP_STAGE;
#pragma unroll
        for (int i = 0; i < 12; i++) {
            int c = tid + (i << 9);
            if (c < 4096) {
                int sub = c >> 11;
                int cc = c & 2047;
                int row = cc >> 3, seg = cc & 7;
                uint32_t dst = sb + sub * SUPA + swz128((row << 7) + (seg << 4));
                cpasync16(dst, Ag + (size_t)(bm + row) * K + k0 + sub * 64 + (seg << 3));
            } else {
                int cc = c - 4096;
                int sub = cc >> 10;
                int c2 = cc & 1023;
                int row = c2 >> 3, seg = c2 & 7;
                uint32_t dst = sb + 2 * SUPA + sub * SUPB + swz128((row << 7) + (seg << 4));
                cpasync16(dst, Bg + (size_t)(bn + row) * K + k0 + sub * 64 + (seg << 3));
            }
        }
        cp_commit();
    };

    float d[2][8][4];
#pragma unroll
    for (int mi = 0; mi < 2; mi++)
#pragma unroll
        for (int ni = 0; ni < 8; ni++)
#pragma unroll
            for (int r = 0; r < 4; r++) d[mi][ni][r] = 0.0f;

    load_super(0, 0);

    for (int c = 0; c < nsup; c++) {
        cp_wait<0>();
        __syncthreads();
        if (c + 1 < nsup) load_super((c + 1) & 1, (c + 1) << 7);

        const uint32_t sb = sbase + (c & 1) * SUP_STAGE;
#pragma unroll
        for (int sub = 0; sub < 2; sub++) {
            const uint32_t aT = sb + sub * SUPA;
            const uint32_t bT = sb + 2 * SUPA + sub * SUPB;
#pragma unroll
            for (int ks = 0; ks < 4; ks++) {
                uint32_t a4[2][4];
#pragma unroll
                for (int mi = 0; mi < 2; mi++) {
                    uint32_t off = swz128(((wm * 32 + mi * 16 + (lid & 15)) << 7) +
                                          ((ks * 2 + (lid >> 4)) << 4));
                    ldsm4(a4[mi], aT + off);
                }
#pragma unroll
                for (int pi = 0; pi < 4; pi++) {
                    uint32_t boff = swz128(((wn * 64 + pi * 16 + (lid & 7) + ((lid >> 4) << 3)) << 7) +
                                           ((ks * 2 + ((lid >> 3) & 1)) << 4));
                    uint32_t b4[4];
                    ldsm4(b4, bT + boff);
#pragma unroll
                    for (int mi = 0; mi < 2; mi++)
#pragma unroll
                        for (int sub2 = 0; sub2 < 2; sub2++)
                            mma16816(d[mi][pi * 2 + sub2], a4[mi], b4 + sub2 * 2);
                }
            }
        }
    }

#pragma unroll
    for (int mi = 0; mi < 2; mi++) {
        int row = bm + wm * 32 + mi * 16 + (lid >> 2);
#pragma unroll
        for (int ni = 0; ni < 8; ni++) {
            int col = bn + wn * 64 + ni * 8 + ((lid & 3) << 1);
            float2 bv = *(const float2*)&bias[col];
            float v00 = d[mi][ni][0] + bv.x, v01 = d[mi][ni][1] + bv.y;
            float v10 = d[mi][ni][2] + bv.x, v11 = d[mi][ni][3] + bv.y;
            if (F16OUT) {
                float qs = (col < qcols) ? QSCALE : 1.0f;
                v00 *= qs; v01 *= qs; v10 *= qs; v11 *= qs;
                *(uint32_t*)&Ch[(size_t)row * N + col] = pack_f16(v00, v01);
                *(uint32_t*)&Ch[(size_t)(row + 8) * N + col] = pack_f16(v10, v11);
            } else {
                *(float2*)&Cf[(size_t)row * N + col] = make_float2(v00, v01);
                *(float2*)&Cf[(size_t)(row + 8) * N + col] = make_float2(v10, v11);
            }
        }
    }
}

// ---------------------------------------------------------------------------
// HMMA fp16 flash attention, 128-KEY CHUNKS: one softmax + one barrier per
// 128 keys (2x MMAs per sync interval vs 64-key version).
// Q pre-scaled -> base-2 softmax. 2-stage KV ring, single barrier per chunk.
// ---------------------------------------------------------------------------
#define AQT 16384
#define AKT2 16384                         // K tile: 128 keys x 128B
#define AKV_STAGE2 (2 * AKT2)              // K + V = 32KB
#define ASMEM (AQT + 2 * AKV_STAGE2)       // 81920; 2 CTAs/SM -> 160KB

__global__ __launch_bounds__(256, 2) void attn_f16_kernel(
    const __half* __restrict__ qkvh, __half* __restrict__ yh)
{
    extern __shared__ char smem[];
    const uint32_t sbase = smem_u32(smem);
    const int tid = threadIdx.x;
    const int w = tid >> 5;
    const int lid = tid & 31;
    const int qt = gridDim.x - 1 - blockIdx.x;   // big causal tiles first
    const int h  = blockIdx.y;
    const int b  = blockIdx.z;
    const int qbase = qt * 128;
    const int nch = qt + 1;                      // 128-key chunks

    const uint32_t sQ = sbase;
    const uint32_t sKV = sbase + AQT;

    const size_t rowbase = (size_t)b * CT * 3 * CD + (size_t)h * CHD;

    // Q load (joins KV group 0's commit)
#pragma unroll
    for (int i = 0; i < 4; i++) {
        int c = tid + (i << 8);
        int row = c >> 3;
        int seg = c & 7;
        uint32_t so = swz128((row << 7) + (seg << 4));
        cpasync16(sQ + so, qkvh + rowbase + (size_t)(qbase + row) * (3 * CD) + (seg << 3));
    }

    auto load_kv = [&](int buf, int kt0) {
        uint32_t sb = sKV + buf * AKV_STAGE2;
#pragma unroll
        for (int i = 0; i < 8; i++) {
            int c = tid + (i << 8);            // 0..2047 16B chunks
            int tile = c >> 10;                // 0 K, 1 V (128 rows each)
            int row = (c >> 3) & 127;
            int seg = c & 7;
            uint32_t so = swz128((row << 7) + (seg << 4));
            size_t ga = rowbase + (size_t)(kt0 + row) * (3 * CD) + (seg << 3) +
                        (tile ? 2 * CD : CD);
            cpasync16(sb + tile * AKT2 + so, qkvh + ga);
        }
        cp_commit();
    };

    load_kv(0, 0);

    float m0 = -INFINITY, m1 = -INFINITY, l0 = 0.0f, l1 = 0.0f;
    float oacc[8][4];
#pragma unroll
    for (int nb = 0; nb < 8; nb++)
#pragma unroll
        for (int r = 0; r < 4; r++) oacc[nb][r] = 0.0f;

    for (int c = 0; c < nch; c++) {
        cp_wait<0>();                    // drain stage c (only group outstanding)
        __syncthreads();                 // publish stage c; other slot fully read
        if (c + 1 < nch) load_kv((c + 1) & 1, (c + 1) << 7);

        const uint32_t sb = sKV + (c & 1) * AKV_STAGE2;
        const uint32_t sK = sb, sV = sb + AKT2;

        // Q fragments (reloaded per chunk to bound register pressure)
        uint32_t qf[4][4];
#pragma unroll
        for (int ks = 0; ks < 4; ks++) {
            uint32_t off = swz128(((w * 16 + (lid & 15)) << 7) +
                                  ((ks * 2 + (lid >> 4)) << 4));
            ldsm4(qf[ks], sQ + off);
        }

        // ---- S = Q' @ K^T over 128 keys ----
        float sacc[16][4];
#pragma unroll
        for (int nb = 0; nb < 16; nb++)
#pragma unroll
            for (int r = 0; r < 4; r++) sacc[nb][r] = 0.0f;

#pragma unroll
        for (int ks = 0; ks < 4; ks++) {
#pragma unroll
            for (int pi = 0; pi < 8; pi++) {
                uint32_t boff = swz128(((pi * 16 + (lid & 7) + ((lid >> 4) << 3)) << 7) +
                                       ((ks * 2 + ((lid >> 3) & 1)) << 4));
                uint32_t k4[4];
                ldsm4(k4, sK + boff);
#pragma unroll
                for (int sub = 0; sub < 2; sub++)
                    mma16816(sacc[pi * 2 + sub], qf[ks], k4 + sub * 2);
            }
        }

        // ---- causal mask (only the diagonal chunk c == qt) ----
        const int rin0 = w * 16 + (lid >> 2);   // row within tile
        const int rin1 = rin0 + 8;
        if (c == qt) {
#pragma unroll
            for (int nb = 0; nb < 16; nb++) {
                int col = nb * 8 + ((lid & 3) << 1);
                if (col > rin0)     sacc[nb][0] = -INFINITY;
                if (col + 1 > rin0) sacc[nb][1] = -INFINITY;
                if (col > rin1)     sacc[nb][2] = -INFINITY;
                if (col + 1 > rin1) sacc[nb][3] = -INFINITY;
            }
        }

        // ---- online softmax (base-2) over 128 cols ----
        {
            float mx0 = -INFINITY, mx1 = -INFINITY;
#pragma unroll
            for (int nb = 0; nb < 16; nb++) {
                mx0 = fmaxf(mx0, fmaxf(sacc[nb][0], sacc[nb][1]));
                mx1 = fmaxf(mx1, fmaxf(sacc[nb][2], sacc[nb][3]));
            }
            mx0 = fmaxf(mx0, __shfl_xor_sync(0xffffffffu, mx0, 1));
            mx0 = fmaxf(mx0, __shfl_xor_sync(0xffffffffu, mx0, 2));
            mx1 = fmaxf(mx1, __shfl_xor_sync(0xffffffffu, mx1, 1));
            mx1 = fmaxf(mx1, __shfl_xor_sync(0xffffffffu, mx1, 2));
            float mn0 = fmaxf(m0, mx0), mn1 = fmaxf(m1, mx1);
            float f0 = fexp2(m0 - mn0), f1 = fexp2(m1 - mn1);
            float s0 = 0.0f, s1 = 0.0f;
#pragma unroll
            for (int nb = 0; nb < 16; nb++) {
                sacc[nb][0] = fexp2(sacc[nb][0] - mn0);
                sacc[nb][1] = fexp2(sacc[nb][1] - mn0);
                sacc[nb][2] = fexp2(sacc[nb][2] - mn1);
                sacc[nb][3] = fexp2(sacc[nb][3] - mn1);
                s0 += sacc[nb][0] + sacc[nb][1];
                s1 += sacc[nb][2] + sacc[nb][3];
            }
            s0 += __shfl_xor_sync(0xffffffffu, s0, 1);
            s0 += __shfl_xor_sync(0xffffffffu, s0, 2);
            s1 += __shfl_xor_sync(0xffffffffu, s1, 1);
            s1 += __shfl_xor_sync(0xffffffffu, s1, 2);
            l0 = l0 * f0 + s0; l1 = l1 * f1 + s1;
            m0 = mn0; m1 = mn1;
#pragma unroll
            for (int nb = 0; nb < 8; nb++) {
                oacc[nb][0] *= f0; oacc[nb][1] *= f0;
                oacc[nb][2] *= f1; oacc[nb][3] *= f1;
            }
        }

        // ---- O += P @ V over 128 keys ----
#pragma unroll
        for (int kp = 0; kp < 8; kp++) {
            uint32_t ph[4];
            ph[0] = pack_f16(sacc[2 * kp][0], sacc[2 * kp][1]);
            ph[1] = pack_f16(sacc[2 * kp][2], sacc[2 * kp][3]);
            ph[2] = pack_f16(sacc[2 * kp + 1][0], sacc[2 * kp + 1][1]);
            ph[3] = pack_f16(sacc[2 * kp + 1][2], sacc[2 * kp + 1][3]);
            const int mi = lid >> 3, r8 = lid & 7;
#pragma unroll
            for (int pi = 0; pi < 4; pi++) {
                uint32_t voff = swz128(((kp * 16 + ((mi & 1) << 3) + r8) << 7) +
                                       ((pi * 16 + ((mi >> 1) << 3)) << 1));
                uint32_t v4[4];
                ldsm4t(v4, sV + voff);
#pragma unroll
                for (int sub = 0; sub < 2; sub++)
                    mma16816(oacc[pi * 2 + sub], ph, v4 + sub * 2);
            }
        }
    }

    // ---- epilogue: normalize, fp16 store ----
    const float inv0 = 1.0f / l0, inv1 = 1.0f / l1;
    const int row0 = qbase + w * 16 + (lid >> 2);
    __half* yhb = yh + (size_t)b * CT * CD + (size_t)h * CHD;
#pragma unroll
    for (int nb = 0; nb < 8; nb++) {
        int col = nb * 8 + ((lid & 3) << 1);
        *(uint32_t*)&yhb[(size_t)row0 * CD + col] =
            pack_f16(oacc[nb][0] * inv0, oacc[nb][1] * inv0);
        *(uint32_t*)&yhb[(size_t)(row0 + 8) * CD + col] =
            pack_f16(oacc[nb][2] * inv1, oacc[nb][3] * inv1);
    }
}

// ---------------------------------------------------------------------------
// Launch
// ---------------------------------------------------------------------------
extern "C" void kernel_launch(void* const* d_in, const int* in_sizes, int n_in,
                              void* d_out, int out_size)
{
    (void)in_sizes; (void)n_in; (void)out_size;
    const float* x  = (const float*)d_in[0];
    const float* W1 = (const float*)d_in[1];
    const float* b1 = (const float*)d_in[2];
    const float* W2 = (const float*)d_in[3];
    const float* b2 = (const float*)d_in[4];
    float* out = (float*)d_out;

    __half *qkvh, *xh, *yh, *w1t, *w2t;
    cudaGetSymbolAddress((void**)&qkvh, g_qkvh);
    cudaGetSymbolAddress((void**)&xh, g_xh);
    cudaGetSymbolAddress((void**)&yh, g_yh);
    cudaGetSymbolAddress((void**)&w1t, g_w1t);
    cudaGetSymbolAddress((void**)&w2t, g_w2t);

    cudaFuncSetAttribute(gemm_f16_kernel<true>,
                         cudaFuncAttributeMaxDynamicSharedMemorySize, GSMEM);
    cudaFuncSetAttribute(gemm_f16_kernel<false>,
                         cudaFuncAttributeMaxDynamicSharedMemorySize, GSMEM);
    cudaFuncSetAttribute(attn_f16_kernel,
                         cudaFuncAttributeMaxDynamicSharedMemorySize, ASMEM);

    const int M = CB * CT;                 // 4096

    // merged prep: x convert + W1^T + W2^T
    prep_kernel<<<NB_X + NB_W1 + NB_W2, 256>>>(x, xh, W1, w1t, W2, w2t);

    // qkv (fp16) = x @ W1 + b1 ; Q columns pre-scaled by QSCALE
    gemm_f16_kernel<true><<<dim3(3 * CD / 128, M / 256), 512, GSMEM>>>(
        xh, w1t, b1, nullptr, qkvh, CD, 3 * CD, CD);

    // flash attention -> y (fp16), 128-key chunks
    attn_f16_kernel<<<dim3(CT / 128, CH, CB), 256, ASMEM>>>(qkvh, yh);

    // out (fp32) = y @ W2 + b2
    gemm_f16_kernel<false><<<dim3(CD / 128, M / 256), 512, GSMEM>>>(
        yh, w2t, b2, out, nullptr, 0, CD, CD);
}